// round 9
// baseline (speedup 1.0000x reference)
#include <cuda_runtime.h>
#include <cuda_bf16.h>
#include <cstdint>
#include <math.h>

#define NB    2
#define NQ    4096
#define NKV   1024
#define CD    512
#define NHEAD 8
#define DH    64
#define RLORA 8
#define LN_EPS 1e-5f

typedef __nv_bfloat16 bf16;

// ---------------------------------------------------------------------------
// Device scratch
// ---------------------------------------------------------------------------
__device__ bf16  g_x_hi [NB*NQ*CD],      g_x_lo [NB*NQ*CD];
__device__ bf16  g_BqT_hi[CD*CD],        g_BqT_lo[CD*CD];
__device__ bf16  g_BkvT_hi[2*CD*CD],     g_BkvT_lo[2*CD*CD];
__device__ bf16  g_BsrT_hi[CD*4*CD],     g_BsrT_lo[CD*4*CD];
__device__ bf16  g_BpT_hi[CD*CD],        g_BpT_lo[CD*CD];
__device__ bf16  g_q_hi [NB*NQ*CD],      g_q_lo [NB*NQ*CD];
__device__ float g_xs [NB*NKV*CD];
__device__ bf16  g_kv_hi[NB*NKV*2*CD],   g_kv_lo[NB*NKV*2*CD];
__device__ bf16  g_xs_hi[NB*NKV*CD],     g_xs_lo[NB*NKV*CD];
__device__ bf16  g_o_hi[NB*NQ*CD],       g_o_lo[NB*NQ*CD];

// ---------------------------------------------------------------------------
// helpers
// ---------------------------------------------------------------------------
__device__ __forceinline__ uint32_t smem_u32(const void* p) {
    uint32_t a;
    asm("{ .reg .u64 t; cvta.to.shared.u64 t, %1; cvt.u32.u64 %0, t; }" : "=r"(a) : "l"(p));
    return a;
}
#define SW128(o) ((o) ^ (((o) >> 3) & 0x70))

__device__ __forceinline__ void cp16(uint32_t dst, const void* src) {
    asm volatile("cp.async.cg.shared.global [%0], [%1], 16;" :: "r"(dst), "l"(src));
}
__device__ __forceinline__ void cp_commit() { asm volatile("cp.async.commit_group;"); }
template<int N> __device__ __forceinline__ void cp_wait() {
    asm volatile("cp.async.wait_group %0;" :: "n"(N));
}

__device__ __forceinline__ void ldm_x4(uint32_t addr, uint32_t* r) {
    asm volatile("ldmatrix.sync.aligned.m8n8.x4.shared.b16 {%0,%1,%2,%3}, [%4];"
        : "=r"(r[0]), "=r"(r[1]), "=r"(r[2]), "=r"(r[3]) : "r"(addr));
}
__device__ __forceinline__ void ldm_x4_t(uint32_t addr, uint32_t* r) {
    asm volatile("ldmatrix.sync.aligned.m8n8.x4.trans.shared.b16 {%0,%1,%2,%3}, [%4];"
        : "=r"(r[0]), "=r"(r[1]), "=r"(r[2]), "=r"(r[3]) : "r"(addr));
}
__device__ __forceinline__ void mma16816(float* c, const uint32_t* a, const uint32_t* b) {
    asm volatile("mma.sync.aligned.m16n8k16.row.col.f32.bf16.bf16.f32 "
        "{%0,%1,%2,%3}, {%4,%5,%6,%7}, {%8,%9}, {%0,%1,%2,%3};"
        : "+f"(c[0]), "+f"(c[1]), "+f"(c[2]), "+f"(c[3])
        : "r"(a[0]), "r"(a[1]), "r"(a[2]), "r"(a[3]), "r"(b[0]), "r"(b[1]));
}

__device__ __forceinline__ void bsplit(float a, bf16& hi, bf16& lo) {
    hi = __float2bfloat16_rn(a);
    lo = __float2bfloat16_rn(a - __bfloat162float(hi));
}
__device__ __forceinline__ uint32_t packbf(bf16 a, bf16 b) {
    __nv_bfloat162 h = __halves2bfloat162(a, b);
    return *reinterpret_cast<uint32_t*>(&h);
}

// ---------------------------------------------------------------------------
// GEMM core (HMMA bf16x3): C[M,N] = A @ B^T + bias
//   CTA tile 128x256, BK=64, 256 threads, 8 warps (2x4), warp tile 64x64,
//   2-stage cp.async. OB=0: fp32 out; OB=1: split bf16 out.
//   PERM=1: A addresses the conv patch permutation of g_x (K=2048).
//   smem per stage: A hi/lo 2x16KB + B hi/lo 2x32KB = 96KB; 2 stages = 192KB.
// ---------------------------------------------------------------------------
#define A_TILE_B 16384              // 128 rows x 128B
#define B_TILE_B 32768              // 256 rows x 128B
#define STAGE_B  (2 * A_TILE_B + 2 * B_TILE_B)   // 96 KB
#define GEMM_SMEM (2 * STAGE_B)                  // 192 KB

template<int OB, int PERM>
__device__ __forceinline__ void gemm_core(
    uint32_t sb,
    const bf16* __restrict__ Ah, const bf16* __restrict__ Al,
    const bf16* __restrict__ Bh, const bf16* __restrict__ Bl,
    const float* __restrict__ bias, void* __restrict__ Cv, void* __restrict__ Cv2,
    int K, int ldc, int bx, int by)
{
    int tid = threadIdx.x, wid = tid >> 5, lane = tid & 31;

    const bf16* aAh = PERM ? Ah : Ah + (size_t)by * 128 * K;
    const bf16* aAl = PERM ? Al : Al + (size_t)by * 128 * K;
    const bf16* aBh = Bh + (size_t)bx * 256 * K;
    const bf16* aBl = Bl + (size_t)bx * 256 * K;

    auto issue = [&](int chunk, int buf) {
        int k0 = chunk << 6;
        uint32_t stg = sb + buf * STAGE_B;
        // A tiles (hi, lo): 1024 16B units each -> 4 per thread
#pragma unroll
        for (int t = 0; t < 2; t++) {
            const bf16* src = t ? aAl : aAh;
#pragma unroll
            for (int it = 0; it < 4; it++) {
                int idx = it * 256 + tid;
                int r = idx >> 3, c16 = idx & 7;
                size_t goff;
                if (PERM) {
                    int m = by * 128 + r;
                    int p = k0 >> 9;                 // patch index 0..3
                    int bb = m >> 10, pp = m & 1023;
                    int tok = bb * NQ + ((pp >> 5) * 2 + (p >> 1)) * 64
                            + ((pp & 31) * 2 + (p & 1));
                    goff = (size_t)tok * CD + (k0 & 511) + c16 * 8;
                } else {
                    goff = (size_t)r * K + k0 + c16 * 8;
                }
                cp16(stg + t * A_TILE_B + SW128(r * 128 + c16 * 16), src + goff);
            }
        }
        // B tiles (hi, lo): 2048 16B units each -> 8 per thread
#pragma unroll
        for (int t = 0; t < 2; t++) {
            const bf16* src = (t ? aBl : aBh) + k0;
            uint32_t base = stg + 2 * A_TILE_B + t * B_TILE_B;
#pragma unroll
            for (int it = 0; it < 8; it++) {
                int idx = it * 256 + tid;
                int r = idx >> 3, c16 = idx & 7;
                cp16(base + SW128(r * 128 + c16 * 16),
                     src + (size_t)r * K + c16 * 8);
            }
        }
        cp_commit();
    };

    float acc[4][8][4];
#pragma unroll
    for (int i = 0; i < 4; i++)
#pragma unroll
        for (int j = 0; j < 8; j++)
#pragma unroll
            for (int e = 0; e < 4; e++) acc[i][j][e] = 0.f;

    int wm = wid >> 2, wn = wid & 3;     // 2 x 4 warp grid, 64x64 per warp
    int nch = K >> 6;

    issue(0, 0);
    for (int i = 0; i < nch; i++) {
        int buf = i & 1;
        if (i + 1 < nch) { issue(i + 1, buf ^ 1); cp_wait<1>(); }
        else             { cp_wait<0>(); }
        __syncthreads();

        uint32_t stg = sb + buf * STAGE_B;
        uint32_t aH = stg;
        uint32_t aL = stg + A_TILE_B;
        uint32_t bH = stg + 2 * A_TILE_B;
        uint32_t bL = bH + B_TILE_B;

#pragma unroll
        for (int ks = 0; ks < 4; ks++) {
            int kb = ks * 32;
            // stage ALL B fragments for this ks (8 n-tiles, hi+lo = 32 regs)
            uint32_t bh[8][2], bl[8][2];
#pragma unroll
            for (int bt = 0; bt < 4; bt++) {
                int row = wn * 64 + bt * 16 + ((lane >> 4) << 3) + (lane & 7);
                int colb = kb + (((lane >> 3) & 1) << 4);
                uint32_t off = SW128(row * 128 + colb);
                uint32_t t[4];
                ldm_x4(bH + off, t);
                bh[bt * 2][0] = t[0]; bh[bt * 2][1] = t[1];
                bh[bt * 2 + 1][0] = t[2]; bh[bt * 2 + 1][1] = t[3];
                ldm_x4(bL + off, t);
                bl[bt * 2][0] = t[0]; bl[bt * 2][1] = t[1];
                bl[bt * 2 + 1][0] = t[2]; bl[bt * 2 + 1][1] = t[3];
            }
            // stream A tiles (4 m-tiles), 8 regs live at a time
#pragma unroll
            for (int at = 0; at < 4; at++) {
                int row = wm * 64 + at * 16 + (lane & 15);
                int colb = kb + ((lane >> 4) << 4);
                uint32_t off = SW128(row * 128 + colb);
                uint32_t ah[4], al[4];
                ldm_x4(aH + off, ah);
                ldm_x4(aL + off, al);
#pragma unroll
                for (int nt = 0; nt < 8; nt++) {
                    mma16816(acc[at][nt], ah, bh[nt]);
                    mma16816(acc[at][nt], ah, bl[nt]);
                    mma16816(acc[at][nt], al, bh[nt]);
                }
            }
        }
        __syncthreads();
    }

    int g = lane >> 2, tc = (lane & 3) * 2;
#pragma unroll
    for (int nt = 0; nt < 8; nt++) {
        int col = bx * 256 + wn * 64 + nt * 8 + tc;
        float b0 = bias[col], b1 = bias[col + 1];
#pragma unroll
        for (int at = 0; at < 4; at++) {
            int row0 = by * 128 + wm * 64 + at * 16 + g;
            float v00 = acc[at][nt][0] + b0, v01 = acc[at][nt][1] + b1;
            float v10 = acc[at][nt][2] + b0, v11 = acc[at][nt][3] + b1;
            if (OB) {
                bf16* C  = (bf16*)Cv;
                bf16* C2 = (bf16*)Cv2;
                bf16 h0, l0, h1, l1;
                bsplit(v00, h0, l0); bsplit(v01, h1, l1);
                *(uint32_t*)(C  + (size_t)row0 * ldc + col) = packbf(h0, h1);
                *(uint32_t*)(C2 + (size_t)row0 * ldc + col) = packbf(l0, l1);
                bsplit(v10, h0, l0); bsplit(v11, h1, l1);
                *(uint32_t*)(C  + (size_t)(row0 + 8) * ldc + col) = packbf(h0, h1);
                *(uint32_t*)(C2 + (size_t)(row0 + 8) * ldc + col) = packbf(l0, l1);
            } else {
                float* C = (float*)Cv;
                *(float2*)(C + (size_t)row0 * ldc + col)       = make_float2(v00, v01);
                *(float2*)(C + (size_t)(row0 + 8) * ldc + col) = make_float2(v10, v11);
            }
        }
    }
}

template<int OB>
__global__ __launch_bounds__(256, 1) void gemm_bf16x3(
    const bf16* __restrict__ Ah, const bf16* __restrict__ Al,
    const bf16* __restrict__ Bh, const bf16* __restrict__ Bl,
    const float* __restrict__ bias, void* __restrict__ Cv, void* __restrict__ Cv2,
    int K, int ldc)
{
    extern __shared__ char smem[];
    gemm_core<OB, 0>(smem_u32(smem), Ah, Al, Bh, Bl, bias, Cv, Cv2, K, ldc,
                     blockIdx.x, blockIdx.y);
}

// Merged independent GEMMs: grid (2, 80).
//  by in [0,16):  xs = patch(x) @ WsrT + bsr  (2048 x 512, K=2048, fp32 out)
//  by in [16,80): q  = x @ WqT + bq           (8192 x 512, K=512, split bf16)
__global__ __launch_bounds__(256, 1) void gemm_q_xs(
    const float* __restrict__ bq, const float* __restrict__ bsr)
{
    extern __shared__ char smem[];
    uint32_t sb = smem_u32(smem);
    if (blockIdx.y < 16) {
        gemm_core<0, 1>(sb, g_x_hi, g_x_lo, g_BsrT_hi, g_BsrT_lo, bsr,
                        (void*)g_xs, nullptr, 4 * CD, CD, blockIdx.x, blockIdx.y);
    } else {
        gemm_core<1, 0>(sb, g_x_hi, g_x_lo, g_BqT_hi, g_BqT_lo, bq,
                        (void*)g_q_hi, (void*)g_q_lo, CD, CD, blockIdx.x, blockIdx.y - 16);
    }
}

// ---------------------------------------------------------------------------
// Merged prep: blocks [0,4096) split x into bf16 hi/lo;
//              blocks [4096,6144) transpose+LoRA-fold+split the weights.
// ---------------------------------------------------------------------------
__global__ __launch_bounds__(256) void prep_all(
    const float* __restrict__ x,
    const float* __restrict__ Wq,   const float* __restrict__ Aq, const float* __restrict__ Bq,
    const float* __restrict__ Wkv,  const float* __restrict__ Av, const float* __restrict__ Bv,
    const float* __restrict__ Wsr,  const float* __restrict__ Wproj)
{
    if (blockIdx.x < 4096) {
        int e = blockIdx.x * 256 + threadIdx.x;      // < 1048576 float4
        float4 v = ((const float4*)x)[e];
        bf16 h0, l0, h1, l1, h2, l2, h3, l3;
        bsplit(v.x, h0, l0); bsplit(v.y, h1, l1);
        bsplit(v.z, h2, l2); bsplit(v.w, h3, l3);
        ((uint32_t*)g_x_hi)[e * 2]     = packbf(h0, h1);
        ((uint32_t*)g_x_hi)[e * 2 + 1] = packbf(h2, h3);
        ((uint32_t*)g_x_lo)[e * 2]     = packbf(l0, l1);
        ((uint32_t*)g_x_lo)[e * 2 + 1] = packbf(l2, l3);
        return;
    }

    __shared__ float tile[32][33];
    int t = blockIdx.x - 4096;
    const float *W, *A = nullptr, *LB = nullptr;
    bf16 *Dh, *Dl;
    int K, stride, k0, n0;

    if (t < 256) {
        W = Wq; A = Aq; LB = Bq; Dh = g_BqT_hi; Dl = g_BqT_lo;
        K = 512; stride = 512; k0 = (t >> 4) * 32; n0 = (t & 15) * 32;
    } else if (t < 768) {
        int i = t - 256;
        W = Wkv; A = Av; LB = Bv; Dh = g_BkvT_hi; Dl = g_BkvT_lo;
        K = 512; stride = 1024; k0 = (i >> 5) * 32; n0 = (i & 31) * 32;
    } else if (t < 1792) {
        int i = t - 768;
        W = Wsr; Dh = g_BsrT_hi; Dl = g_BsrT_lo;
        K = 2048; stride = 512; k0 = (i >> 4) * 32; n0 = (i & 15) * 32;
    } else {
        int i = t - 1792;
        W = Wproj; Dh = g_BpT_hi; Dl = g_BpT_lo;
        K = 512; stride = 512; k0 = (i >> 4) * 32; n0 = (i & 15) * 32;
    }

    int tx = threadIdx.x & 31, ty = threadIdx.x >> 5;
#pragma unroll
    for (int i = 0; i < 4; i++) {
        int k = k0 + ty + i * 8, n = n0 + tx;
        float v = W[(size_t)k * stride + n];
        if (A) {
            float l = 0.f;
#pragma unroll
            for (int r = 0; r < RLORA; r++)
                l = fmaf(A[k * RLORA + r], LB[r * CD + (n & (CD - 1))], l);
            v += l;
        }
        tile[ty + i * 8][tx] = v;
    }
    __syncthreads();
#pragma unroll
    for (int i = 0; i < 4; i++) {
        int n = n0 + ty + i * 8, k = k0 + tx;
        float v = tile[tx][ty + i * 8];
        bf16 h, l; bsplit(v, h, l);
        Dh[(size_t)n * K + k] = h;
        Dl[(size_t)n * K + k] = l;
    }
}

// ---------------------------------------------------------------------------
// LayerNorm -> split bf16
// ---------------------------------------------------------------------------
__device__ __forceinline__ float warp_sum(float v) {
#pragma unroll
    for (int o = 16; o > 0; o >>= 1) v += __shfl_xor_sync(0xffffffffu, v, o);
    return v;
}

__global__ __launch_bounds__(256) void ln_split_kernel(const float* __restrict__ gamma,
                                                       const float* __restrict__ beta) {
    int row = blockIdx.x;
    const float* p = g_xs + (size_t)row * CD;
    int tid = threadIdx.x;
    float a = p[tid], c = p[tid + 256];

    float s  = warp_sum(a + c);
    float sq = warp_sum(a * a + c * c);
    __shared__ float sh[16];
    int w = tid >> 5, l = tid & 31;
    if (l == 0) { sh[w] = s; sh[8 + w] = sq; }
    __syncthreads();
    if (w == 0) {
        float ts = (l < 8) ? sh[l] : 0.f;
        float tq = (l < 8) ? sh[8 + l] : 0.f;
        ts = warp_sum(ts); tq = warp_sum(tq);
        if (l == 0) { sh[0] = ts; sh[1] = tq; }
    }
    __syncthreads();
    float mean = sh[0] * (1.f / CD);
    float var  = sh[1] * (1.f / CD) - mean * mean;
    float inv  = rsqrtf(var + LN_EPS);
    float y0 = (a - mean) * inv * gamma[tid] + beta[tid];
    float y1 = (c - mean) * inv * gamma[tid + 256] + beta[tid + 256];
    bf16 h, lo;
    bsplit(y0, h, lo); g_xs_hi[(size_t)row * CD + tid] = h;       g_xs_lo[(size_t)row * CD + tid] = lo;
    bsplit(y1, h, lo); g_xs_hi[(size_t)row * CD + tid + 256] = h; g_xs_lo[(size_t)row * CD + tid + 256] = lo;
}

// ---------------------------------------------------------------------------
// HMMA flash attention with bf16x3 in BOTH matmuls.
// grid (NQ/128, NHEAD, NB), 256 threads (8 warps x 16 q-rows).
// ---------------------------------------------------------------------------
#define ATTN_SMEM (32768 + 65536)   // 96 KB

__global__ __launch_bounds__(256, 1) void attn_hmma(
    const bf16* __restrict__ qh, const bf16* __restrict__ ql,
    const bf16* __restrict__ kvh, const bf16* __restrict__ kvl)
{
    extern __shared__ char smem[];
    uint32_t sb = smem_u32(smem);
    const uint32_t QH = sb, QL = sb + 16384, ST = sb + 32768;

    int tid = threadIdx.x, lane = tid & 31, wid = tid >> 5;
    int b = blockIdx.z, h = blockIdx.y;
    int q0 = blockIdx.x * 128;

    const bf16* qgh = qh + (size_t)(b * NQ + q0) * CD + h * DH;
    const bf16* qgl = ql + (size_t)(b * NQ + q0) * CD + h * DH;
    const bf16* kgh = kvh + (size_t)b * NKV * (2 * CD) + h * DH;
    const bf16* kgl = kvl + (size_t)b * NKV * (2 * CD) + h * DH;
    const bf16* vgh = kgh + CD;
    const bf16* vgl = kgl + CD;

#pragma unroll
    for (int it = 0; it < 4; it++) {
        int idx = it * 256 + tid;
        int r = idx >> 3, c16 = idx & 7;
        uint32_t so = SW128(r * 128 + c16 * 16);
        size_t go = (size_t)r * CD + c16 * 8;
        cp16(QH + so, qgh + go);
        cp16(QL + so, qgl + go);
    }
    cp_commit();

    auto issue_kv = [&](int t, int bufi) {
        int m0 = t * 64;
        uint32_t SBB = ST + bufi * 32768;
#pragma unroll
        for (int it = 0; it < 2; it++) {
            int idx = it * 256 + tid;
            int r = idx >> 3, c16 = idx & 7;
            size_t go = (size_t)(m0 + r) * (2 * CD) + c16 * 8;
            uint32_t so = SW128(r * 128 + c16 * 16);
            cp16(SBB + so,         kgh + go);
            cp16(SBB + 8192 + so,  kgl + go);
            cp16(SBB + 16384 + so, vgh + go);
            cp16(SBB + 24576 + so, vgl + go);
        }
        cp_commit();
    };

    issue_kv(0, 0);
    cp_wait<1>();
    __syncthreads();

    uint32_t aqh[4][4], aql[4][4];
#pragma unroll
    for (int ks = 0; ks < 4; ks++) {
        int row = wid * 16 + (lane & 15);
        int colb = ks * 32 + ((lane >> 4) << 4);
        uint32_t off = SW128(row * 128 + colb);
        ldm_x4(QH + off, aqh[ks]);
        ldm_x4(QL + off, aql[ks]);
    }

    float o[8][4];
#pragma unroll
    for (int nt = 0; nt < 8; nt++)
#pragma unroll
        for (int e = 0; e < 4; e++) o[nt][e] = 0.f;
    float rs0 = 0.f, rs1 = 0.f;

    const float SC = 0.125f;

    for (int t = 0; t < 16; t++) {
        int bufi = t & 1;
        if (t + 1 < 16) { issue_kv(t + 1, bufi ^ 1); cp_wait<1>(); }
        else            { cp_wait<0>(); }
        __syncthreads();

        uint32_t SBB = ST + bufi * 32768;

        float s[8][4];
#pragma unroll
        for (int nt = 0; nt < 8; nt++)
#pragma unroll
            for (int e = 0; e < 4; e++) s[nt][e] = 0.f;

#pragma unroll
        for (int ks = 0; ks < 4; ks++) {
            uint32_t bh[8][2], bl[8][2];
#pragma unroll
            for (int bt = 0; bt < 4; bt++) {
                int row = bt * 16 + ((lane >> 4) << 3) + (lane & 7);
                int colb = ks * 32 + (((lane >> 3) & 1) << 4);
                uint32_t off = SW128(row * 128 + colb);
                uint32_t tr[4];
                ldm_x4(SBB + off, tr);
                bh[bt * 2][0] = tr[0];     bh[bt * 2][1] = tr[1];
                bh[bt * 2 + 1][0] = tr[2]; bh[bt * 2 + 1][1] = tr[3];
                ldm_x4(SBB + 8192 + off, tr);
                bl[bt * 2][0] = tr[0];     bl[bt * 2][1] = tr[1];
                bl[bt * 2 + 1][0] = tr[2]; bl[bt * 2 + 1][1] = tr[3];
            }
#pragma unroll
            for (int nt = 0; nt < 8; nt++) {
                mma16816(s[nt], aqh[ks], bh[nt]);
                mma16816(s[nt], aqh[ks], bl[nt]);
                mma16816(s[nt], aql[ks], bh[nt]);
            }
        }

        uint32_t pah[4][4], pal[4][4];
#pragma unroll
        for (int nt = 0; nt < 8; nt++) {
            float p0 = __expf(s[nt][0] * SC);
            float p1 = __expf(s[nt][1] * SC);
            float p2 = __expf(s[nt][2] * SC);
            float p3 = __expf(s[nt][3] * SC);
            rs0 += p0 + p1;
            rs1 += p2 + p3;
            bf16 h0, l0, h1, l1, h2, l2, h3, l3;
            bsplit(p0, h0, l0); bsplit(p1, h1, l1);
            bsplit(p2, h2, l2); bsplit(p3, h3, l3);
            int j = nt >> 1, half = nt & 1;
            pah[j][half * 2]     = packbf(h0, h1);
            pah[j][half * 2 + 1] = packbf(h2, h3);
            pal[j][half * 2]     = packbf(l0, l1);
            pal[j][half * 2 + 1] = packbf(l2, l3);
        }

#pragma unroll
        for (int j = 0; j < 4; j++) {
            uint32_t vbh[8][2], vbl[8][2];
#pragma unroll
            for (int nh = 0; nh < 4; nh++) {
                int row = j * 16 + (lane & 15);
                int colb = nh * 32 + ((lane >> 4) << 4);
                uint32_t off = SW128(row * 128 + colb);
                uint32_t tr[4];
                ldm_x4_t(SBB + 16384 + off, tr);
                vbh[nh * 2][0] = tr[0];     vbh[nh * 2][1] = tr[1];
                vbh[nh * 2 + 1][0] = tr[2]; vbh[nh * 2 + 1][1] = tr[3];
                ldm_x4_t(SBB + 24576 + off, tr);
                vbl[nh * 2][0] = tr[0];     vbl[nh * 2][1] = tr[1];
                vbl[nh * 2 + 1][0] = tr[2]; vbl[nh * 2 + 1][1] = tr[3];
            }
#pragma unroll
            for (int nt = 0; nt < 8; nt++) {
                mma16816(o[nt], pah[j], vbh[nt]);
                mma16816(o[nt], pah[j], vbl[nt]);
                mma16816(o[nt], pal[j], vbh[nt]);
            }
        }
        __syncthreads();
    }

    rs0 += __shfl_xor_sync(0xffffffffu, rs0, 1);
    rs0 += __shfl_xor_sync(0xffffffffu, rs0, 2);
    rs1 += __shfl_xor_sync(0xffffffffu, rs1, 1);
    rs1 += __shfl_xor_sync(0xffffffffu, rs1, 2);

    int g = lane >> 2, tc = (lane & 3) * 2;
    int row0 = q0 + wid * 16 + g;
    float i0 = 1.f / rs0, i1 = 1.f / rs1;
#pragma unroll
    for (int nt = 0; nt < 8; nt++) {
        int col = h * DH + nt * 8 + tc;
        size_t off0 = (size_t)(b * NQ + row0) * CD + col;
        size_t off1 = off0 + (size_t)8 * CD;
        float v0 = o[nt][0] * i0, v1 = o[nt][1] * i0;
        float v2 = o[nt][2] * i1, v3 = o[nt][3] * i1;
        bf16 h0, l0, h1, l1;
        bsplit(v0, h0, l0); bsplit(v1, h1, l1);
        *(__nv_bfloat162*)(g_o_hi + off0) = __halves2bfloat162(h0, h1);
        *(__nv_bfloat162*)(g_o_lo + off0) = __halves2bfloat162(l0, l1);
        bsplit(v2, h0, l0); bsplit(v3, h1, l1);
        *(__nv_bfloat162*)(g_o_hi + off1) = __halves2bfloat162(h0, h1);
        *(__nv_bfloat162*)(g_o_lo + off1) = __halves2bfloat162(l0, l1);
    }
}

// ---------------------------------------------------------------------------
// kernel_launch
// ---------------------------------------------------------------------------
extern "C" void kernel_launch(void* const* d_in, const int* in_sizes, int n_in,
                              void* d_out, int out_size) {
    const float* x     = (const float*)d_in[0];
    const float* Wq    = (const float*)d_in[1];
    const float* bq    = (const float*)d_in[2];
    const float* Wkv   = (const float*)d_in[3];
    const float* bkv   = (const float*)d_in[4];
    const float* Wproj = (const float*)d_in[5];
    const float* bproj = (const float*)d_in[6];
    const float* Aq    = (const float*)d_in[7];
    const float* Bq    = (const float*)d_in[8];
    const float* Av    = (const float*)d_in[9];
    const float* Bv    = (const float*)d_in[10];
    const float* Wsr   = (const float*)d_in[11];
    const float* bsr   = (const float*)d_in[12];
    const float* gamma = (const float*)d_in[13];
    const float* beta  = (const float*)d_in[14];
    float* outp = (float*)d_out;

    bf16 *xsh, *xsl, *oh, *ol, *pqh, *pql, *pkvh, *pkvl, *bkvh, *bkvl, *bph, *bpl;
    cudaGetSymbolAddress((void**)&bkvh, g_BkvT_hi);cudaGetSymbolAddress((void**)&bkvl, g_BkvT_lo);
    cudaGetSymbolAddress((void**)&bph,  g_BpT_hi); cudaGetSymbolAddress((void**)&bpl,  g_BpT_lo);
    cudaGetSymbolAddress((void**)&xsh,  g_xs_hi);  cudaGetSymbolAddress((void**)&xsl,  g_xs_lo);
    cudaGetSymbolAddress((void**)&oh,   g_o_hi);   cudaGetSymbolAddress((void**)&ol,   g_o_lo);
    cudaGetSymbolAddress((void**)&pqh,  g_q_hi);   cudaGetSymbolAddress((void**)&pql,  g_q_lo);
    cudaGetSymbolAddress((void**)&pkvh, g_kv_hi);  cudaGetSymbolAddress((void**)&pkvl, g_kv_lo);

    cudaFuncSetAttribute(gemm_bf16x3<0>, cudaFuncAttributeMaxDynamicSharedMemorySize, GEMM_SMEM);
    cudaFuncSetAttribute(gemm_bf16x3<1>, cudaFuncAttributeMaxDynamicSharedMemorySize, GEMM_SMEM);
    cudaFuncSetAttribute(gemm_q_xs, cudaFuncAttributeMaxDynamicSharedMemorySize, GEMM_SMEM);
    cudaFuncSetAttribute(attn_hmma, cudaFuncAttributeMaxDynamicSharedMemorySize, ATTN_SMEM);

    // 1) merged prep: split x + weight transpose/LoRA/split
    prep_all<<<6144, 256>>>(x, Wq, Aq, Bq, Wkv, Av, Bv, Wsr, Wproj);

    // 2) merged: xs GEMM (K=2048, permuted A from g_x) + q GEMM (K=512)
    gemm_q_xs<<<dim3(2, 80), 256, GEMM_SMEM>>>(bq, bsr);

    // 3) LayerNorm -> split bf16
    ln_split_kernel<<<NB * NKV, 256>>>(gamma, beta);

    // 4) kv GEMM (2048 x 1024, K=512), split bf16 out
    gemm_bf16x3<1><<<dim3(4, 16), 256, GEMM_SMEM>>>(
        xsh, xsl, bkvh, bkvl, bkv, pkvh, pkvl, CD, 2 * CD);

    // 5) attention (HMMA bf16x3) -> split bf16
    attn_hmma<<<dim3(NQ / 128, NHEAD, NB), 256, ATTN_SMEM>>>(pqh, pql, pkvh, pkvl);

    // 6) out GEMM -> d_out (fp32)
    gemm_bf16x3<0><<<dim3(2, 64), 256, GEMM_SMEM>>>(
        oh, ol, bph, bpl, bproj, outp, nullptr, CD, CD);
}

// round 10
// speedup vs baseline: 1.2217x; 1.2217x over previous
#include <cuda_runtime.h>
#include <cuda_bf16.h>
#include <cstdint>
#include <math.h>

#define NB    2
#define NQ    4096
#define NKV   1024
#define CD    512
#define NHEAD 8
#define DH    64
#define RLORA 8
#define LN_EPS 1e-5f

typedef __nv_bfloat16 bf16;

// ---------------------------------------------------------------------------
// Device scratch
// ---------------------------------------------------------------------------
__device__ bf16  g_x_hi [NB*NQ*CD],      g_x_lo [NB*NQ*CD];
__device__ bf16  g_BqT_hi[CD*CD],        g_BqT_lo[CD*CD];
__device__ bf16  g_BkvT_hi[2*CD*CD],     g_BkvT_lo[2*CD*CD];
__device__ bf16  g_BsrT_hi[CD*4*CD],     g_BsrT_lo[CD*4*CD];
__device__ bf16  g_BpT_hi[CD*CD],        g_BpT_lo[CD*CD];
__device__ bf16  g_q_hi [NB*NQ*CD],      g_q_lo [NB*NQ*CD];
__device__ float g_xs [NB*NKV*CD];
__device__ bf16  g_kv_hi[NB*NKV*2*CD],   g_kv_lo[NB*NKV*2*CD];
__device__ bf16  g_xs_hi[NB*NKV*CD],     g_xs_lo[NB*NKV*CD];
__device__ bf16  g_o_hi[NB*NQ*CD],       g_o_lo[NB*NQ*CD];

// ---------------------------------------------------------------------------
// helpers
// ---------------------------------------------------------------------------
__device__ __forceinline__ uint32_t smem_u32(const void* p) {
    uint32_t a;
    asm("{ .reg .u64 t; cvta.to.shared.u64 t, %1; cvt.u32.u64 %0, t; }" : "=r"(a) : "l"(p));
    return a;
}
#define SW128(o) ((o) ^ (((o) >> 3) & 0x70))

__device__ __forceinline__ void cp16(uint32_t dst, const void* src) {
    asm volatile("cp.async.cg.shared.global [%0], [%1], 16;" :: "r"(dst), "l"(src));
}
__device__ __forceinline__ void cp_commit() { asm volatile("cp.async.commit_group;"); }
template<int N> __device__ __forceinline__ void cp_wait() {
    asm volatile("cp.async.wait_group %0;" :: "n"(N));
}

__device__ __forceinline__ void ldm_x4(uint32_t addr, uint32_t* r) {
    asm volatile("ldmatrix.sync.aligned.m8n8.x4.shared.b16 {%0,%1,%2,%3}, [%4];"
        : "=r"(r[0]), "=r"(r[1]), "=r"(r[2]), "=r"(r[3]) : "r"(addr));
}
__device__ __forceinline__ void ldm_x4_t(uint32_t addr, uint32_t* r) {
    asm volatile("ldmatrix.sync.aligned.m8n8.x4.trans.shared.b16 {%0,%1,%2,%3}, [%4];"
        : "=r"(r[0]), "=r"(r[1]), "=r"(r[2]), "=r"(r[3]) : "r"(addr));
}
__device__ __forceinline__ void mma16816(float* c, const uint32_t* a, const uint32_t* b) {
    asm volatile("mma.sync.aligned.m16n8k16.row.col.f32.bf16.bf16.f32 "
        "{%0,%1,%2,%3}, {%4,%5,%6,%7}, {%8,%9}, {%0,%1,%2,%3};"
        : "+f"(c[0]), "+f"(c[1]), "+f"(c[2]), "+f"(c[3])
        : "r"(a[0]), "r"(a[1]), "r"(a[2]), "r"(a[3]), "r"(b[0]), "r"(b[1]));
}

__device__ __forceinline__ void bsplit(float a, bf16& hi, bf16& lo) {
    hi = __float2bfloat16_rn(a);
    lo = __float2bfloat16_rn(a - __bfloat162float(hi));
}
__device__ __forceinline__ uint32_t packbf(bf16 a, bf16 b) {
    __nv_bfloat162 h = __halves2bfloat162(a, b);
    return *reinterpret_cast<uint32_t*>(&h);
}

// ---------------------------------------------------------------------------
// GEMM core (HMMA bf16x3): C[M,N] = A @ B^T + bias
//   tile 128x128, BK=64, 256 threads, 8 warps (2x4), warp tile 64x32,
//   cp.async 3-stage. OB=0: fp32 out; OB=1: split bf16 out.
//   PERM=1: A addresses the conv patch permutation of g_x (K=2048).
//   bf16x3 terms issued in 3 passes to break accumulator chains
//   (per-accumulator order unchanged: hh, hl, lh -> bit-identical).
// ---------------------------------------------------------------------------
#define TILE_B  16384
#define STAGE_B (4 * TILE_B)
#define GEMM_SMEM (3 * STAGE_B)     // 192 KB, 3 stages

template<int OB, int PERM>
__device__ __forceinline__ void gemm_core(
    uint32_t sb,
    const bf16* __restrict__ Ah, const bf16* __restrict__ Al,
    const bf16* __restrict__ Bh, const bf16* __restrict__ Bl,
    const float* __restrict__ bias, void* __restrict__ Cv, void* __restrict__ Cv2,
    int K, int ldc, int bx, int by)
{
    int tid = threadIdx.x, wid = tid >> 5, lane = tid & 31;

    const bf16* aAh = PERM ? Ah : Ah + (size_t)by * 128 * K;
    const bf16* aAl = PERM ? Al : Al + (size_t)by * 128 * K;
    const bf16* aBh = Bh + (size_t)bx * 128 * K;
    const bf16* aBl = Bl + (size_t)bx * 128 * K;

    auto issue = [&](int chunk, int buf) {
        int k0 = chunk << 6;
        uint32_t stg = sb + buf * STAGE_B;
        // A tiles (hi, lo)
#pragma unroll
        for (int t = 0; t < 2; t++) {
            const bf16* src = t ? aAl : aAh;
#pragma unroll
            for (int it = 0; it < 4; it++) {
                int idx = it * 256 + tid;
                int r = idx >> 3, c16 = idx & 7;
                size_t goff;
                if (PERM) {
                    int m = by * 128 + r;
                    int p = k0 >> 9;                 // patch index 0..3
                    int bb = m >> 10, pp = m & 1023;
                    int tok = bb * NQ + ((pp >> 5) * 2 + (p >> 1)) * 64
                            + ((pp & 31) * 2 + (p & 1));
                    goff = (size_t)tok * CD + (k0 & 511) + c16 * 8;
                } else {
                    goff = (size_t)r * K + k0 + c16 * 8;
                }
                cp16(stg + t * TILE_B + SW128(r * 128 + c16 * 16), src + goff);
            }
        }
        // B tiles (hi, lo)
#pragma unroll
        for (int t = 0; t < 2; t++) {
            const bf16* src = (t ? aBl : aBh) + k0;
#pragma unroll
            for (int it = 0; it < 4; it++) {
                int idx = it * 256 + tid;
                int r = idx >> 3, c16 = idx & 7;
                cp16(stg + (2 + t) * TILE_B + SW128(r * 128 + c16 * 16),
                     src + (size_t)r * K + c16 * 8);
            }
        }
        cp_commit();
    };

    float acc[4][4][4];
#pragma unroll
    for (int i = 0; i < 4; i++)
#pragma unroll
        for (int j = 0; j < 4; j++)
#pragma unroll
            for (int e = 0; e < 4; e++) acc[i][j][e] = 0.f;

    int wm = wid >> 2, wn = wid & 3;
    int nch = K >> 6;

    issue(0, 0);
    if (nch > 1) issue(1, 1);
    for (int i = 0; i < nch; i++) {
        int buf = i % 3;
        if (i + 2 < nch) { issue(i + 2, (i + 2) % 3); cp_wait<2>(); }
        else if (i + 1 < nch) { cp_wait<1>(); }
        else { cp_wait<0>(); }
        __syncthreads();

        uint32_t aH = sb + buf * STAGE_B;
        uint32_t aL = aH + TILE_B;
        uint32_t bH = aH + 2 * TILE_B;
        uint32_t bL = aH + 3 * TILE_B;

#pragma unroll
        for (int ks = 0; ks < 4; ks++) {
            int kb = ks * 32;
            uint32_t ah[4][4], al[4][4], bh[4][2], bl[4][2];
#pragma unroll
            for (int at = 0; at < 4; at++) {
                int row = wm * 64 + at * 16 + (lane & 15);
                int colb = kb + ((lane >> 4) << 4);
                uint32_t off = SW128(row * 128 + colb);
                ldm_x4(aH + off, ah[at]);
                ldm_x4(aL + off, al[at]);
            }
#pragma unroll
            for (int bt = 0; bt < 2; bt++) {
                int row = wn * 32 + bt * 16 + ((lane >> 4) << 3) + (lane & 7);
                int colb = kb + (((lane >> 3) & 1) << 4);
                uint32_t off = SW128(row * 128 + colb);
                uint32_t t[4];
                ldm_x4(bH + off, t);
                bh[bt * 2][0] = t[0]; bh[bt * 2][1] = t[1];
                bh[bt * 2 + 1][0] = t[2]; bh[bt * 2 + 1][1] = t[3];
                ldm_x4(bL + off, t);
                bl[bt * 2][0] = t[0]; bl[bt * 2][1] = t[1];
                bl[bt * 2 + 1][0] = t[2]; bl[bt * 2 + 1][1] = t[3];
            }
            // three passes: hh, hl, lh -- breaks per-accumulator chains,
            // per-accumulator add order unchanged (bit-identical).
#pragma unroll
            for (int at = 0; at < 4; at++)
#pragma unroll
                for (int nt = 0; nt < 4; nt++)
                    mma16816(acc[at][nt], ah[at], bh[nt]);
#pragma unroll
            for (int at = 0; at < 4; at++)
#pragma unroll
                for (int nt = 0; nt < 4; nt++)
                    mma16816(acc[at][nt], ah[at], bl[nt]);
#pragma unroll
            for (int at = 0; at < 4; at++)
#pragma unroll
                for (int nt = 0; nt < 4; nt++)
                    mma16816(acc[at][nt], al[at], bh[nt]);
        }
        __syncthreads();
    }

    int g = lane >> 2, tc = (lane & 3) * 2;
#pragma unroll
    for (int nt = 0; nt < 4; nt++) {
        int col = bx * 128 + wn * 32 + nt * 8 + tc;
        float b0 = bias[col], b1 = bias[col + 1];
#pragma unroll
        for (int at = 0; at < 4; at++) {
            int row0 = by * 128 + wm * 64 + at * 16 + g;
            float v00 = acc[at][nt][0] + b0, v01 = acc[at][nt][1] + b1;
            float v10 = acc[at][nt][2] + b0, v11 = acc[at][nt][3] + b1;
            if (OB) {
                bf16* C  = (bf16*)Cv;
                bf16* C2 = (bf16*)Cv2;
                bf16 h0, l0, h1, l1;
                bsplit(v00, h0, l0); bsplit(v01, h1, l1);
                *(uint32_t*)(C  + (size_t)row0 * ldc + col) = packbf(h0, h1);
                *(uint32_t*)(C2 + (size_t)row0 * ldc + col) = packbf(l0, l1);
                bsplit(v10, h0, l0); bsplit(v11, h1, l1);
                *(uint32_t*)(C  + (size_t)(row0 + 8) * ldc + col) = packbf(h0, h1);
                *(uint32_t*)(C2 + (size_t)(row0 + 8) * ldc + col) = packbf(l0, l1);
            } else {
                float* C = (float*)Cv;
                *(float2*)(C + (size_t)row0 * ldc + col)       = make_float2(v00, v01);
                *(float2*)(C + (size_t)(row0 + 8) * ldc + col) = make_float2(v10, v11);
            }
        }
    }
}

template<int OB>
__global__ __launch_bounds__(256, 1) void gemm_bf16x3(
    const bf16* __restrict__ Ah, const bf16* __restrict__ Al,
    const bf16* __restrict__ Bh, const bf16* __restrict__ Bl,
    const float* __restrict__ bias, void* __restrict__ Cv, void* __restrict__ Cv2,
    int K, int ldc)
{
    extern __shared__ char smem[];
    gemm_core<OB, 0>(smem_u32(smem), Ah, Al, Bh, Bl, bias, Cv, Cv2, K, ldc,
                     blockIdx.x, blockIdx.y);
}

// Merged independent GEMMs: grid (4, 80).
//  by in [0,16):  xs = patch(x) @ WsrT + bsr  (2048 x 512, K=2048, fp32 out)
//  by in [16,80): q  = x @ WqT + bq           (8192 x 512, K=512, split bf16)
__global__ __launch_bounds__(256, 1) void gemm_q_xs(
    const float* __restrict__ bq, const float* __restrict__ bsr)
{
    extern __shared__ char smem[];
    uint32_t sb = smem_u32(smem);
    if (blockIdx.y < 16) {
        gemm_core<0, 1>(sb, g_x_hi, g_x_lo, g_BsrT_hi, g_BsrT_lo, bsr,
                        (void*)g_xs, nullptr, 4 * CD, CD, blockIdx.x, blockIdx.y);
    } else {
        gemm_core<1, 0>(sb, g_x_hi, g_x_lo, g_BqT_hi, g_BqT_lo, bq,
                        (void*)g_q_hi, (void*)g_q_lo, CD, CD, blockIdx.x, blockIdx.y - 16);
    }
}

// ---------------------------------------------------------------------------
// Merged prep: blocks [0,4096) split x into bf16 hi/lo;
//              blocks [4096,6144) transpose+LoRA-fold+split the weights.
// ---------------------------------------------------------------------------
__global__ __launch_bounds__(256) void prep_all(
    const float* __restrict__ x,
    const float* __restrict__ Wq,   const float* __restrict__ Aq, const float* __restrict__ Bq,
    const float* __restrict__ Wkv,  const float* __restrict__ Av, const float* __restrict__ Bv,
    const float* __restrict__ Wsr,  const float* __restrict__ Wproj)
{
    if (blockIdx.x < 4096) {
        int e = blockIdx.x * 256 + threadIdx.x;      // < 1048576 float4
        float4 v = ((const float4*)x)[e];
        bf16 h0, l0, h1, l1, h2, l2, h3, l3;
        bsplit(v.x, h0, l0); bsplit(v.y, h1, l1);
        bsplit(v.z, h2, l2); bsplit(v.w, h3, l3);
        ((uint32_t*)g_x_hi)[e * 2]     = packbf(h0, h1);
        ((uint32_t*)g_x_hi)[e * 2 + 1] = packbf(h2, h3);
        ((uint32_t*)g_x_lo)[e * 2]     = packbf(l0, l1);
        ((uint32_t*)g_x_lo)[e * 2 + 1] = packbf(l2, l3);
        return;
    }

    __shared__ float tile[32][33];
    int t = blockIdx.x - 4096;
    const float *W, *A = nullptr, *LB = nullptr;
    bf16 *Dh, *Dl;
    int K, stride, k0, n0;

    if (t < 256) {
        W = Wq; A = Aq; LB = Bq; Dh = g_BqT_hi; Dl = g_BqT_lo;
        K = 512; stride = 512; k0 = (t >> 4) * 32; n0 = (t & 15) * 32;
    } else if (t < 768) {
        int i = t - 256;
        W = Wkv; A = Av; LB = Bv; Dh = g_BkvT_hi; Dl = g_BkvT_lo;
        K = 512; stride = 1024; k0 = (i >> 5) * 32; n0 = (i & 31) * 32;
    } else if (t < 1792) {
        int i = t - 768;
        W = Wsr; Dh = g_BsrT_hi; Dl = g_BsrT_lo;
        K = 2048; stride = 512; k0 = (i >> 4) * 32; n0 = (i & 15) * 32;
    } else {
        int i = t - 1792;
        W = Wproj; Dh = g_BpT_hi; Dl = g_BpT_lo;
        K = 512; stride = 512; k0 = (i >> 4) * 32; n0 = (i & 15) * 32;
    }

    int tx = threadIdx.x & 31, ty = threadIdx.x >> 5;
#pragma unroll
    for (int i = 0; i < 4; i++) {
        int k = k0 + ty + i * 8, n = n0 + tx;
        float v = W[(size_t)k * stride + n];
        if (A) {
            float l = 0.f;
#pragma unroll
            for (int r = 0; r < RLORA; r++)
                l = fmaf(A[k * RLORA + r], LB[r * CD + (n & (CD - 1))], l);
            v += l;
        }
        tile[ty + i * 8][tx] = v;
    }
    __syncthreads();
#pragma unroll
    for (int i = 0; i < 4; i++) {
        int n = n0 + ty + i * 8, k = k0 + tx;
        float v = tile[tx][ty + i * 8];
        bf16 h, l; bsplit(v, h, l);
        Dh[(size_t)n * K + k] = h;
        Dl[(size_t)n * K + k] = l;
    }
}

// ---------------------------------------------------------------------------
// LayerNorm -> split bf16
// ---------------------------------------------------------------------------
__device__ __forceinline__ float warp_sum(float v) {
#pragma unroll
    for (int o = 16; o > 0; o >>= 1) v += __shfl_xor_sync(0xffffffffu, v, o);
    return v;
}

__global__ __launch_bounds__(256) void ln_split_kernel(const float* __restrict__ gamma,
                                                       const float* __restrict__ beta) {
    int row = blockIdx.x;
    const float* p = g_xs + (size_t)row * CD;
    int tid = threadIdx.x;
    float a = p[tid], c = p[tid + 256];

    float s  = warp_sum(a + c);
    float sq = warp_sum(a * a + c * c);
    __shared__ float sh[16];
    int w = tid >> 5, l = tid & 31;
    if (l == 0) { sh[w] = s; sh[8 + w] = sq; }
    __syncthreads();
    if (w == 0) {
        float ts = (l < 8) ? sh[l] : 0.f;
        float tq = (l < 8) ? sh[8 + l] : 0.f;
        ts = warp_sum(ts); tq = warp_sum(tq);
        if (l == 0) { sh[0] = ts; sh[1] = tq; }
    }
    __syncthreads();
    float mean = sh[0] * (1.f / CD);
    float var  = sh[1] * (1.f / CD) - mean * mean;
    float inv  = rsqrtf(var + LN_EPS);
    float y0 = (a - mean) * inv * gamma[tid] + beta[tid];
    float y1 = (c - mean) * inv * gamma[tid + 256] + beta[tid + 256];
    bf16 h, lo;
    bsplit(y0, h, lo); g_xs_hi[(size_t)row * CD + tid] = h;       g_xs_lo[(size_t)row * CD + tid] = lo;
    bsplit(y1, h, lo); g_xs_hi[(size_t)row * CD + tid + 256] = h; g_xs_lo[(size_t)row * CD + tid + 256] = lo;
}

// ---------------------------------------------------------------------------
// HMMA flash attention with bf16x3 in BOTH matmuls.
// grid (NQ/128, NHEAD, NB), 256 threads (8 warps x 16 q-rows).
// bf16x3 terms in 3 passes (chain-breaking; bit-identical per accumulator).
// ---------------------------------------------------------------------------
#define ATTN_SMEM (32768 + 65536)   // 96 KB

__global__ __launch_bounds__(256, 1) void attn_hmma(
    const bf16* __restrict__ qh, const bf16* __restrict__ ql,
    const bf16* __restrict__ kvh, const bf16* __restrict__ kvl)
{
    extern __shared__ char smem[];
    uint32_t sb = smem_u32(smem);
    const uint32_t QH = sb, QL = sb + 16384, ST = sb + 32768;

    int tid = threadIdx.x, lane = tid & 31, wid = tid >> 5;
    int b = blockIdx.z, h = blockIdx.y;
    int q0 = blockIdx.x * 128;

    const bf16* qgh = qh + (size_t)(b * NQ + q0) * CD + h * DH;
    const bf16* qgl = ql + (size_t)(b * NQ + q0) * CD + h * DH;
    const bf16* kgh = kvh + (size_t)b * NKV * (2 * CD) + h * DH;
    const bf16* kgl = kvl + (size_t)b * NKV * (2 * CD) + h * DH;
    const bf16* vgh = kgh + CD;
    const bf16* vgl = kgl + CD;

#pragma unroll
    for (int it = 0; it < 4; it++) {
        int idx = it * 256 + tid;
        int r = idx >> 3, c16 = idx & 7;
        uint32_t so = SW128(r * 128 + c16 * 16);
        size_t go = (size_t)r * CD + c16 * 8;
        cp16(QH + so, qgh + go);
        cp16(QL + so, qgl + go);
    }
    cp_commit();

    auto issue_kv = [&](int t, int bufi) {
        int m0 = t * 64;
        uint32_t SBB = ST + bufi * 32768;
#pragma unroll
        for (int it = 0; it < 2; it++) {
            int idx = it * 256 + tid;
            int r = idx >> 3, c16 = idx & 7;
            size_t go = (size_t)(m0 + r) * (2 * CD) + c16 * 8;
            uint32_t so = SW128(r * 128 + c16 * 16);
            cp16(SBB + so,         kgh + go);
            cp16(SBB + 8192 + so,  kgl + go);
            cp16(SBB + 16384 + so, vgh + go);
            cp16(SBB + 24576 + so, vgl + go);
        }
        cp_commit();
    };

    issue_kv(0, 0);
    cp_wait<1>();
    __syncthreads();

    uint32_t aqh[4][4], aql[4][4];
#pragma unroll
    for (int ks = 0; ks < 4; ks++) {
        int row = wid * 16 + (lane & 15);
        int colb = ks * 32 + ((lane >> 4) << 4);
        uint32_t off = SW128(row * 128 + colb);
        ldm_x4(QH + off, aqh[ks]);
        ldm_x4(QL + off, aql[ks]);
    }

    float o[8][4];
#pragma unroll
    for (int nt = 0; nt < 8; nt++)
#pragma unroll
        for (int e = 0; e < 4; e++) o[nt][e] = 0.f;
    float rs0 = 0.f, rs1 = 0.f;

    const float SC = 0.125f;

    for (int t = 0; t < 16; t++) {
        int bufi = t & 1;
        if (t + 1 < 16) { issue_kv(t + 1, bufi ^ 1); cp_wait<1>(); }
        else            { cp_wait<0>(); }
        __syncthreads();

        uint32_t SBB = ST + bufi * 32768;

        float s[8][4];
#pragma unroll
        for (int nt = 0; nt < 8; nt++)
#pragma unroll
            for (int e = 0; e < 4; e++) s[nt][e] = 0.f;

#pragma unroll
        for (int ks = 0; ks < 4; ks++) {
            uint32_t bh[8][2], bl[8][2];
#pragma unroll
            for (int bt = 0; bt < 4; bt++) {
                int row = bt * 16 + ((lane >> 4) << 3) + (lane & 7);
                int colb = ks * 32 + (((lane >> 3) & 1) << 4);
                uint32_t off = SW128(row * 128 + colb);
                uint32_t tr[4];
                ldm_x4(SBB + off, tr);
                bh[bt * 2][0] = tr[0];     bh[bt * 2][1] = tr[1];
                bh[bt * 2 + 1][0] = tr[2]; bh[bt * 2 + 1][1] = tr[3];
                ldm_x4(SBB + 8192 + off, tr);
                bl[bt * 2][0] = tr[0];     bl[bt * 2][1] = tr[1];
                bl[bt * 2 + 1][0] = tr[2]; bl[bt * 2 + 1][1] = tr[3];
            }
            // three passes over nt (chain-breaking)
#pragma unroll
            for (int nt = 0; nt < 8; nt++)
                mma16816(s[nt], aqh[ks], bh[nt]);
#pragma unroll
            for (int nt = 0; nt < 8; nt++)
                mma16816(s[nt], aqh[ks], bl[nt]);
#pragma unroll
            for (int nt = 0; nt < 8; nt++)
                mma16816(s[nt], aql[ks], bh[nt]);
        }

        uint32_t pah[4][4], pal[4][4];
#pragma unroll
        for (int nt = 0; nt < 8; nt++) {
            float p0 = __expf(s[nt][0] * SC);
            float p1 = __expf(s[nt][1] * SC);
            float p2 = __expf(s[nt][2] * SC);
            float p3 = __expf(s[nt][3] * SC);
            rs0 += p0 + p1;
            rs1 += p2 + p3;
            bf16 h0, l0, h1, l1, h2, l2, h3, l3;
            bsplit(p0, h0, l0); bsplit(p1, h1, l1);
            bsplit(p2, h2, l2); bsplit(p3, h3, l3);
            int j = nt >> 1, half = nt & 1;
            pah[j][half * 2]     = packbf(h0, h1);
            pah[j][half * 2 + 1] = packbf(h2, h3);
            pal[j][half * 2]     = packbf(l0, l1);
            pal[j][half * 2 + 1] = packbf(l2, l3);
        }

#pragma unroll
        for (int j = 0; j < 4; j++) {
            uint32_t vbh[8][2], vbl[8][2];
#pragma unroll
            for (int nh = 0; nh < 4; nh++) {
                int row = j * 16 + (lane & 15);
                int colb = nh * 32 + ((lane >> 4) << 4);
                uint32_t off = SW128(row * 128 + colb);
                uint32_t tr[4];
                ldm_x4_t(SBB + 16384 + off, tr);
                vbh[nh * 2][0] = tr[0];     vbh[nh * 2][1] = tr[1];
                vbh[nh * 2 + 1][0] = tr[2]; vbh[nh * 2 + 1][1] = tr[3];
                ldm_x4_t(SBB + 24576 + off, tr);
                vbl[nh * 2][0] = tr[0];     vbl[nh * 2][1] = tr[1];
                vbl[nh * 2 + 1][0] = tr[2]; vbl[nh * 2 + 1][1] = tr[3];
            }
            // three passes over nt (chain-breaking)
#pragma unroll
            for (int nt = 0; nt < 8; nt++)
                mma16816(o[nt], pah[j], vbh[nt]);
#pragma unroll
            for (int nt = 0; nt < 8; nt++)
                mma16816(o[nt], pah[j], vbl[nt]);
#pragma unroll
            for (int nt = 0; nt < 8; nt++)
                mma16816(o[nt], pal[j], vbh[nt]);
        }
        __syncthreads();
    }

    rs0 += __shfl_xor_sync(0xffffffffu, rs0, 1);
    rs0 += __shfl_xor_sync(0xffffffffu, rs0, 2);
    rs1 += __shfl_xor_sync(0xffffffffu, rs1, 1);
    rs1 += __shfl_xor_sync(0xffffffffu, rs1, 2);

    int g = lane >> 2, tc = (lane & 3) * 2;
    int row0 = q0 + wid * 16 + g;
    float i0 = 1.f / rs0, i1 = 1.f / rs1;
#pragma unroll
    for (int nt = 0; nt < 8; nt++) {
        int col = h * DH + nt * 8 + tc;
        size_t off0 = (size_t)(b * NQ + row0) * CD + col;
        size_t off1 = off0 + (size_t)8 * CD;
        float v0 = o[nt][0] * i0, v1 = o[nt][1] * i0;
        float v2 = o[nt][2] * i1, v3 = o[nt][3] * i1;
        bf16 h0, l0, h1, l1;
        bsplit(v0, h0, l0); bsplit(v1, h1, l1);
        *(__nv_bfloat162*)(g_o_hi + off0) = __halves2bfloat162(h0, h1);
        *(__nv_bfloat162*)(g_o_lo + off0) = __halves2bfloat162(l0, l1);
        bsplit(v2, h0, l0); bsplit(v3, h1, l1);
        *(__nv_bfloat162*)(g_o_hi + off1) = __halves2bfloat162(h0, h1);
        *(__nv_bfloat162*)(g_o_lo + off1) = __halves2bfloat162(l0, l1);
    }
}

// ---------------------------------------------------------------------------
// kernel_launch
// ---------------------------------------------------------------------------
extern "C" void kernel_launch(void* const* d_in, const int* in_sizes, int n_in,
                              void* d_out, int out_size) {
    const float* x     = (const float*)d_in[0];
    const float* Wq    = (const float*)d_in[1];
    const float* bq    = (const float*)d_in[2];
    const float* Wkv   = (const float*)d_in[3];
    const float* bkv   = (const float*)d_in[4];
    const float* Wproj = (const float*)d_in[5];
    const float* bproj = (const float*)d_in[6];
    const float* Aq    = (const float*)d_in[7];
    const float* Bq    = (const float*)d_in[8];
    const float* Av    = (const float*)d_in[9];
    const float* Bv    = (const float*)d_in[10];
    const float* Wsr   = (const float*)d_in[11];
    const float* bsr   = (const float*)d_in[12];
    const float* gamma = (const float*)d_in[13];
    const float* beta  = (const float*)d_in[14];
    float* outp = (float*)d_out;

    bf16 *xsh, *xsl, *oh, *ol, *pqh, *pql, *pkvh, *pkvl, *bkvh, *bkvl, *bph, *bpl;
    cudaGetSymbolAddress((void**)&bkvh, g_BkvT_hi);cudaGetSymbolAddress((void**)&bkvl, g_BkvT_lo);
    cudaGetSymbolAddress((void**)&bph,  g_BpT_hi); cudaGetSymbolAddress((void**)&bpl,  g_BpT_lo);
    cudaGetSymbolAddress((void**)&xsh,  g_xs_hi);  cudaGetSymbolAddress((void**)&xsl,  g_xs_lo);
    cudaGetSymbolAddress((void**)&oh,   g_o_hi);   cudaGetSymbolAddress((void**)&ol,   g_o_lo);
    cudaGetSymbolAddress((void**)&pqh,  g_q_hi);   cudaGetSymbolAddress((void**)&pql,  g_q_lo);
    cudaGetSymbolAddress((void**)&pkvh, g_kv_hi);  cudaGetSymbolAddress((void**)&pkvl, g_kv_lo);

    cudaFuncSetAttribute(gemm_bf16x3<0>, cudaFuncAttributeMaxDynamicSharedMemorySize, GEMM_SMEM);
    cudaFuncSetAttribute(gemm_bf16x3<1>, cudaFuncAttributeMaxDynamicSharedMemorySize, GEMM_SMEM);
    cudaFuncSetAttribute(gemm_q_xs, cudaFuncAttributeMaxDynamicSharedMemorySize, GEMM_SMEM);
    cudaFuncSetAttribute(attn_hmma, cudaFuncAttributeMaxDynamicSharedMemorySize, ATTN_SMEM);

    // 1) merged prep: split x + weight transpose/LoRA/split
    prep_all<<<6144, 256>>>(x, Wq, Aq, Bq, Wkv, Av, Bv, Wsr, Wproj);

    // 2) merged: xs GEMM (K=2048, permuted A from g_x) + q GEMM (K=512)
    gemm_q_xs<<<dim3(4, 80), 256, GEMM_SMEM>>>(bq, bsr);

    // 3) LayerNorm -> split bf16
    ln_split_kernel<<<NB * NKV, 256>>>(gamma, beta);

    // 4) kv GEMM (2048 x 1024, K=512), split bf16 out
    gemm_bf16x3<1><<<dim3(8, 16), 256, GEMM_SMEM>>>(
        xsh, xsl, bkvh, bkvl, bkv, pkvh, pkvl, CD, 2 * CD);

    // 5) attention (HMMA bf16x3) -> split bf16
    attn_hmma<<<dim3(NQ / 128, NHEAD, NB), 256, ATTN_SMEM>>>(pqh, pql, pkvh, pkvl);

    // 6) out GEMM -> d_out (fp32)
    gemm_bf16x3<0><<<dim3(4, 64), 256, GEMM_SMEM>>>(
        oh, ol, bph, bpl, bproj, outp, nullptr, CD, CD);
}

// round 12
// speedup vs baseline: 1.2891x; 1.0551x over previous
#include <cuda_runtime.h>
#include <cuda_bf16.h>
#include <cstdint>
#include <math.h>

#define NB    2
#define NQ    4096
#define NKV   1024
#define CD    512
#define NHEAD 8
#define DH    64
#define RLORA 8
#define LN_EPS 1e-5f

typedef __nv_bfloat16 bf16;

// ---------------------------------------------------------------------------
// Device scratch
// ---------------------------------------------------------------------------
__device__ bf16  g_x_hi [NB*NQ*CD],      g_x_lo [NB*NQ*CD];
__device__ bf16  g_BqT_hi[CD*CD],        g_BqT_lo[CD*CD];
__device__ bf16  g_BkvT_hi[2*CD*CD],     g_BkvT_lo[2*CD*CD];
__device__ bf16  g_BsrT_hi[CD*4*CD],     g_BsrT_lo[CD*4*CD];   // slice-blocked: [p][n][k]
__device__ bf16  g_BpT_hi[CD*CD],        g_BpT_lo[CD*CD];
__device__ bf16  g_q_hi [NB*NQ*CD],      g_q_lo [NB*NQ*CD];
__device__ float g_xsp[4][NB*NKV*CD];    // split-K partials (one per patch)
__device__ bf16  g_kv_hi[NB*NKV*2*CD],   g_kv_lo[NB*NKV*2*CD];
__device__ bf16  g_xs_hi[NB*NKV*CD],     g_xs_lo[NB*NKV*CD];
__device__ bf16  g_o_hi[NB*NQ*CD],       g_o_lo[NB*NQ*CD];
__device__ float g_zbias[2*CD];          // zero bias (static-zeroed)

// ---------------------------------------------------------------------------
// helpers
// ---------------------------------------------------------------------------
__device__ __forceinline__ uint32_t smem_u32(const void* p) {
    uint32_t a;
    asm("{ .reg .u64 t; cvta.to.shared.u64 t, %1; cvt.u32.u64 %0, t; }" : "=r"(a) : "l"(p));
    return a;
}
#define SW128(o) ((o) ^ (((o) >> 3) & 0x70))

__device__ __forceinline__ void cp16(uint32_t dst, const void* src) {
    asm volatile("cp.async.cg.shared.global [%0], [%1], 16;" :: "r"(dst), "l"(src));
}
__device__ __forceinline__ void cp_commit() { asm volatile("cp.async.commit_group;"); }
template<int N> __device__ __forceinline__ void cp_wait() {
    asm volatile("cp.async.wait_group %0;" :: "n"(N));
}

__device__ __forceinline__ void ldm_x4(uint32_t addr, uint32_t* r) {
    asm volatile("ldmatrix.sync.aligned.m8n8.x4.shared.b16 {%0,%1,%2,%3}, [%4];"
        : "=r"(r[0]), "=r"(r[1]), "=r"(r[2]), "=r"(r[3]) : "r"(addr));
}
__device__ __forceinline__ void ldm_x4_t(uint32_t addr, uint32_t* r) {
    asm volatile("ldmatrix.sync.aligned.m8n8.x4.trans.shared.b16 {%0,%1,%2,%3}, [%4];"
        : "=r"(r[0]), "=r"(r[1]), "=r"(r[2]), "=r"(r[3]) : "r"(addr));
}
__device__ __forceinline__ void mma16816(float* c, const uint32_t* a, const uint32_t* b) {
    asm volatile("mma.sync.aligned.m16n8k16.row.col.f32.bf16.bf16.f32 "
        "{%0,%1,%2,%3}, {%4,%5,%6,%7}, {%8,%9}, {%0,%1,%2,%3};"
        : "+f"(c[0]), "+f"(c[1]), "+f"(c[2]), "+f"(c[3])
        : "r"(a[0]), "r"(a[1]), "r"(a[2]), "r"(a[3]), "r"(b[0]), "r"(b[1]));
}

__device__ __forceinline__ void bsplit(float a, bf16& hi, bf16& lo) {
    hi = __float2bfloat16_rn(a);
    lo = __float2bfloat16_rn(a - __bfloat162float(hi));
}
__device__ __forceinline__ uint32_t packbf(bf16 a, bf16 b) {
    __nv_bfloat162 h = __halves2bfloat162(a, b);
    return *reinterpret_cast<uint32_t*>(&h);
}

// ---------------------------------------------------------------------------
// GEMM core (HMMA bf16x3): C[M,N] = A @ B^T + bias
//   CTA tile 128x64, BK=64, 256 threads, 8 warps (4x2), warp tile 32x32,
//   2-stage cp.async, 96 KB smem -> 2 CTAs/SM (independent barrier domains
//   overlap per-chunk latency; same-CTA warps cannot, per R8).
//   OB=0: fp32 out; OB=1: split bf16 out.
//   PERM=1: A addresses patch `pslice` of the conv permutation of g_x.
// ---------------------------------------------------------------------------
#define A_TILE_B 16384              // 128 rows x 128B
#define B_TILE_B 8192               // 64 rows x 128B
#define STAGE_B  (2 * A_TILE_B + 2 * B_TILE_B)   // 48 KB
#define GEMM_SMEM (2 * STAGE_B)                  // 96 KB

template<int OB, int PERM>
__device__ __forceinline__ void gemm_core(
    uint32_t sb,
    const bf16* __restrict__ Ah, const bf16* __restrict__ Al,
    const bf16* __restrict__ Bh, const bf16* __restrict__ Bl,
    const float* __restrict__ bias, void* __restrict__ Cv, void* __restrict__ Cv2,
    int K, int ldc, int bx, int by, int pslice)
{
    int tid = threadIdx.x, wid = tid >> 5, lane = tid & 31;

    const bf16* aAh = PERM ? Ah : Ah + (size_t)by * 128 * K;
    const bf16* aAl = PERM ? Al : Al + (size_t)by * 128 * K;
    const bf16* aBh = Bh + (size_t)bx * 64 * K;
    const bf16* aBl = Bl + (size_t)bx * 64 * K;

    auto issue = [&](int chunk, int buf) {
        int k0 = chunk << 6;
        uint32_t stg = sb + buf * STAGE_B;
        // A tiles (hi, lo): 1024 16B units each -> 4 per thread
#pragma unroll
        for (int t = 0; t < 2; t++) {
            const bf16* src = t ? aAl : aAh;
#pragma unroll
            for (int it = 0; it < 4; it++) {
                int idx = it * 256 + tid;
                int r = idx >> 3, c16 = idx & 7;
                size_t goff;
                if (PERM) {
                    int m = by * 128 + r;
                    int bb = m >> 10, pp = m & 1023;
                    int tok = bb * NQ + ((pp >> 5) * 2 + (pslice >> 1)) * 64
                            + ((pp & 31) * 2 + (pslice & 1));
                    goff = (size_t)tok * CD + k0 + c16 * 8;
                } else {
                    goff = (size_t)r * K + k0 + c16 * 8;
                }
                cp16(stg + t * A_TILE_B + SW128(r * 128 + c16 * 16), src + goff);
            }
        }
        // B tiles (hi, lo): 512 16B units each -> 2 per thread
#pragma unroll
        for (int t = 0; t < 2; t++) {
            const bf16* src = (t ? aBl : aBh) + k0;
            uint32_t base = stg + 2 * A_TILE_B + t * B_TILE_B;
#pragma unroll
            for (int it = 0; it < 2; it++) {
                int idx = it * 256 + tid;
                int r = idx >> 3, c16 = idx & 7;
                cp16(base + SW128(r * 128 + c16 * 16),
                     src + (size_t)r * K + c16 * 8);
            }
        }
        cp_commit();
    };

    float acc[2][4][4];
#pragma unroll
    for (int i = 0; i < 2; i++)
#pragma unroll
        for (int j = 0; j < 4; j++)
#pragma unroll
            for (int e = 0; e < 4; e++) acc[i][j][e] = 0.f;

    int wm = wid >> 1, wn = wid & 1;     // 4 x 2 warp grid, 32x32 per warp
    int nch = K >> 6;

    issue(0, 0);
    for (int i = 0; i < nch; i++) {
        int buf = i & 1;
        if (i + 1 < nch) { issue(i + 1, buf ^ 1); cp_wait<1>(); }
        else             { cp_wait<0>(); }
        __syncthreads();

        uint32_t stg = sb + buf * STAGE_B;
        uint32_t aH = stg;
        uint32_t aL = stg + A_TILE_B;
        uint32_t bH = stg + 2 * A_TILE_B;
        uint32_t bL = bH + B_TILE_B;

#pragma unroll
        for (int ks = 0; ks < 4; ks++) {
            int kb = ks * 32;
            uint32_t ah[2][4], al[2][4], bh[4][2], bl[4][2];
#pragma unroll
            for (int at = 0; at < 2; at++) {
                int row = wm * 32 + at * 16 + (lane & 15);
                int colb = kb + ((lane >> 4) << 4);
                uint32_t off = SW128(row * 128 + colb);
                ldm_x4(aH + off, ah[at]);
                ldm_x4(aL + off, al[at]);
            }
#pragma unroll
            for (int bt = 0; bt < 2; bt++) {
                int row = wn * 32 + bt * 16 + ((lane >> 4) << 3) + (lane & 7);
                int colb = kb + (((lane >> 3) & 1) << 4);
                uint32_t off = SW128(row * 128 + colb);
                uint32_t t[4];
                ldm_x4(bH + off, t);
                bh[bt * 2][0] = t[0]; bh[bt * 2][1] = t[1];
                bh[bt * 2 + 1][0] = t[2]; bh[bt * 2 + 1][1] = t[3];
                ldm_x4(bL + off, t);
                bl[bt * 2][0] = t[0]; bl[bt * 2][1] = t[1];
                bl[bt * 2 + 1][0] = t[2]; bl[bt * 2 + 1][1] = t[3];
            }
            // three passes (chain-breaking; bit-identical per accumulator)
#pragma unroll
            for (int at = 0; at < 2; at++)
#pragma unroll
                for (int nt = 0; nt < 4; nt++)
                    mma16816(acc[at][nt], ah[at], bh[nt]);
#pragma unroll
            for (int at = 0; at < 2; at++)
#pragma unroll
                for (int nt = 0; nt < 4; nt++)
                    mma16816(acc[at][nt], ah[at], bl[nt]);
#pragma unroll
            for (int at = 0; at < 2; at++)
#pragma unroll
                for (int nt = 0; nt < 4; nt++)
                    mma16816(acc[at][nt], al[at], bh[nt]);
        }
        __syncthreads();
    }

    int g = lane >> 2, tc = (lane & 3) * 2;
#pragma unroll
    for (int nt = 0; nt < 4; nt++) {
        int col = bx * 64 + wn * 32 + nt * 8 + tc;
        float b0 = bias[col], b1 = bias[col + 1];
#pragma unroll
        for (int at = 0; at < 2; at++) {
            int row0 = by * 128 + wm * 32 + at * 16 + g;
            float v00 = acc[at][nt][0] + b0, v01 = acc[at][nt][1] + b1;
            float v10 = acc[at][nt][2] + b0, v11 = acc[at][nt][3] + b1;
            if (OB) {
                bf16* C  = (bf16*)Cv;
                bf16* C2 = (bf16*)Cv2;
                bf16 h0, l0, h1, l1;
                bsplit(v00, h0, l0); bsplit(v01, h1, l1);
                *(uint32_t*)(C  + (size_t)row0 * ldc + col) = packbf(h0, h1);
                *(uint32_t*)(C2 + (size_t)row0 * ldc + col) = packbf(l0, l1);
                bsplit(v10, h0, l0); bsplit(v11, h1, l1);
                *(uint32_t*)(C  + (size_t)(row0 + 8) * ldc + col) = packbf(h0, h1);
                *(uint32_t*)(C2 + (size_t)(row0 + 8) * ldc + col) = packbf(l0, l1);
            } else {
                float* C = (float*)Cv;
                *(float2*)(C + (size_t)row0 * ldc + col)       = make_float2(v00, v01);
                *(float2*)(C + (size_t)(row0 + 8) * ldc + col) = make_float2(v10, v11);
            }
        }
    }
}

template<int OB>
__global__ __launch_bounds__(256, 2) void gemm_bf16x3(
    const bf16* __restrict__ Ah, const bf16* __restrict__ Al,
    const bf16* __restrict__ Bh, const bf16* __restrict__ Bl,
    const float* __restrict__ bias, void* __restrict__ Cv, void* __restrict__ Cv2,
    int K, int ldc)
{
    extern __shared__ char smem[];
    gemm_core<OB, 0>(smem_u32(smem), Ah, Al, Bh, Bl, bias, Cv, Cv2, K, ldc,
                     blockIdx.x, blockIdx.y, 0);
}

// Merged independent GEMMs: grid (8, 128).
//  by in [0,64):   xs partial: slice = by>>4 (the conv patch), m-tile = by&15
//                  (2048 x 512, K=512 per slice, fp32 out, no bias)
//  by in [64,128): q = x @ WqT + bq   (8192 x 512, K=512, split bf16)
__global__ __launch_bounds__(256, 2) void gemm_q_xs(
    const float* __restrict__ bq)
{
    extern __shared__ char smem[];
    uint32_t sb = smem_u32(smem);
    if (blockIdx.y < 64) {
        int slice = blockIdx.y >> 4, mt = blockIdx.y & 15;
        // FIX (R11 bug): slice blocks are CD*CD apart, not CD.
        gemm_core<0, 1>(sb, g_x_hi, g_x_lo,
                        g_BsrT_hi + (size_t)slice * CD * CD,
                        g_BsrT_lo + (size_t)slice * CD * CD,
                        g_zbias, (void*)g_xsp[slice], nullptr,
                        CD, CD, blockIdx.x, mt, slice);
    } else {
        gemm_core<1, 0>(sb, g_x_hi, g_x_lo, g_BqT_hi, g_BqT_lo, bq,
                        (void*)g_q_hi, (void*)g_q_lo, CD, CD,
                        blockIdx.x, blockIdx.y - 64, 0);
    }
}

// ---------------------------------------------------------------------------
// Merged prep: blocks [0,4096) split x into bf16 hi/lo;
//              blocks [4096,6144) transpose+LoRA-fold+split the weights.
// WsrT slice-blocked: slice p occupies [p*CD*CD, (p+1)*CD*CD) with
// layout Dh[p*CD*CD + n*CD + k].
// ---------------------------------------------------------------------------
__global__ __launch_bounds__(256) void prep_all(
    const float* __restrict__ x,
    const float* __restrict__ Wq,   const float* __restrict__ Aq, const float* __restrict__ Bq,
    const float* __restrict__ Wkv,  const float* __restrict__ Av, const float* __restrict__ Bv,
    const float* __restrict__ Wsr,  const float* __restrict__ Wproj)
{
    if (blockIdx.x < 4096) {
        int e = blockIdx.x * 256 + threadIdx.x;      // < 1048576 float4
        float4 v = ((const float4*)x)[e];
        bf16 h0, l0, h1, l1, h2, l2, h3, l3;
        bsplit(v.x, h0, l0); bsplit(v.y, h1, l1);
        bsplit(v.z, h2, l2); bsplit(v.w, h3, l3);
        ((uint32_t*)g_x_hi)[e * 2]     = packbf(h0, h1);
        ((uint32_t*)g_x_hi)[e * 2 + 1] = packbf(h2, h3);
        ((uint32_t*)g_x_lo)[e * 2]     = packbf(l0, l1);
        ((uint32_t*)g_x_lo)[e * 2 + 1] = packbf(l2, l3);
        return;
    }

    __shared__ float tile[32][33];
    int t = blockIdx.x - 4096;
    const float *W, *A = nullptr, *LB = nullptr;
    bf16 *Dh, *Dl;
    int K, stride, k0, n0;

    if (t < 256) {
        W = Wq; A = Aq; LB = Bq; Dh = g_BqT_hi; Dl = g_BqT_lo;
        K = 512; stride = 512; k0 = (t >> 4) * 32; n0 = (t & 15) * 32;
    } else if (t < 768) {
        int i = t - 256;
        W = Wkv; A = Av; LB = Bv; Dh = g_BkvT_hi; Dl = g_BkvT_lo;
        K = 512; stride = 1024; k0 = (i >> 5) * 32; n0 = (i & 31) * 32;
    } else if (t < 1792) {
        // Wsr: global K index kk in [0,2048) = patch p*512 + k.
        int i = t - 768;
        W = Wsr;
        int kk0 = (i >> 4) * 32;
        int nn0 = (i & 15) * 32;
        int tx = threadIdx.x & 31, ty = threadIdx.x >> 5;
#pragma unroll
        for (int ii = 0; ii < 4; ii++) {
            int kk = kk0 + ty + ii * 8, n = nn0 + tx;
            tile[ty + ii * 8][tx] = W[(size_t)kk * 512 + n];
        }
        __syncthreads();
#pragma unroll
        for (int ii = 0; ii < 4; ii++) {
            int n = nn0 + ty + ii * 8, kk = kk0 + tx;
            int p = kk >> 9, k = kk & 511;
            float v = tile[tx][ty + ii * 8];
            bf16 h, l; bsplit(v, h, l);
            size_t d = (size_t)p * CD * CD + (size_t)n * CD + k;
            g_BsrT_hi[d] = h;
            g_BsrT_lo[d] = l;
        }
        return;
    } else {
        int i = t - 1792;
        W = Wproj; Dh = g_BpT_hi; Dl = g_BpT_lo;
        K = 512; stride = 512; k0 = (i >> 4) * 32; n0 = (i & 15) * 32;
    }

    int tx = threadIdx.x & 31, ty = threadIdx.x >> 5;
#pragma unroll
    for (int i = 0; i < 4; i++) {
        int k = k0 + ty + i * 8, n = n0 + tx;
        float v = W[(size_t)k * stride + n];
        if (A) {
            float l = 0.f;
#pragma unroll
            for (int r = 0; r < RLORA; r++)
                l = fmaf(A[k * RLORA + r], LB[r * CD + (n & (CD - 1))], l);
            v += l;
        }
        tile[ty + i * 8][tx] = v;
    }
    __syncthreads();
#pragma unroll
    for (int i = 0; i < 4; i++) {
        int n = n0 + ty + i * 8, k = k0 + tx;
        float v = tile[tx][ty + i * 8];
        bf16 h, l; bsplit(v, h, l);
        Dh[(size_t)n * K + k] = h;
        Dl[(size_t)n * K + k] = l;
    }
}

// ---------------------------------------------------------------------------
// LayerNorm: sum the 4 split-K partials (+bsr) then normalize -> split bf16.
// ---------------------------------------------------------------------------
__device__ __forceinline__ float warp_sum(float v) {
#pragma unroll
    for (int o = 16; o > 0; o >>= 1) v += __shfl_xor_sync(0xffffffffu, v, o);
    return v;
}

__global__ __launch_bounds__(256) void ln_split_kernel(const float* __restrict__ gamma,
                                                       const float* __restrict__ beta,
                                                       const float* __restrict__ bsr) {
    int row = blockIdx.x;
    size_t base = (size_t)row * CD;
    int tid = threadIdx.x;
    float a = ((g_xsp[0][base + tid]       + g_xsp[1][base + tid])
            +  (g_xsp[2][base + tid]       + g_xsp[3][base + tid])) + bsr[tid];
    float c = ((g_xsp[0][base + tid + 256] + g_xsp[1][base + tid + 256])
            +  (g_xsp[2][base + tid + 256] + g_xsp[3][base + tid + 256])) + bsr[tid + 256];

    float s  = warp_sum(a + c);
    float sq = warp_sum(a * a + c * c);
    __shared__ float sh[16];
    int w = tid >> 5, l = tid & 31;
    if (l == 0) { sh[w] = s; sh[8 + w] = sq; }
    __syncthreads();
    if (w == 0) {
        float ts = (l < 8) ? sh[l] : 0.f;
        float tq = (l < 8) ? sh[8 + l] : 0.f;
        ts = warp_sum(ts); tq = warp_sum(tq);
        if (l == 0) { sh[0] = ts; sh[1] = tq; }
    }
    __syncthreads();
    float mean = sh[0] * (1.f / CD);
    float var  = sh[1] * (1.f / CD) - mean * mean;
    float inv  = rsqrtf(var + LN_EPS);
    float y0 = (a - mean) * inv * gamma[tid] + beta[tid];
    float y1 = (c - mean) * inv * gamma[tid + 256] + beta[tid + 256];
    bf16 h, lo;
    bsplit(y0, h, lo); g_xs_hi[base + tid] = h;       g_xs_lo[base + tid] = lo;
    bsplit(y1, h, lo); g_xs_hi[base + tid + 256] = h; g_xs_lo[base + tid + 256] = lo;
}

// ---------------------------------------------------------------------------
// HMMA flash attention with bf16x3 in BOTH matmuls (validated, unchanged).
// grid (NQ/128, NHEAD, NB), 256 threads (8 warps x 16 q-rows).
// ---------------------------------------------------------------------------
#define ATTN_SMEM (32768 + 65536)   // 96 KB

__global__ __launch_bounds__(256, 1) void attn_hmma(
    const bf16* __restrict__ qh, const bf16* __restrict__ ql,
    const bf16* __restrict__ kvh, const bf16* __restrict__ kvl)
{
    extern __shared__ char smem[];
    uint32_t sb = smem_u32(smem);
    const uint32_t QH = sb, QL = sb + 16384, ST = sb + 32768;

    int tid = threadIdx.x, lane = tid & 31, wid = tid >> 5;
    int b = blockIdx.z, h = blockIdx.y;
    int q0 = blockIdx.x * 128;

    const bf16* qgh = qh + (size_t)(b * NQ + q0) * CD + h * DH;
    const bf16* qgl = ql + (size_t)(b * NQ + q0) * CD + h * DH;
    const bf16* kgh = kvh + (size_t)b * NKV * (2 * CD) + h * DH;
    const bf16* kgl = kvl + (size_t)b * NKV * (2 * CD) + h * DH;
    const bf16* vgh = kgh + CD;
    const bf16* vgl = kgl + CD;

#pragma unroll
    for (int it = 0; it < 4; it++) {
        int idx = it * 256 + tid;
        int r = idx >> 3, c16 = idx & 7;
        uint32_t so = SW128(r * 128 + c16 * 16);
        size_t go = (size_t)r * CD + c16 * 8;
        cp16(QH + so, qgh + go);
        cp16(QL + so, qgl + go);
    }
    cp_commit();

    auto issue_kv = [&](int t, int bufi) {
        int m0 = t * 64;
        uint32_t SBB = ST + bufi * 32768;
#pragma unroll
        for (int it = 0; it < 2; it++) {
            int idx = it * 256 + tid;
            int r = idx >> 3, c16 = idx & 7;
            size_t go = (size_t)(m0 + r) * (2 * CD) + c16 * 8;
            uint32_t so = SW128(r * 128 + c16 * 16);
            cp16(SBB + so,         kgh + go);
            cp16(SBB + 8192 + so,  kgl + go);
            cp16(SBB + 16384 + so, vgh + go);
            cp16(SBB + 24576 + so, vgl + go);
        }
        cp_commit();
    };

    issue_kv(0, 0);
    cp_wait<1>();
    __syncthreads();

    uint32_t aqh[4][4], aql[4][4];
#pragma unroll
    for (int ks = 0; ks < 4; ks++) {
        int row = wid * 16 + (lane & 15);
        int colb = ks * 32 + ((lane >> 4) << 4);
        uint32_t off = SW128(row * 128 + colb);
        ldm_x4(QH + off, aqh[ks]);
        ldm_x4(QL + off, aql[ks]);
    }

    float o[8][4];
#pragma unroll
    for (int nt = 0; nt < 8; nt++)
#pragma unroll
        for (int e = 0; e < 4; e++) o[nt][e] = 0.f;
    float rs0 = 0.f, rs1 = 0.f;

    const float SC = 0.125f;

    for (int t = 0; t < 16; t++) {
        int bufi = t & 1;
        if (t + 1 < 16) { issue_kv(t + 1, bufi ^ 1); cp_wait<1>(); }
        else            { cp_wait<0>(); }
        __syncthreads();

        uint32_t SBB = ST + bufi * 32768;

        float s[8][4];
#pragma unroll
        for (int nt = 0; nt < 8; nt++)
#pragma unroll
            for (int e = 0; e < 4; e++) s[nt][e] = 0.f;

#pragma unroll
        for (int ks = 0; ks < 4; ks++) {
            uint32_t bh[8][2], bl[8][2];
#pragma unroll
            for (int bt = 0; bt < 4; bt++) {
                int row = bt * 16 + ((lane >> 4) << 3) + (lane & 7);
                int colb = ks * 32 + (((lane >> 3) & 1) << 4);
                uint32_t off = SW128(row * 128 + colb);
                uint32_t tr[4];
                ldm_x4(SBB + off, tr);
                bh[bt * 2][0] = tr[0];     bh[bt * 2][1] = tr[1];
                bh[bt * 2 + 1][0] = tr[2]; bh[bt * 2 + 1][1] = tr[3];
                ldm_x4(SBB + 8192 + off, tr);
                bl[bt * 2][0] = tr[0];     bl[bt * 2][1] = tr[1];
                bl[bt * 2 + 1][0] = tr[2]; bl[bt * 2 + 1][1] = tr[3];
            }
#pragma unroll
            for (int nt = 0; nt < 8; nt++)
                mma16816(s[nt], aqh[ks], bh[nt]);
#pragma unroll
            for (int nt = 0; nt < 8; nt++)
                mma16816(s[nt], aqh[ks], bl[nt]);
#pragma unroll
            for (int nt = 0; nt < 8; nt++)
                mma16816(s[nt], aql[ks], bh[nt]);
        }

        uint32_t pah[4][4], pal[4][4];
#pragma unroll
        for (int nt = 0; nt < 8; nt++) {
            float p0 = __expf(s[nt][0] * SC);
            float p1 = __expf(s[nt][1] * SC);
            float p2 = __expf(s[nt][2] * SC);
            float p3 = __expf(s[nt][3] * SC);
            rs0 += p0 + p1;
            rs1 += p2 + p3;
            bf16 h0, l0, h1, l1, h2, l2, h3, l3;
            bsplit(p0, h0, l0); bsplit(p1, h1, l1);
            bsplit(p2, h2, l2); bsplit(p3, h3, l3);
            int j = nt >> 1, half = nt & 1;
            pah[j][half * 2]     = packbf(h0, h1);
            pah[j][half * 2 + 1] = packbf(h2, h3);
            pal[j][half * 2]     = packbf(l0, l1);
            pal[j][half * 2 + 1] = packbf(l2, l3);
        }

#pragma unroll
        for (int j = 0; j < 4; j++) {
            uint32_t vbh[8][2], vbl[8][2];
#pragma unroll
            for (int nh = 0; nh < 4; nh++) {
                int row = j * 16 + (lane & 15);
                int colb = nh * 32 + ((lane >> 4) << 4);
                uint32_t off = SW128(row * 128 + colb);
                uint32_t tr[4];
                ldm_x4_t(SBB + 16384 + off, tr);
                vbh[nh * 2][0] = tr[0];     vbh[nh * 2][1] = tr[1];
                vbh[nh * 2 + 1][0] = tr[2]; vbh[nh * 2 + 1][1] = tr[3];
                ldm_x4_t(SBB + 24576 + off, tr);
                vbl[nh * 2][0] = tr[0];     vbl[nh * 2][1] = tr[1];
                vbl[nh * 2 + 1][0] = tr[2]; vbl[nh * 2 + 1][1] = tr[3];
            }
#pragma unroll
            for (int nt = 0; nt < 8; nt++)
                mma16816(o[nt], pah[j], vbh[nt]);
#pragma unroll
            for (int nt = 0; nt < 8; nt++)
                mma16816(o[nt], pah[j], vbl[nt]);
#pragma unroll
            for (int nt = 0; nt < 8; nt++)
                mma16816(o[nt], pal[j], vbh[nt]);
        }
        __syncthreads();
    }

    rs0 += __shfl_xor_sync(0xffffffffu, rs0, 1);
    rs0 += __shfl_xor_sync(0xffffffffu, rs0, 2);
    rs1 += __shfl_xor_sync(0xffffffffu, rs1, 1);
    rs1 += __shfl_xor_sync(0xffffffffu, rs1, 2);

    int g = lane >> 2, tc = (lane & 3) * 2;
    int row0 = q0 + wid * 16 + g;
    float i0 = 1.f / rs0, i1 = 1.f / rs1;
#pragma unroll
    for (int nt = 0; nt < 8; nt++) {
        int col = h * DH + nt * 8 + tc;
        size_t off0 = (size_t)(b * NQ + row0) * CD + col;
        size_t off1 = off0 + (size_t)8 * CD;
        float v0 = o[nt][0] * i0, v1 = o[nt][1] * i0;
        float v2 = o[nt][2] * i1, v3 = o[nt][3] * i1;
        bf16 h0, l0, h1, l1;
        bsplit(v0, h0, l0); bsplit(v1, h1, l1);
        *(__nv_bfloat162*)(g_o_hi + off0) = __halves2bfloat162(h0, h1);
        *(__nv_bfloat162*)(g_o_lo + off0) = __halves2bfloat162(l0, l1);
        bsplit(v2, h0, l0); bsplit(v3, h1, l1);
        *(__nv_bfloat162*)(g_o_hi + off1) = __halves2bfloat162(h0, h1);
        *(__nv_bfloat162*)(g_o_lo + off1) = __halves2bfloat162(l0, l1);
    }
}

// ---------------------------------------------------------------------------
// kernel_launch
// ---------------------------------------------------------------------------
extern "C" void kernel_launch(void* const* d_in, const int* in_sizes, int n_in,
                              void* d_out, int out_size) {
    const float* x     = (const float*)d_in[0];
    const float* Wq    = (const float*)d_in[1];
    const float* bq    = (const float*)d_in[2];
    const float* Wkv   = (const float*)d_in[3];
    const float* bkv   = (const float*)d_in[4];
    const float* Wproj = (const float*)d_in[5];
    const float* bproj = (const float*)d_in[6];
    const float* Aq    = (const float*)d_in[7];
    const float* Bq    = (const float*)d_in[8];
    const float* Av    = (const float*)d_in[9];
    const float* Bv    = (const float*)d_in[10];
    const float* Wsr   = (const float*)d_in[11];
    const float* bsr   = (const float*)d_in[12];
    const float* gamma = (const float*)d_in[13];
    const float* beta  = (const float*)d_in[14];
    float* outp = (float*)d_out;

    bf16 *xsh, *xsl, *oh, *ol, *pqh, *pql, *pkvh, *pkvl, *bkvh, *bkvl, *bph, *bpl;
    cudaGetSymbolAddress((void**)&bkvh, g_BkvT_hi);cudaGetSymbolAddress((void**)&bkvl, g_BkvT_lo);
    cudaGetSymbolAddress((void**)&bph,  g_BpT_hi); cudaGetSymbolAddress((void**)&bpl,  g_BpT_lo);
    cudaGetSymbolAddress((void**)&xsh,  g_xs_hi);  cudaGetSymbolAddress((void**)&xsl,  g_xs_lo);
    cudaGetSymbolAddress((void**)&oh,   g_o_hi);   cudaGetSymbolAddress((void**)&ol,   g_o_lo);
    cudaGetSymbolAddress((void**)&pqh,  g_q_hi);   cudaGetSymbolAddress((void**)&pql,  g_q_lo);
    cudaGetSymbolAddress((void**)&pkvh, g_kv_hi);  cudaGetSymbolAddress((void**)&pkvl, g_kv_lo);

    cudaFuncSetAttribute(gemm_bf16x3<0>, cudaFuncAttributeMaxDynamicSharedMemorySize, GEMM_SMEM);
    cudaFuncSetAttribute(gemm_bf16x3<1>, cudaFuncAttributeMaxDynamicSharedMemorySize, GEMM_SMEM);
    cudaFuncSetAttribute(gemm_q_xs, cudaFuncAttributeMaxDynamicSharedMemorySize, GEMM_SMEM);
    cudaFuncSetAttribute(attn_hmma, cudaFuncAttributeMaxDynamicSharedMemorySize, ATTN_SMEM);

    // 1) merged prep: split x + weight transpose/LoRA/split (Wsr slice-blocked)
    prep_all<<<6144, 256>>>(x, Wq, Aq, Bq, Wkv, Av, Bv, Wsr, Wproj);

    // 2) merged: xs split-K partial GEMMs (4 slices, K=512) + q GEMM (K=512)
    gemm_q_xs<<<dim3(8, 128), 256, GEMM_SMEM>>>(bq);

    // 3) LayerNorm (sums split-K partials + bsr) -> split bf16
    ln_split_kernel<<<NB * NKV, 256>>>(gamma, beta, bsr);

    // 4) kv GEMM (2048 x 1024, K=512), split bf16 out
    gemm_bf16x3<1><<<dim3(16, 16), 256, GEMM_SMEM>>>(
        xsh, xsl, bkvh, bkvl, bkv, pkvh, pkvl, CD, 2 * CD);

    // 5) attention (HMMA bf16x3) -> split bf16
    attn_hmma<<<dim3(NQ / 128, NHEAD, NB), 256, ATTN_SMEM>>>(pqh, pql, pkvh, pkvl);

    // 6) out GEMM -> d_out (fp32)
    gemm_bf16x3<0><<<dim3(8, 64), 256, GEMM_SMEM>>>(
        oh, ol, bph, bpl, bproj, outp, nullptr, CD, CD);
}

// round 13
// speedup vs baseline: 1.3077x; 1.0144x over previous
#include <cuda_runtime.h>
#include <cuda_bf16.h>
#include <cstdint>
#include <math.h>

#define NB    2
#define NQ    4096
#define NKV   1024
#define CD    512
#define NHEAD 8
#define DH    64
#define RLORA 8
#define LN_EPS 1e-5f

typedef __nv_bfloat16 bf16;

// ---------------------------------------------------------------------------
// Device scratch
// ---------------------------------------------------------------------------
__device__ bf16  g_x_hi [NB*NQ*CD],      g_x_lo [NB*NQ*CD];
__device__ bf16  g_BqT_hi[CD*CD],        g_BqT_lo[CD*CD];
__device__ bf16  g_BkvT_hi[2*CD*CD],     g_BkvT_lo[2*CD*CD];
__device__ bf16  g_BsrT_hi[CD*4*CD],     g_BsrT_lo[CD*4*CD];   // slice-blocked: [p][n][k]
__device__ bf16  g_BpT_hi[CD*CD],        g_BpT_lo[CD*CD];
__device__ bf16  g_q_hi [NB*NQ*CD],      g_q_lo [NB*NQ*CD];
__device__ float g_xsp[4][NB*NKV*CD];    // split-K partials (one per patch)
__device__ bf16  g_kv_hi[NB*NKV*2*CD],   g_kv_lo[NB*NKV*2*CD];
__device__ bf16  g_xs_hi[NB*NKV*CD],     g_xs_lo[NB*NKV*CD];
__device__ bf16  g_o_hi[NB*NQ*CD],       g_o_lo[NB*NQ*CD];
__device__ float g_zbias[2*CD];          // zero bias (static-zeroed)

// ---------------------------------------------------------------------------
// helpers
// ---------------------------------------------------------------------------
__device__ __forceinline__ uint32_t smem_u32(const void* p) {
    uint32_t a;
    asm("{ .reg .u64 t; cvta.to.shared.u64 t, %1; cvt.u32.u64 %0, t; }" : "=r"(a) : "l"(p));
    return a;
}
#define SW128(o) ((o) ^ (((o) >> 3) & 0x70))

__device__ __forceinline__ void cp16(uint32_t dst, const void* src) {
    asm volatile("cp.async.cg.shared.global [%0], [%1], 16;" :: "r"(dst), "l"(src));
}
__device__ __forceinline__ void cp_commit() { asm volatile("cp.async.commit_group;"); }
template<int N> __device__ __forceinline__ void cp_wait() {
    asm volatile("cp.async.wait_group %0;" :: "n"(N));
}

__device__ __forceinline__ void ldm_x4(uint32_t addr, uint32_t* r) {
    asm volatile("ldmatrix.sync.aligned.m8n8.x4.shared.b16 {%0,%1,%2,%3}, [%4];"
        : "=r"(r[0]), "=r"(r[1]), "=r"(r[2]), "=r"(r[3]) : "r"(addr));
}
__device__ __forceinline__ void ldm_x4_t(uint32_t addr, uint32_t* r) {
    asm volatile("ldmatrix.sync.aligned.m8n8.x4.trans.shared.b16 {%0,%1,%2,%3}, [%4];"
        : "=r"(r[0]), "=r"(r[1]), "=r"(r[2]), "=r"(r[3]) : "r"(addr));
}
__device__ __forceinline__ void mma16816(float* c, const uint32_t* a, const uint32_t* b) {
    asm volatile("mma.sync.aligned.m16n8k16.row.col.f32.bf16.bf16.f32 "
        "{%0,%1,%2,%3}, {%4,%5,%6,%7}, {%8,%9}, {%0,%1,%2,%3};"
        : "+f"(c[0]), "+f"(c[1]), "+f"(c[2]), "+f"(c[3])
        : "r"(a[0]), "r"(a[1]), "r"(a[2]), "r"(a[3]), "r"(b[0]), "r"(b[1]));
}

__device__ __forceinline__ void bsplit(float a, bf16& hi, bf16& lo) {
    hi = __float2bfloat16_rn(a);
    lo = __float2bfloat16_rn(a - __bfloat162float(hi));
}
__device__ __forceinline__ uint32_t packbf(bf16 a, bf16 b) {
    __nv_bfloat162 h = __halves2bfloat162(a, b);
    return *reinterpret_cast<uint32_t*>(&h);
}

// ---------------------------------------------------------------------------
// GEMM core (HMMA bf16x3): C[M,N] = A @ B^T + bias
//   CTA tile 128x64, BK=64, 256 threads, 8 warps (4x2), warp tile 32x32,
//   2-stage cp.async, 96 KB smem -> 2 CTAs/SM.
//   OB=0: fp32 out; OB=1: split bf16 out.
//   PERM=1: A addresses patch `pslice` of the conv permutation of g_x.
// ---------------------------------------------------------------------------
#define A_TILE_B 16384              // 128 rows x 128B
#define B_TILE_B 8192               // 64 rows x 128B
#define STAGE_B  (2 * A_TILE_B + 2 * B_TILE_B)   // 48 KB
#define GEMM_SMEM (2 * STAGE_B)                  // 96 KB

template<int OB, int PERM>
__device__ __forceinline__ void gemm_core(
    uint32_t sb,
    const bf16* __restrict__ Ah, const bf16* __restrict__ Al,
    const bf16* __restrict__ Bh, const bf16* __restrict__ Bl,
    const float* __restrict__ bias, void* __restrict__ Cv, void* __restrict__ Cv2,
    int K, int ldc, int bx, int by, int pslice)
{
    int tid = threadIdx.x, wid = tid >> 5, lane = tid & 31;

    const bf16* aAh = PERM ? Ah : Ah + (size_t)by * 128 * K;
    const bf16* aAl = PERM ? Al : Al + (size_t)by * 128 * K;
    const bf16* aBh = Bh + (size_t)bx * 64 * K;
    const bf16* aBl = Bl + (size_t)bx * 64 * K;

    auto issue = [&](int chunk, int buf) {
        int k0 = chunk << 6;
        uint32_t stg = sb + buf * STAGE_B;
#pragma unroll
        for (int t = 0; t < 2; t++) {
            const bf16* src = t ? aAl : aAh;
#pragma unroll
            for (int it = 0; it < 4; it++) {
                int idx = it * 256 + tid;
                int r = idx >> 3, c16 = idx & 7;
                size_t goff;
                if (PERM) {
                    int m = by * 128 + r;
                    int bb = m >> 10, pp = m & 1023;
                    int tok = bb * NQ + ((pp >> 5) * 2 + (pslice >> 1)) * 64
                            + ((pp & 31) * 2 + (pslice & 1));
                    goff = (size_t)tok * CD + k0 + c16 * 8;
                } else {
                    goff = (size_t)r * K + k0 + c16 * 8;
                }
                cp16(stg + t * A_TILE_B + SW128(r * 128 + c16 * 16), src + goff);
            }
        }
#pragma unroll
        for (int t = 0; t < 2; t++) {
            const bf16* src = (t ? aBl : aBh) + k0;
            uint32_t base = stg + 2 * A_TILE_B + t * B_TILE_B;
#pragma unroll
            for (int it = 0; it < 2; it++) {
                int idx = it * 256 + tid;
                int r = idx >> 3, c16 = idx & 7;
                cp16(base + SW128(r * 128 + c16 * 16),
                     src + (size_t)r * K + c16 * 8);
            }
        }
        cp_commit();
    };

    float acc[2][4][4];
#pragma unroll
    for (int i = 0; i < 2; i++)
#pragma unroll
        for (int j = 0; j < 4; j++)
#pragma unroll
            for (int e = 0; e < 4; e++) acc[i][j][e] = 0.f;

    int wm = wid >> 1, wn = wid & 1;     // 4 x 2 warp grid, 32x32 per warp
    int nch = K >> 6;

    issue(0, 0);
    for (int i = 0; i < nch; i++) {
        int buf = i & 1;
        if (i + 1 < nch) { issue(i + 1, buf ^ 1); cp_wait<1>(); }
        else             { cp_wait<0>(); }
        __syncthreads();

        uint32_t stg = sb + buf * STAGE_B;
        uint32_t aH = stg;
        uint32_t aL = stg + A_TILE_B;
        uint32_t bH = stg + 2 * A_TILE_B;
        uint32_t bL = bH + B_TILE_B;

#pragma unroll
        for (int ks = 0; ks < 4; ks++) {
            int kb = ks * 32;
            uint32_t ah[2][4], al[2][4], bh[4][2], bl[4][2];
#pragma unroll
            for (int at = 0; at < 2; at++) {
                int row = wm * 32 + at * 16 + (lane & 15);
                int colb = kb + ((lane >> 4) << 4);
                uint32_t off = SW128(row * 128 + colb);
                ldm_x4(aH + off, ah[at]);
                ldm_x4(aL + off, al[at]);
            }
#pragma unroll
            for (int bt = 0; bt < 2; bt++) {
                int row = wn * 32 + bt * 16 + ((lane >> 4) << 3) + (lane & 7);
                int colb = kb + (((lane >> 3) & 1) << 4);
                uint32_t off = SW128(row * 128 + colb);
                uint32_t t[4];
                ldm_x4(bH + off, t);
                bh[bt * 2][0] = t[0]; bh[bt * 2][1] = t[1];
                bh[bt * 2 + 1][0] = t[2]; bh[bt * 2 + 1][1] = t[3];
                ldm_x4(bL + off, t);
                bl[bt * 2][0] = t[0]; bl[bt * 2][1] = t[1];
                bl[bt * 2 + 1][0] = t[2]; bl[bt * 2 + 1][1] = t[3];
            }
#pragma unroll
            for (int at = 0; at < 2; at++)
#pragma unroll
                for (int nt = 0; nt < 4; nt++)
                    mma16816(acc[at][nt], ah[at], bh[nt]);
#pragma unroll
            for (int at = 0; at < 2; at++)
#pragma unroll
                for (int nt = 0; nt < 4; nt++)
                    mma16816(acc[at][nt], ah[at], bl[nt]);
#pragma unroll
            for (int at = 0; at < 2; at++)
#pragma unroll
                for (int nt = 0; nt < 4; nt++)
                    mma16816(acc[at][nt], al[at], bh[nt]);
        }
        __syncthreads();
    }

    int g = lane >> 2, tc = (lane & 3) * 2;
#pragma unroll
    for (int nt = 0; nt < 4; nt++) {
        int col = bx * 64 + wn * 32 + nt * 8 + tc;
        float b0 = bias[col], b1 = bias[col + 1];
#pragma unroll
        for (int at = 0; at < 2; at++) {
            int row0 = by * 128 + wm * 32 + at * 16 + g;
            float v00 = acc[at][nt][0] + b0, v01 = acc[at][nt][1] + b1;
            float v10 = acc[at][nt][2] + b0, v11 = acc[at][nt][3] + b1;
            if (OB) {
                bf16* C  = (bf16*)Cv;
                bf16* C2 = (bf16*)Cv2;
                bf16 h0, l0, h1, l1;
                bsplit(v00, h0, l0); bsplit(v01, h1, l1);
                *(uint32_t*)(C  + (size_t)row0 * ldc + col) = packbf(h0, h1);
                *(uint32_t*)(C2 + (size_t)row0 * ldc + col) = packbf(l0, l1);
                bsplit(v10, h0, l0); bsplit(v11, h1, l1);
                *(uint32_t*)(C  + (size_t)(row0 + 8) * ldc + col) = packbf(h0, h1);
                *(uint32_t*)(C2 + (size_t)(row0 + 8) * ldc + col) = packbf(l0, l1);
            } else {
                float* C = (float*)Cv;
                *(float2*)(C + (size_t)row0 * ldc + col)       = make_float2(v00, v01);
                *(float2*)(C + (size_t)(row0 + 8) * ldc + col) = make_float2(v10, v11);
            }
        }
    }
}

template<int OB>
__global__ __launch_bounds__(256, 2) void gemm_bf16x3(
    const bf16* __restrict__ Ah, const bf16* __restrict__ Al,
    const bf16* __restrict__ Bh, const bf16* __restrict__ Bl,
    const float* __restrict__ bias, void* __restrict__ Cv, void* __restrict__ Cv2,
    int K, int ldc)
{
    extern __shared__ char smem[];
    gemm_core<OB, 0>(smem_u32(smem), Ah, Al, Bh, Bl, bias, Cv, Cv2, K, ldc,
                     blockIdx.x, blockIdx.y, 0);
}

// Merged independent GEMMs: grid (8, 128).
__global__ __launch_bounds__(256, 2) void gemm_q_xs(
    const float* __restrict__ bq)
{
    extern __shared__ char smem[];
    uint32_t sb = smem_u32(smem);
    if (blockIdx.y < 64) {
        int slice = blockIdx.y >> 4, mt = blockIdx.y & 15;
        gemm_core<0, 1>(sb, g_x_hi, g_x_lo,
                        g_BsrT_hi + (size_t)slice * CD * CD,
                        g_BsrT_lo + (size_t)slice * CD * CD,
                        g_zbias, (void*)g_xsp[slice], nullptr,
                        CD, CD, blockIdx.x, mt, slice);
    } else {
        gemm_core<1, 0>(sb, g_x_hi, g_x_lo, g_BqT_hi, g_BqT_lo, bq,
                        (void*)g_q_hi, (void*)g_q_lo, CD, CD,
                        blockIdx.x, blockIdx.y - 64, 0);
    }
}

// ---------------------------------------------------------------------------
// Merged prep (unchanged from R12)
// ---------------------------------------------------------------------------
__global__ __launch_bounds__(256) void prep_all(
    const float* __restrict__ x,
    const float* __restrict__ Wq,   const float* __restrict__ Aq, const float* __restrict__ Bq,
    const float* __restrict__ Wkv,  const float* __restrict__ Av, const float* __restrict__ Bv,
    const float* __restrict__ Wsr,  const float* __restrict__ Wproj)
{
    if (blockIdx.x < 4096) {
        int e = blockIdx.x * 256 + threadIdx.x;
        float4 v = ((const float4*)x)[e];
        bf16 h0, l0, h1, l1, h2, l2, h3, l3;
        bsplit(v.x, h0, l0); bsplit(v.y, h1, l1);
        bsplit(v.z, h2, l2); bsplit(v.w, h3, l3);
        ((uint32_t*)g_x_hi)[e * 2]     = packbf(h0, h1);
        ((uint32_t*)g_x_hi)[e * 2 + 1] = packbf(h2, h3);
        ((uint32_t*)g_x_lo)[e * 2]     = packbf(l0, l1);
        ((uint32_t*)g_x_lo)[e * 2 + 1] = packbf(l2, l3);
        return;
    }

    __shared__ float tile[32][33];
    int t = blockIdx.x - 4096;
    const float *W, *A = nullptr, *LB = nullptr;
    bf16 *Dh, *Dl;
    int K, stride, k0, n0;

    if (t < 256) {
        W = Wq; A = Aq; LB = Bq; Dh = g_BqT_hi; Dl = g_BqT_lo;
        K = 512; stride = 512; k0 = (t >> 4) * 32; n0 = (t & 15) * 32;
    } else if (t < 768) {
        int i = t - 256;
        W = Wkv; A = Av; LB = Bv; Dh = g_BkvT_hi; Dl = g_BkvT_lo;
        K = 512; stride = 1024; k0 = (i >> 5) * 32; n0 = (i & 31) * 32;
    } else if (t < 1792) {
        int i = t - 768;
        W = Wsr;
        int kk0 = (i >> 4) * 32;
        int nn0 = (i & 15) * 32;
        int tx = threadIdx.x & 31, ty = threadIdx.x >> 5;
#pragma unroll
        for (int ii = 0; ii < 4; ii++) {
            int kk = kk0 + ty + ii * 8, n = nn0 + tx;
            tile[ty + ii * 8][tx] = W[(size_t)kk * 512 + n];
        }
        __syncthreads();
#pragma unroll
        for (int ii = 0; ii < 4; ii++) {
            int n = nn0 + ty + ii * 8, kk = kk0 + tx;
            int p = kk >> 9, k = kk & 511;
            float v = tile[tx][ty + ii * 8];
            bf16 h, l; bsplit(v, h, l);
            size_t d = (size_t)p * CD * CD + (size_t)n * CD + k;
            g_BsrT_hi[d] = h;
            g_BsrT_lo[d] = l;
        }
        return;
    } else {
        int i = t - 1792;
        W = Wproj; Dh = g_BpT_hi; Dl = g_BpT_lo;
        K = 512; stride = 512; k0 = (i >> 4) * 32; n0 = (i & 15) * 32;
    }

    int tx = threadIdx.x & 31, ty = threadIdx.x >> 5;
#pragma unroll
    for (int i = 0; i < 4; i++) {
        int k = k0 + ty + i * 8, n = n0 + tx;
        float v = W[(size_t)k * stride + n];
        if (A) {
            float l = 0.f;
#pragma unroll
            for (int r = 0; r < RLORA; r++)
                l = fmaf(A[k * RLORA + r], LB[r * CD + (n & (CD - 1))], l);
            v += l;
        }
        tile[ty + i * 8][tx] = v;
    }
    __syncthreads();
#pragma unroll
    for (int i = 0; i < 4; i++) {
        int n = n0 + ty + i * 8, k = k0 + tx;
        float v = tile[tx][ty + i * 8];
        bf16 h, l; bsplit(v, h, l);
        Dh[(size_t)n * K + k] = h;
        Dl[(size_t)n * K + k] = l;
    }
}

// ---------------------------------------------------------------------------
// LayerNorm (unchanged from R12)
// ---------------------------------------------------------------------------
__device__ __forceinline__ float warp_sum(float v) {
#pragma unroll
    for (int o = 16; o > 0; o >>= 1) v += __shfl_xor_sync(0xffffffffu, v, o);
    return v;
}

__global__ __launch_bounds__(256) void ln_split_kernel(const float* __restrict__ gamma,
                                                       const float* __restrict__ beta,
                                                       const float* __restrict__ bsr) {
    int row = blockIdx.x;
    size_t base = (size_t)row * CD;
    int tid = threadIdx.x;
    float a = ((g_xsp[0][base + tid]       + g_xsp[1][base + tid])
            +  (g_xsp[2][base + tid]       + g_xsp[3][base + tid])) + bsr[tid];
    float c = ((g_xsp[0][base + tid + 256] + g_xsp[1][base + tid + 256])
            +  (g_xsp[2][base + tid + 256] + g_xsp[3][base + tid + 256])) + bsr[tid + 256];

    float s  = warp_sum(a + c);
    float sq = warp_sum(a * a + c * c);
    __shared__ float sh[16];
    int w = tid >> 5, l = tid & 31;
    if (l == 0) { sh[w] = s; sh[8 + w] = sq; }
    __syncthreads();
    if (w == 0) {
        float ts = (l < 8) ? sh[l] : 0.f;
        float tq = (l < 8) ? sh[8 + l] : 0.f;
        ts = warp_sum(ts); tq = warp_sum(tq);
        if (l == 0) { sh[0] = ts; sh[1] = tq; }
    }
    __syncthreads();
    float mean = sh[0] * (1.f / CD);
    float var  = sh[1] * (1.f / CD) - mean * mean;
    float inv  = rsqrtf(var + LN_EPS);
    float y0 = (a - mean) * inv * gamma[tid] + beta[tid];
    float y1 = (c - mean) * inv * gamma[tid + 256] + beta[tid + 256];
    bf16 h, lo;
    bsplit(y0, h, lo); g_xs_hi[base + tid] = h;       g_xs_lo[base + tid] = lo;
    bsplit(y1, h, lo); g_xs_hi[base + tid + 256] = h; g_xs_lo[base + tid + 256] = lo;
}

// ---------------------------------------------------------------------------
// HMMA flash attention, bf16x3 both matmuls.
// NOW 2 CTAs/SM: Q fragments are re-loaded from smem per ks (frees 32 regs,
// peak live regs ~100) -> __launch_bounds__(256, 2). Math bit-identical.
// grid (NQ/128, NHEAD, NB), 256 threads (8 warps x 16 q-rows).
// ---------------------------------------------------------------------------
#define ATTN_SMEM (32768 + 65536)   // 96 KB -> 2 CTAs/SM (192 <= 227 KB)

__global__ __launch_bounds__(256, 2) void attn_hmma(
    const bf16* __restrict__ qh, const bf16* __restrict__ ql,
    const bf16* __restrict__ kvh, const bf16* __restrict__ kvl)
{
    extern __shared__ char smem[];
    uint32_t sb = smem_u32(smem);
    const uint32_t QH = sb, QL = sb + 16384, ST = sb + 32768;

    int tid = threadIdx.x, lane = tid & 31, wid = tid >> 5;
    int b = blockIdx.z, h = blockIdx.y;
    int q0 = blockIdx.x * 128;

    const bf16* qgh = qh + (size_t)(b * NQ + q0) * CD + h * DH;
    const bf16* qgl = ql + (size_t)(b * NQ + q0) * CD + h * DH;
    const bf16* kgh = kvh + (size_t)b * NKV * (2 * CD) + h * DH;
    const bf16* kgl = kvl + (size_t)b * NKV * (2 * CD) + h * DH;
    const bf16* vgh = kgh + CD;
    const bf16* vgl = kgl + CD;

#pragma unroll
    for (int it = 0; it < 4; it++) {
        int idx = it * 256 + tid;
        int r = idx >> 3, c16 = idx & 7;
        uint32_t so = SW128(r * 128 + c16 * 16);
        size_t go = (size_t)r * CD + c16 * 8;
        cp16(QH + so, qgh + go);
        cp16(QL + so, qgl + go);
    }
    cp_commit();

    auto issue_kv = [&](int t, int bufi) {
        int m0 = t * 64;
        uint32_t SBB = ST + bufi * 32768;
#pragma unroll
        for (int it = 0; it < 2; it++) {
            int idx = it * 256 + tid;
            int r = idx >> 3, c16 = idx & 7;
            size_t go = (size_t)(m0 + r) * (2 * CD) + c16 * 8;
            uint32_t so = SW128(r * 128 + c16 * 16);
            cp16(SBB + so,         kgh + go);
            cp16(SBB + 8192 + so,  kgl + go);
            cp16(SBB + 16384 + so, vgh + go);
            cp16(SBB + 24576 + so, vgl + go);
        }
        cp_commit();
    };

    issue_kv(0, 0);
    cp_wait<1>();
    __syncthreads();

    float o[8][4];
#pragma unroll
    for (int nt = 0; nt < 8; nt++)
#pragma unroll
        for (int e = 0; e < 4; e++) o[nt][e] = 0.f;
    float rs0 = 0.f, rs1 = 0.f;

    const float SC = 0.125f;

    // Q fragment address pieces (row/col fixed per thread)
    int qrow = wid * 16 + (lane & 15);
    int qcolb = (lane >> 4) << 4;

    for (int t = 0; t < 16; t++) {
        int bufi = t & 1;
        if (t + 1 < 16) { issue_kv(t + 1, bufi ^ 1); cp_wait<1>(); }
        else            { cp_wait<0>(); }
        __syncthreads();

        uint32_t SBB = ST + bufi * 32768;

        float s[8][4];
#pragma unroll
        for (int nt = 0; nt < 8; nt++)
#pragma unroll
            for (int e = 0; e < 4; e++) s[nt][e] = 0.f;

#pragma unroll
        for (int ks = 0; ks < 4; ks++) {
            // reload Q fragments from smem (frees 32 persistent regs)
            uint32_t aqh[4], aql[4];
            {
                uint32_t off = SW128(qrow * 128 + ks * 32 + qcolb);
                ldm_x4(QH + off, aqh);
                ldm_x4(QL + off, aql);
            }
            uint32_t bh[8][2], bl[8][2];
#pragma unroll
            for (int bt = 0; bt < 4; bt++) {
                int row = bt * 16 + ((lane >> 4) << 3) + (lane & 7);
                int colb = ks * 32 + (((lane >> 3) & 1) << 4);
                uint32_t off = SW128(row * 128 + colb);
                uint32_t tr[4];
                ldm_x4(SBB + off, tr);
                bh[bt * 2][0] = tr[0];     bh[bt * 2][1] = tr[1];
                bh[bt * 2 + 1][0] = tr[2]; bh[bt * 2 + 1][1] = tr[3];
                ldm_x4(SBB + 8192 + off, tr);
                bl[bt * 2][0] = tr[0];     bl[bt * 2][1] = tr[1];
                bl[bt * 2 + 1][0] = tr[2]; bl[bt * 2 + 1][1] = tr[3];
            }
#pragma unroll
            for (int nt = 0; nt < 8; nt++)
                mma16816(s[nt], aqh, bh[nt]);
#pragma unroll
            for (int nt = 0; nt < 8; nt++)
                mma16816(s[nt], aqh, bl[nt]);
#pragma unroll
            for (int nt = 0; nt < 8; nt++)
                mma16816(s[nt], aql, bh[nt]);
        }

        uint32_t pah[4][4], pal[4][4];
#pragma unroll
        for (int nt = 0; nt < 8; nt++) {
            float p0 = __expf(s[nt][0] * SC);
            float p1 = __expf(s[nt][1] * SC);
            float p2 = __expf(s[nt][2] * SC);
            float p3 = __expf(s[nt][3] * SC);
            rs0 += p0 + p1;
            rs1 += p2 + p3;
            bf16 h0, l0, h1, l1, h2, l2, h3, l3;
            bsplit(p0, h0, l0); bsplit(p1, h1, l1);
            bsplit(p2, h2, l2); bsplit(p3, h3, l3);
            int j = nt >> 1, half = nt & 1;
            pah[j][half * 2]     = packbf(h0, h1);
            pah[j][half * 2 + 1] = packbf(h2, h3);
            pal[j][half * 2]     = packbf(l0, l1);
            pal[j][half * 2 + 1] = packbf(l2, l3);
        }

#pragma unroll
        for (int j = 0; j < 4; j++) {
            uint32_t vbh[8][2], vbl[8][2];
#pragma unroll
            for (int nh = 0; nh < 4; nh++) {
                int row = j * 16 + (lane & 15);
                int colb = nh * 32 + ((lane >> 4) << 4);
                uint32_t off = SW128(row * 128 + colb);
                uint32_t tr[4];
                ldm_x4_t(SBB + 16384 + off, tr);
                vbh[nh * 2][0] = tr[0];     vbh[nh * 2][1] = tr[1];
                vbh[nh * 2 + 1][0] = tr[2]; vbh[nh * 2 + 1][1] = tr[3];
                ldm_x4_t(SBB + 24576 + off, tr);
                vbl[nh * 2][0] = tr[0];     vbl[nh * 2][1] = tr[1];
                vbl[nh * 2 + 1][0] = tr[2]; vbl[nh * 2 + 1][1] = tr[3];
            }
#pragma unroll
            for (int nt = 0; nt < 8; nt++)
                mma16816(o[nt], pah[j], vbh[nt]);
#pragma unroll
            for (int nt = 0; nt < 8; nt++)
                mma16816(o[nt], pah[j], vbl[nt]);
#pragma unroll
            for (int nt = 0; nt < 8; nt++)
                mma16816(o[nt], pal[j], vbh[nt]);
        }
        __syncthreads();
    }

    rs0 += __shfl_xor_sync(0xffffffffu, rs0, 1);
    rs0 += __shfl_xor_sync(0xffffffffu, rs0, 2);
    rs1 += __shfl_xor_sync(0xffffffffu, rs1, 1);
    rs1 += __shfl_xor_sync(0xffffffffu, rs1, 2);

    int g = lane >> 2, tc = (lane & 3) * 2;
    int row0 = q0 + wid * 16 + g;
    float i0 = 1.f / rs0, i1 = 1.f / rs1;
#pragma unroll
    for (int nt = 0; nt < 8; nt++) {
        int col = h * DH + nt * 8 + tc;
        size_t off0 = (size_t)(b * NQ + row0) * CD + col;
        size_t off1 = off0 + (size_t)8 * CD;
        float v0 = o[nt][0] * i0, v1 = o[nt][1] * i0;
        float v2 = o[nt][2] * i1, v3 = o[nt][3] * i1;
        bf16 h0, l0, h1, l1;
        bsplit(v0, h0, l0); bsplit(v1, h1, l1);
        *(__nv_bfloat162*)(g_o_hi + off0) = __halves2bfloat162(h0, h1);
        *(__nv_bfloat162*)(g_o_lo + off0) = __halves2bfloat162(l0, l1);
        bsplit(v2, h0, l0); bsplit(v3, h1, l1);
        *(__nv_bfloat162*)(g_o_hi + off1) = __halves2bfloat162(h0, h1);
        *(__nv_bfloat162*)(g_o_lo + off1) = __halves2bfloat162(l0, l1);
    }
}

// ---------------------------------------------------------------------------
// kernel_launch
// ---------------------------------------------------------------------------
extern "C" void kernel_launch(void* const* d_in, const int* in_sizes, int n_in,
                              void* d_out, int out_size) {
    const float* x     = (const float*)d_in[0];
    const float* Wq    = (const float*)d_in[1];
    const float* bq    = (const float*)d_in[2];
    const float* Wkv   = (const float*)d_in[3];
    const float* bkv   = (const float*)d_in[4];
    const float* Wproj = (const float*)d_in[5];
    const float* bproj = (const float*)d_in[6];
    const float* Aq    = (const float*)d_in[7];
    const float* Bq    = (const float*)d_in[8];
    const float* Av    = (const float*)d_in[9];
    const float* Bv    = (const float*)d_in[10];
    const float* Wsr   = (const float*)d_in[11];
    const float* bsr   = (const float*)d_in[12];
    const float* gamma = (const float*)d_in[13];
    const float* beta  = (const float*)d_in[14];
    float* outp = (float*)d_out;

    bf16 *xsh, *xsl, *oh, *ol, *pqh, *pql, *pkvh, *pkvl, *bkvh, *bkvl, *bph, *bpl;
    cudaGetSymbolAddress((void**)&bkvh, g_BkvT_hi);cudaGetSymbolAddress((void**)&bkvl, g_BkvT_lo);
    cudaGetSymbolAddress((void**)&bph,  g_BpT_hi); cudaGetSymbolAddress((void**)&bpl,  g_BpT_lo);
    cudaGetSymbolAddress((void**)&xsh,  g_xs_hi);  cudaGetSymbolAddress((void**)&xsl,  g_xs_lo);
    cudaGetSymbolAddress((void**)&oh,   g_o_hi);   cudaGetSymbolAddress((void**)&ol,   g_o_lo);
    cudaGetSymbolAddress((void**)&pqh,  g_q_hi);   cudaGetSymbolAddress((void**)&pql,  g_q_lo);
    cudaGetSymbolAddress((void**)&pkvh, g_kv_hi);  cudaGetSymbolAddress((void**)&pkvl, g_kv_lo);

    cudaFuncSetAttribute(gemm_bf16x3<0>, cudaFuncAttributeMaxDynamicSharedMemorySize, GEMM_SMEM);
    cudaFuncSetAttribute(gemm_bf16x3<1>, cudaFuncAttributeMaxDynamicSharedMemorySize, GEMM_SMEM);
    cudaFuncSetAttribute(gemm_q_xs, cudaFuncAttributeMaxDynamicSharedMemorySize, GEMM_SMEM);
    cudaFuncSetAttribute(attn_hmma, cudaFuncAttributeMaxDynamicSharedMemorySize, ATTN_SMEM);

    // 1) merged prep: split x + weight transpose/LoRA/split
    prep_all<<<6144, 256>>>(x, Wq, Aq, Bq, Wkv, Av, Bv, Wsr, Wproj);

    // 2) merged: xs split-K partial GEMMs (4 slices) + q GEMM
    gemm_q_xs<<<dim3(8, 128), 256, GEMM_SMEM>>>(bq);

    // 3) LayerNorm (sums split-K partials + bsr) -> split bf16
    ln_split_kernel<<<NB * NKV, 256>>>(gamma, beta, bsr);

    // 4) kv GEMM (2048 x 1024, K=512), split bf16 out
    gemm_bf16x3<1><<<dim3(16, 16), 256, GEMM_SMEM>>>(
        xsh, xsl, bkvh, bkvl, bkv, pkvh, pkvl, CD, 2 * CD);

    // 5) attention (HMMA bf16x3, 2 CTAs/SM) -> split bf16
    attn_hmma<<<dim3(NQ / 128, NHEAD, NB), 256, ATTN_SMEM>>>(pqh, pql, pkvh, pkvl);

    // 6) out GEMM -> d_out (fp32)
    gemm_bf16x3<0><<<dim3(8, 64), 256, GEMM_SMEM>>>(
        oh, ol, bph, bpl, bproj, outp, nullptr, CD, CD);
}

// round 14
// speedup vs baseline: 1.5447x; 1.1812x over previous
#include <cuda_runtime.h>
#include <cuda_bf16.h>
#include <cuda_fp16.h>
#include <cstdint>
#include <math.h>

#define NB    2
#define NQ    4096
#define NKV   1024
#define CD    512
#define NHEAD 8
#define DH    64
#define RLORA 8
#define LN_EPS 1e-5f

typedef __nv_bfloat16 bf16;
typedef __half fp16;

// ---------------------------------------------------------------------------
// Device scratch
// ---------------------------------------------------------------------------
__device__ bf16  g_x_hi [NB*NQ*CD],      g_x_lo [NB*NQ*CD];
__device__ bf16  g_BqT_hi[CD*CD],        g_BqT_lo[CD*CD];
__device__ bf16  g_BkvT_hi[2*CD*CD],     g_BkvT_lo[2*CD*CD];
__device__ bf16  g_BsrT_hi[CD*4*CD],     g_BsrT_lo[CD*4*CD];   // slice-blocked
__device__ bf16  g_BpT_hi[CD*CD],        g_BpT_lo[CD*CD];
__device__ fp16  g_q_h16[NB*NQ*CD],      g_q_l16[NB*NQ*CD];    // q: fp16 hi/lo
__device__ fp16  g_kv_h16[NB*NKV*2*CD];                        // kv: fp16 single
__device__ float g_xsp[4][NB*NKV*CD];
__device__ bf16  g_xs_hi[NB*NKV*CD],     g_xs_lo[NB*NKV*CD];
__device__ bf16  g_o_hi[NB*NQ*CD],       g_o_lo[NB*NQ*CD];
__device__ float g_zbias[2*CD];

// ---------------------------------------------------------------------------
// helpers
// ---------------------------------------------------------------------------
__device__ __forceinline__ uint32_t smem_u32(const void* p) {
    uint32_t a;
    asm("{ .reg .u64 t; cvta.to.shared.u64 t, %1; cvt.u32.u64 %0, t; }" : "=r"(a) : "l"(p));
    return a;
}
#define SW128(o) ((o) ^ (((o) >> 3) & 0x70))

__device__ __forceinline__ void cp16(uint32_t dst, const void* src) {
    asm volatile("cp.async.cg.shared.global [%0], [%1], 16;" :: "r"(dst), "l"(src));
}
__device__ __forceinline__ void cp_commit() { asm volatile("cp.async.commit_group;"); }
template<int N> __device__ __forceinline__ void cp_wait() {
    asm volatile("cp.async.wait_group %0;" :: "n"(N));
}

__device__ __forceinline__ void ldm_x4(uint32_t addr, uint32_t* r) {
    asm volatile("ldmatrix.sync.aligned.m8n8.x4.shared.b16 {%0,%1,%2,%3}, [%4];"
        : "=r"(r[0]), "=r"(r[1]), "=r"(r[2]), "=r"(r[3]) : "r"(addr));
}
__device__ __forceinline__ void ldm_x4_t(uint32_t addr, uint32_t* r) {
    asm volatile("ldmatrix.sync.aligned.m8n8.x4.trans.shared.b16 {%0,%1,%2,%3}, [%4];"
        : "=r"(r[0]), "=r"(r[1]), "=r"(r[2]), "=r"(r[3]) : "r"(addr));
}
__device__ __forceinline__ void mma16816(float* c, const uint32_t* a, const uint32_t* b) {
    asm volatile("mma.sync.aligned.m16n8k16.row.col.f32.bf16.bf16.f32 "
        "{%0,%1,%2,%3}, {%4,%5,%6,%7}, {%8,%9}, {%0,%1,%2,%3};"
        : "+f"(c[0]), "+f"(c[1]), "+f"(c[2]), "+f"(c[3])
        : "r"(a[0]), "r"(a[1]), "r"(a[2]), "r"(a[3]), "r"(b[0]), "r"(b[1]));
}
__device__ __forceinline__ void mma16816h(float* c, const uint32_t* a, const uint32_t* b) {
    asm volatile("mma.sync.aligned.m16n8k16.row.col.f32.f16.f16.f32 "
        "{%0,%1,%2,%3}, {%4,%5,%6,%7}, {%8,%9}, {%0,%1,%2,%3};"
        : "+f"(c[0]), "+f"(c[1]), "+f"(c[2]), "+f"(c[3])
        : "r"(a[0]), "r"(a[1]), "r"(a[2]), "r"(a[3]), "r"(b[0]), "r"(b[1]));
}

__device__ __forceinline__ void bsplit(float a, bf16& hi, bf16& lo) {
    hi = __float2bfloat16_rn(a);
    lo = __float2bfloat16_rn(a - __bfloat162float(hi));
}
__device__ __forceinline__ void hsplit(float a, fp16& hi, fp16& lo) {
    hi = __float2half_rn(a);
    lo = __float2half_rn(a - __half2float(hi));
}
__device__ __forceinline__ uint32_t packbf(bf16 a, bf16 b) {
    __nv_bfloat162 h = __halves2bfloat162(a, b);
    return *reinterpret_cast<uint32_t*>(&h);
}
__device__ __forceinline__ uint32_t packhf(fp16 a, fp16 b) {
    __half2 h = __halves2half2(a, b);
    return *reinterpret_cast<uint32_t*>(&h);
}

// ---------------------------------------------------------------------------
// GEMM core (HMMA bf16x3): C[M,N] = A @ B^T + bias
//   CTA tile 128x64, BK=64, 256 threads, 8 warps (4x2), warp tile 32x32.
//   OB=0: fp32 out; OB=1: fp16 hi/lo out; OB=2: fp16 single out.
//   PERM=1: A addresses patch `pslice` of the conv permutation of g_x.
// ---------------------------------------------------------------------------
#define A_TILE_B 16384
#define B_TILE_B 8192
#define STAGE_B  (2 * A_TILE_B + 2 * B_TILE_B)   // 48 KB
#define GEMM_SMEM (2 * STAGE_B)                  // 96 KB

template<int OB, int PERM>
__device__ __forceinline__ void gemm_core(
    uint32_t sb,
    const bf16* __restrict__ Ah, const bf16* __restrict__ Al,
    const bf16* __restrict__ Bh, const bf16* __restrict__ Bl,
    const float* __restrict__ bias, void* __restrict__ Cv, void* __restrict__ Cv2,
    int K, int ldc, int bx, int by, int pslice)
{
    int tid = threadIdx.x, wid = tid >> 5, lane = tid & 31;

    const bf16* aAh = PERM ? Ah : Ah + (size_t)by * 128 * K;
    const bf16* aAl = PERM ? Al : Al + (size_t)by * 128 * K;
    const bf16* aBh = Bh + (size_t)bx * 64 * K;
    const bf16* aBl = Bl + (size_t)bx * 64 * K;

    auto issue = [&](int chunk, int buf) {
        int k0 = chunk << 6;
        uint32_t stg = sb + buf * STAGE_B;
#pragma unroll
        for (int t = 0; t < 2; t++) {
            const bf16* src = t ? aAl : aAh;
#pragma unroll
            for (int it = 0; it < 4; it++) {
                int idx = it * 256 + tid;
                int r = idx >> 3, c16 = idx & 7;
                size_t goff;
                if (PERM) {
                    int m = by * 128 + r;
                    int bb = m >> 10, pp = m & 1023;
                    int tok = bb * NQ + ((pp >> 5) * 2 + (pslice >> 1)) * 64
                            + ((pp & 31) * 2 + (pslice & 1));
                    goff = (size_t)tok * CD + k0 + c16 * 8;
                } else {
                    goff = (size_t)r * K + k0 + c16 * 8;
                }
                cp16(stg + t * A_TILE_B + SW128(r * 128 + c16 * 16), src + goff);
            }
        }
#pragma unroll
        for (int t = 0; t < 2; t++) {
            const bf16* src = (t ? aBl : aBh) + k0;
            uint32_t base = stg + 2 * A_TILE_B + t * B_TILE_B;
#pragma unroll
            for (int it = 0; it < 2; it++) {
                int idx = it * 256 + tid;
                int r = idx >> 3, c16 = idx & 7;
                cp16(base + SW128(r * 128 + c16 * 16),
                     src + (size_t)r * K + c16 * 8);
            }
        }
        cp_commit();
    };

    float acc[2][4][4];
#pragma unroll
    for (int i = 0; i < 2; i++)
#pragma unroll
        for (int j = 0; j < 4; j++)
#pragma unroll
            for (int e = 0; e < 4; e++) acc[i][j][e] = 0.f;

    int wm = wid >> 1, wn = wid & 1;
    int nch = K >> 6;

    issue(0, 0);
    for (int i = 0; i < nch; i++) {
        int buf = i & 1;
        if (i + 1 < nch) { issue(i + 1, buf ^ 1); cp_wait<1>(); }
        else             { cp_wait<0>(); }
        __syncthreads();

        uint32_t stg = sb + buf * STAGE_B;
        uint32_t aH = stg;
        uint32_t aL = stg + A_TILE_B;
        uint32_t bH = stg + 2 * A_TILE_B;
        uint32_t bL = bH + B_TILE_B;

#pragma unroll
        for (int ks = 0; ks < 4; ks++) {
            int kb = ks * 32;
            uint32_t ah[2][4], al[2][4], bh[4][2], bl[4][2];
#pragma unroll
            for (int at = 0; at < 2; at++) {
                int row = wm * 32 + at * 16 + (lane & 15);
                int colb = kb + ((lane >> 4) << 4);
                uint32_t off = SW128(row * 128 + colb);
                ldm_x4(aH + off, ah[at]);
                ldm_x4(aL + off, al[at]);
            }
#pragma unroll
            for (int bt = 0; bt < 2; bt++) {
                int row = wn * 32 + bt * 16 + ((lane >> 4) << 3) + (lane & 7);
                int colb = kb + (((lane >> 3) & 1) << 4);
                uint32_t off = SW128(row * 128 + colb);
                uint32_t t[4];
                ldm_x4(bH + off, t);
                bh[bt * 2][0] = t[0]; bh[bt * 2][1] = t[1];
                bh[bt * 2 + 1][0] = t[2]; bh[bt * 2 + 1][1] = t[3];
                ldm_x4(bL + off, t);
                bl[bt * 2][0] = t[0]; bl[bt * 2][1] = t[1];
                bl[bt * 2 + 1][0] = t[2]; bl[bt * 2 + 1][1] = t[3];
            }
#pragma unroll
            for (int at = 0; at < 2; at++)
#pragma unroll
                for (int nt = 0; nt < 4; nt++)
                    mma16816(acc[at][nt], ah[at], bh[nt]);
#pragma unroll
            for (int at = 0; at < 2; at++)
#pragma unroll
                for (int nt = 0; nt < 4; nt++)
                    mma16816(acc[at][nt], ah[at], bl[nt]);
#pragma unroll
            for (int at = 0; at < 2; at++)
#pragma unroll
                for (int nt = 0; nt < 4; nt++)
                    mma16816(acc[at][nt], al[at], bh[nt]);
        }
        __syncthreads();
    }

    int g = lane >> 2, tc = (lane & 3) * 2;
#pragma unroll
    for (int nt = 0; nt < 4; nt++) {
        int col = bx * 64 + wn * 32 + nt * 8 + tc;
        float b0 = bias[col], b1 = bias[col + 1];
#pragma unroll
        for (int at = 0; at < 2; at++) {
            int row0 = by * 128 + wm * 32 + at * 16 + g;
            float v00 = acc[at][nt][0] + b0, v01 = acc[at][nt][1] + b1;
            float v10 = acc[at][nt][2] + b0, v11 = acc[at][nt][3] + b1;
            if (OB == 1) {
                fp16* C  = (fp16*)Cv;
                fp16* C2 = (fp16*)Cv2;
                fp16 h0, l0, h1, l1;
                hsplit(v00, h0, l0); hsplit(v01, h1, l1);
                *(uint32_t*)(C  + (size_t)row0 * ldc + col) = packhf(h0, h1);
                *(uint32_t*)(C2 + (size_t)row0 * ldc + col) = packhf(l0, l1);
                hsplit(v10, h0, l0); hsplit(v11, h1, l1);
                *(uint32_t*)(C  + (size_t)(row0 + 8) * ldc + col) = packhf(h0, h1);
                *(uint32_t*)(C2 + (size_t)(row0 + 8) * ldc + col) = packhf(l0, l1);
            } else if (OB == 2) {
                fp16* C = (fp16*)Cv;
                *(uint32_t*)(C + (size_t)row0 * ldc + col) =
                    packhf(__float2half_rn(v00), __float2half_rn(v01));
                *(uint32_t*)(C + (size_t)(row0 + 8) * ldc + col) =
                    packhf(__float2half_rn(v10), __float2half_rn(v11));
            } else {
                float* C = (float*)Cv;
                *(float2*)(C + (size_t)row0 * ldc + col)       = make_float2(v00, v01);
                *(float2*)(C + (size_t)(row0 + 8) * ldc + col) = make_float2(v10, v11);
            }
        }
    }
}

template<int OB>
__global__ __launch_bounds__(256, 2) void gemm_bf16x3(
    const bf16* __restrict__ Ah, const bf16* __restrict__ Al,
    const bf16* __restrict__ Bh, const bf16* __restrict__ Bl,
    const float* __restrict__ bias, void* __restrict__ Cv, void* __restrict__ Cv2,
    int K, int ldc)
{
    extern __shared__ char smem[];
    gemm_core<OB, 0>(smem_u32(smem), Ah, Al, Bh, Bl, bias, Cv, Cv2, K, ldc,
                     blockIdx.x, blockIdx.y, 0);
}

// Merged independent GEMMs: grid (8, 128).
__global__ __launch_bounds__(256, 2) void gemm_q_xs(
    const float* __restrict__ bq)
{
    extern __shared__ char smem[];
    uint32_t sb = smem_u32(smem);
    if (blockIdx.y < 64) {
        int slice = blockIdx.y >> 4, mt = blockIdx.y & 15;
        gemm_core<0, 1>(sb, g_x_hi, g_x_lo,
                        g_BsrT_hi + (size_t)slice * CD * CD,
                        g_BsrT_lo + (size_t)slice * CD * CD,
                        g_zbias, (void*)g_xsp[slice], nullptr,
                        CD, CD, blockIdx.x, mt, slice);
    } else {
        gemm_core<1, 0>(sb, g_x_hi, g_x_lo, g_BqT_hi, g_BqT_lo, bq,
                        (void*)g_q_h16, (void*)g_q_l16, CD, CD,
                        blockIdx.x, blockIdx.y - 64, 0);
    }
}

// ---------------------------------------------------------------------------
// Merged prep (unchanged)
// ---------------------------------------------------------------------------
__global__ __launch_bounds__(256) void prep_all(
    const float* __restrict__ x,
    const float* __restrict__ Wq,   const float* __restrict__ Aq, const float* __restrict__ Bq,
    const float* __restrict__ Wkv,  const float* __restrict__ Av, const float* __restrict__ Bv,
    const float* __restrict__ Wsr,  const float* __restrict__ Wproj)
{
    if (blockIdx.x < 4096) {
        int e = blockIdx.x * 256 + threadIdx.x;
        float4 v = ((const float4*)x)[e];
        bf16 h0, l0, h1, l1, h2, l2, h3, l3;
        bsplit(v.x, h0, l0); bsplit(v.y, h1, l1);
        bsplit(v.z, h2, l2); bsplit(v.w, h3, l3);
        ((uint32_t*)g_x_hi)[e * 2]     = packbf(h0, h1);
        ((uint32_t*)g_x_hi)[e * 2 + 1] = packbf(h2, h3);
        ((uint32_t*)g_x_lo)[e * 2]     = packbf(l0, l1);
        ((uint32_t*)g_x_lo)[e * 2 + 1] = packbf(l2, l3);
        return;
    }

    __shared__ float tile[32][33];
    int t = blockIdx.x - 4096;
    const float *W, *A = nullptr, *LB = nullptr;
    bf16 *Dh, *Dl;
    int K, stride, k0, n0;

    if (t < 256) {
        W = Wq; A = Aq; LB = Bq; Dh = g_BqT_hi; Dl = g_BqT_lo;
        K = 512; stride = 512; k0 = (t >> 4) * 32; n0 = (t & 15) * 32;
    } else if (t < 768) {
        int i = t - 256;
        W = Wkv; A = Av; LB = Bv; Dh = g_BkvT_hi; Dl = g_BkvT_lo;
        K = 512; stride = 1024; k0 = (i >> 5) * 32; n0 = (i & 31) * 32;
    } else if (t < 1792) {
        int i = t - 768;
        W = Wsr;
        int kk0 = (i >> 4) * 32;
        int nn0 = (i & 15) * 32;
        int tx = threadIdx.x & 31, ty = threadIdx.x >> 5;
#pragma unroll
        for (int ii = 0; ii < 4; ii++) {
            int kk = kk0 + ty + ii * 8, n = nn0 + tx;
            tile[ty + ii * 8][tx] = W[(size_t)kk * 512 + n];
        }
        __syncthreads();
#pragma unroll
        for (int ii = 0; ii < 4; ii++) {
            int n = nn0 + ty + ii * 8, kk = kk0 + tx;
            int p = kk >> 9, k = kk & 511;
            float v = tile[tx][ty + ii * 8];
            bf16 h, l; bsplit(v, h, l);
            size_t d = (size_t)p * CD * CD + (size_t)n * CD + k;
            g_BsrT_hi[d] = h;
            g_BsrT_lo[d] = l;
        }
        return;
    } else {
        int i = t - 1792;
        W = Wproj; Dh = g_BpT_hi; Dl = g_BpT_lo;
        K = 512; stride = 512; k0 = (i >> 4) * 32; n0 = (i & 15) * 32;
    }

    int tx = threadIdx.x & 31, ty = threadIdx.x >> 5;
#pragma unroll
    for (int i = 0; i < 4; i++) {
        int k = k0 + ty + i * 8, n = n0 + tx;
        float v = W[(size_t)k * stride + n];
        if (A) {
            float l = 0.f;
#pragma unroll
            for (int r = 0; r < RLORA; r++)
                l = fmaf(A[k * RLORA + r], LB[r * CD + (n & (CD - 1))], l);
            v += l;
        }
        tile[ty + i * 8][tx] = v;
    }
    __syncthreads();
#pragma unroll
    for (int i = 0; i < 4; i++) {
        int n = n0 + ty + i * 8, k = k0 + tx;
        float v = tile[tx][ty + i * 8];
        bf16 h, l; bsplit(v, h, l);
        Dh[(size_t)n * K + k] = h;
        Dl[(size_t)n * K + k] = l;
    }
}

// ---------------------------------------------------------------------------
// LayerNorm (unchanged)
// ---------------------------------------------------------------------------
__device__ __forceinline__ float warp_sum(float v) {
#pragma unroll
    for (int o = 16; o > 0; o >>= 1) v += __shfl_xor_sync(0xffffffffu, v, o);
    return v;
}

__global__ __launch_bounds__(256) void ln_split_kernel(const float* __restrict__ gamma,
                                                       const float* __restrict__ beta,
                                                       const float* __restrict__ bsr) {
    int row = blockIdx.x;
    size_t base = (size_t)row * CD;
    int tid = threadIdx.x;
    float a = ((g_xsp[0][base + tid]       + g_xsp[1][base + tid])
            +  (g_xsp[2][base + tid]       + g_xsp[3][base + tid])) + bsr[tid];
    float c = ((g_xsp[0][base + tid + 256] + g_xsp[1][base + tid + 256])
            +  (g_xsp[2][base + tid + 256] + g_xsp[3][base + tid + 256])) + bsr[tid + 256];

    float s  = warp_sum(a + c);
    float sq = warp_sum(a * a + c * c);
    __shared__ float sh[16];
    int w = tid >> 5, l = tid & 31;
    if (l == 0) { sh[w] = s; sh[8 + w] = sq; }
    __syncthreads();
    if (w == 0) {
        float ts = (l < 8) ? sh[l] : 0.f;
        float tq = (l < 8) ? sh[8 + l] : 0.f;
        ts = warp_sum(ts); tq = warp_sum(tq);
        if (l == 0) { sh[0] = ts; sh[1] = tq; }
    }
    __syncthreads();
    float mean = sh[0] * (1.f / CD);
    float var  = sh[1] * (1.f / CD) - mean * mean;
    float inv  = rsqrtf(var + LN_EPS);
    float y0 = (a - mean) * inv * gamma[tid] + beta[tid];
    float y1 = (c - mean) * inv * gamma[tid + 256] + beta[tid + 256];
    bf16 h, lo;
    bsplit(y0, h, lo); g_xs_hi[base + tid] = h;       g_xs_lo[base + tid] = lo;
    bsplit(y1, h, lo); g_xs_hi[base + tid + 256] = h; g_xs_lo[base + tid + 256] = lo;
}

// ---------------------------------------------------------------------------
// HMMA flash attention, fp16x2:
//   S = (qh + ql) . kh        (2 fp16 MMA passes; k_lo not needed at all)
//   O = (ph + pl) . vh        (2 fp16 MMA passes; v_lo not needed at all)
// Error: k damped through softmax (~3e-6), v single fp16 direct (~3e-4).
// grid (NQ/128, NHEAD, NB), 256 threads (8 warps x 16 q-rows), 64KB smem.
// ---------------------------------------------------------------------------
#define ATTN_SMEM 65536   // Q hi/lo 32KB + 2 x (kh 8KB + vh 8KB)

__global__ __launch_bounds__(256, 2) void attn_hmma(
    const fp16* __restrict__ qh, const fp16* __restrict__ ql,
    const fp16* __restrict__ kv)
{
    extern __shared__ char smem[];
    uint32_t sb = smem_u32(smem);
    const uint32_t QH = sb, QL = sb + 16384, ST = sb + 32768;

    int tid = threadIdx.x, lane = tid & 31, wid = tid >> 5;
    int b = blockIdx.z, h = blockIdx.y;
    int q0 = blockIdx.x * 128;

    const fp16* qgh = qh + (size_t)(b * NQ + q0) * CD + h * DH;
    const fp16* qgl = ql + (size_t)(b * NQ + q0) * CD + h * DH;
    const fp16* kg  = kv + (size_t)b * NKV * (2 * CD) + h * DH;
    const fp16* vg  = kg + CD;

#pragma unroll
    for (int it = 0; it < 4; it++) {
        int idx = it * 256 + tid;
        int r = idx >> 3, c16 = idx & 7;
        uint32_t so = SW128(r * 128 + c16 * 16);
        size_t go = (size_t)r * CD + c16 * 8;
        cp16(QH + so, qgh + go);
        cp16(QL + so, qgl + go);
    }
    cp_commit();

    auto issue_kv = [&](int t, int bufi) {
        int m0 = t * 64;
        uint32_t SBB = ST + bufi * 16384;
#pragma unroll
        for (int it = 0; it < 2; it++) {
            int idx = it * 256 + tid;
            int r = idx >> 3, c16 = idx & 7;
            size_t go = (size_t)(m0 + r) * (2 * CD) + c16 * 8;
            uint32_t so = SW128(r * 128 + c16 * 16);
            cp16(SBB + so,        kg + go);
            cp16(SBB + 8192 + so, vg + go);
        }
        cp_commit();
    };

    issue_kv(0, 0);
    cp_wait<1>();
    __syncthreads();

    float o[8][4];
#pragma unroll
    for (int nt = 0; nt < 8; nt++)
#pragma unroll
        for (int e = 0; e < 4; e++) o[nt][e] = 0.f;
    float rs0 = 0.f, rs1 = 0.f;

    const float SC = 0.125f;
    int qrow = wid * 16 + (lane & 15);
    int qcolb = (lane >> 4) << 4;

    for (int t = 0; t < 16; t++) {
        int bufi = t & 1;
        if (t + 1 < 16) { issue_kv(t + 1, bufi ^ 1); cp_wait<1>(); }
        else            { cp_wait<0>(); }
        __syncthreads();

        uint32_t SBB = ST + bufi * 16384;

        float s[8][4];
#pragma unroll
        for (int nt = 0; nt < 8; nt++)
#pragma unroll
            for (int e = 0; e < 4; e++) s[nt][e] = 0.f;

#pragma unroll
        for (int ks = 0; ks < 4; ks++) {
            uint32_t aqh[4], aql[4];
            {
                uint32_t off = SW128(qrow * 128 + ks * 32 + qcolb);
                ldm_x4(QH + off, aqh);
                ldm_x4(QL + off, aql);
            }
            uint32_t bh[8][2];
#pragma unroll
            for (int bt = 0; bt < 4; bt++) {
                int row = bt * 16 + ((lane >> 4) << 3) + (lane & 7);
                int colb = ks * 32 + (((lane >> 3) & 1) << 4);
                uint32_t off = SW128(row * 128 + colb);
                uint32_t tr[4];
                ldm_x4(SBB + off, tr);
                bh[bt * 2][0] = tr[0];     bh[bt * 2][1] = tr[1];
                bh[bt * 2 + 1][0] = tr[2]; bh[bt * 2 + 1][1] = tr[3];
            }
#pragma unroll
            for (int nt = 0; nt < 8; nt++)
                mma16816h(s[nt], aqh, bh[nt]);
#pragma unroll
            for (int nt = 0; nt < 8; nt++)
                mma16816h(s[nt], aql, bh[nt]);
        }

        uint32_t pah[4][4], pal[4][4];
#pragma unroll
        for (int nt = 0; nt < 8; nt++) {
            float p0 = __expf(s[nt][0] * SC);
            float p1 = __expf(s[nt][1] * SC);
            float p2 = __expf(s[nt][2] * SC);
            float p3 = __expf(s[nt][3] * SC);
            rs0 += p0 + p1;
            rs1 += p2 + p3;
            fp16 h0, l0, h1, l1, h2, l2, h3, l3;
            hsplit(p0, h0, l0); hsplit(p1, h1, l1);
            hsplit(p2, h2, l2); hsplit(p3, h3, l3);
            int j = nt >> 1, half = nt & 1;
            pah[j][half * 2]     = packhf(h0, h1);
            pah[j][half * 2 + 1] = packhf(h2, h3);
            pal[j][half * 2]     = packhf(l0, l1);
            pal[j][half * 2 + 1] = packhf(l2, l3);
        }

#pragma unroll
        for (int j = 0; j < 4; j++) {
            uint32_t vbh[8][2];
#pragma unroll
            for (int nh = 0; nh < 4; nh++) {
                int row = j * 16 + (lane & 15);
                int colb = nh * 32 + ((lane >> 4) << 4);
                uint32_t off = SW128(row * 128 + colb);
                uint32_t tr[4];
                ldm_x4_t(SBB + 8192 + off, tr);
                vbh[nh * 2][0] = tr[0];     vbh[nh * 2][1] = tr[1];
                vbh[nh * 2 + 1][0] = tr[2]; vbh[nh * 2 + 1][1] = tr[3];
            }
#pragma unroll
            for (int nt = 0; nt < 8; nt++)
                mma16816h(o[nt], pah[j], vbh[nt]);
#pragma unroll
            for (int nt = 0; nt < 8; nt++)
                mma16816h(o[nt], pal[j], vbh[nt]);
        }
        __syncthreads();
    }

    rs0 += __shfl_xor_sync(0xffffffffu, rs0, 1);
    rs0 += __shfl_xor_sync(0xffffffffu, rs0, 2);
    rs1 += __shfl_xor_sync(0xffffffffu, rs1, 1);
    rs1 += __shfl_xor_sync(0xffffffffu, rs1, 2);

    int g = lane >> 2, tc = (lane & 3) * 2;
    int row0 = q0 + wid * 16 + g;
    float i0 = 1.f / rs0, i1 = 1.f / rs1;
#pragma unroll
    for (int nt = 0; nt < 8; nt++) {
        int col = h * DH + nt * 8 + tc;
        size_t off0 = (size_t)(b * NQ + row0) * CD + col;
        size_t off1 = off0 + (size_t)8 * CD;
        float v0 = o[nt][0] * i0, v1 = o[nt][1] * i0;
        float v2 = o[nt][2] * i1, v3 = o[nt][3] * i1;
        bf16 h0, l0, h1, l1;
        bsplit(v0, h0, l0); bsplit(v1, h1, l1);
        *(__nv_bfloat162*)(g_o_hi + off0) = __halves2bfloat162(h0, h1);
        *(__nv_bfloat162*)(g_o_lo + off0) = __halves2bfloat162(l0, l1);
        bsplit(v2, h0, l0); bsplit(v3, h1, l1);
        *(__nv_bfloat162*)(g_o_hi + off1) = __halves2bfloat162(h0, h1);
        *(__nv_bfloat162*)(g_o_lo + off1) = __halves2bfloat162(l0, l1);
    }
}

// ---------------------------------------------------------------------------
// kernel_launch
// ---------------------------------------------------------------------------
extern "C" void kernel_launch(void* const* d_in, const int* in_sizes, int n_in,
                              void* d_out, int out_size) {
    const float* x     = (const float*)d_in[0];
    const float* Wq    = (const float*)d_in[1];
    const float* bq    = (const float*)d_in[2];
    const float* Wkv   = (const float*)d_in[3];
    const float* bkv   = (const float*)d_in[4];
    const float* Wproj = (const float*)d_in[5];
    const float* bproj = (const float*)d_in[6];
    const float* Aq    = (const float*)d_in[7];
    const float* Bq    = (const float*)d_in[8];
    const float* Av    = (const float*)d_in[9];
    const float* Bv    = (const float*)d_in[10];
    const float* Wsr   = (const float*)d_in[11];
    const float* bsr   = (const float*)d_in[12];
    const float* gamma = (const float*)d_in[13];
    const float* beta  = (const float*)d_in[14];
    float* outp = (float*)d_out;

    bf16 *xsh, *xsl, *oh, *ol, *bkvh, *bkvl, *bph, *bpl;
    fp16 *pqh, *pql, *pkv;
    cudaGetSymbolAddress((void**)&bkvh, g_BkvT_hi);cudaGetSymbolAddress((void**)&bkvl, g_BkvT_lo);
    cudaGetSymbolAddress((void**)&bph,  g_BpT_hi); cudaGetSymbolAddress((void**)&bpl,  g_BpT_lo);
    cudaGetSymbolAddress((void**)&xsh,  g_xs_hi);  cudaGetSymbolAddress((void**)&xsl,  g_xs_lo);
    cudaGetSymbolAddress((void**)&oh,   g_o_hi);   cudaGetSymbolAddress((void**)&ol,   g_o_lo);
    cudaGetSymbolAddress((void**)&pqh,  g_q_h16);  cudaGetSymbolAddress((void**)&pql,  g_q_l16);
    cudaGetSymbolAddress((void**)&pkv,  g_kv_h16);

    cudaFuncSetAttribute(gemm_bf16x3<0>, cudaFuncAttributeMaxDynamicSharedMemorySize, GEMM_SMEM);
    cudaFuncSetAttribute(gemm_bf16x3<2>, cudaFuncAttributeMaxDynamicSharedMemorySize, GEMM_SMEM);
    cudaFuncSetAttribute(gemm_q_xs, cudaFuncAttributeMaxDynamicSharedMemorySize, GEMM_SMEM);
    cudaFuncSetAttribute(attn_hmma, cudaFuncAttributeMaxDynamicSharedMemorySize, ATTN_SMEM);

    // 1) merged prep: split x + weight transpose/LoRA/split
    prep_all<<<6144, 256>>>(x, Wq, Aq, Bq, Wkv, Av, Bv, Wsr, Wproj);

    // 2) merged: xs split-K partial GEMMs (4 slices) + q GEMM (fp16 hi/lo out)
    gemm_q_xs<<<dim3(8, 128), 256, GEMM_SMEM>>>(bq);

    // 3) LayerNorm (sums split-K partials + bsr) -> split bf16
    ln_split_kernel<<<NB * NKV, 256>>>(gamma, beta, bsr);

    // 4) kv GEMM (2048 x 1024, K=512), fp16 single out
    gemm_bf16x3<2><<<dim3(16, 16), 256, GEMM_SMEM>>>(
        xsh, xsl, bkvh, bkvl, bkv, pkv, nullptr, CD, 2 * CD);

    // 5) attention (fp16x2 HMMA) -> split bf16
    attn_hmma<<<dim3(NQ / 128, NHEAD, NB), 256, ATTN_SMEM>>>(pqh, pql, pkv);

    // 6) out GEMM -> d_out (fp32)
    gemm_bf16x3<0><<<dim3(8, 64), 256, GEMM_SMEM>>>(
        oh, ol, bph, bpl, bproj, outp, nullptr, CD, CD);
}

// round 15
// speedup vs baseline: 1.7794x; 1.1519x over previous
#include <cuda_runtime.h>
#include <cuda_bf16.h>
#include <cuda_fp16.h>
#include <cstdint>
#include <math.h>

#define NB    2
#define NQ    4096
#define NKV   1024
#define CD    512
#define NHEAD 8
#define DH    64
#define RLORA 8
#define LN_EPS 1e-5f

typedef __half fp16;

// ---------------------------------------------------------------------------
// Device scratch (all activation/weight tensors now fp16)
// ---------------------------------------------------------------------------
__device__ fp16  g_x_hi [NB*NQ*CD],      g_x_lo [NB*NQ*CD];
__device__ fp16  g_BqT [CD*CD];
__device__ fp16  g_BkvT[2*CD*CD];
__device__ fp16  g_BsrT[CD*4*CD];        // slice-blocked: [p][n][k]
__device__ fp16  g_BpT [CD*CD];
__device__ fp16  g_q_hi[NB*NQ*CD],       g_q_lo[NB*NQ*CD];
__device__ fp16  g_kv  [NB*NKV*2*CD];
__device__ float g_xsp[4][NB*NKV*CD];
__device__ fp16  g_xs_hi[NB*NKV*CD],     g_xs_lo[NB*NKV*CD];
__device__ fp16  g_o_hi[NB*NQ*CD],       g_o_lo[NB*NQ*CD];
__device__ float g_zbias[2*CD];

// ---------------------------------------------------------------------------
// helpers
// ---------------------------------------------------------------------------
__device__ __forceinline__ uint32_t smem_u32(const void* p) {
    uint32_t a;
    asm("{ .reg .u64 t; cvta.to.shared.u64 t, %1; cvt.u32.u64 %0, t; }" : "=r"(a) : "l"(p));
    return a;
}
#define SW128(o) ((o) ^ (((o) >> 3) & 0x70))

__device__ __forceinline__ void cp16(uint32_t dst, const void* src) {
    asm volatile("cp.async.cg.shared.global [%0], [%1], 16;" :: "r"(dst), "l"(src));
}
__device__ __forceinline__ void cp_commit() { asm volatile("cp.async.commit_group;"); }
template<int N> __device__ __forceinline__ void cp_wait() {
    asm volatile("cp.async.wait_group %0;" :: "n"(N));
}

__device__ __forceinline__ void ldm_x4(uint32_t addr, uint32_t* r) {
    asm volatile("ldmatrix.sync.aligned.m8n8.x4.shared.b16 {%0,%1,%2,%3}, [%4];"
        : "=r"(r[0]), "=r"(r[1]), "=r"(r[2]), "=r"(r[3]) : "r"(addr));
}
__device__ __forceinline__ void ldm_x4_t(uint32_t addr, uint32_t* r) {
    asm volatile("ldmatrix.sync.aligned.m8n8.x4.trans.shared.b16 {%0,%1,%2,%3}, [%4];"
        : "=r"(r[0]), "=r"(r[1]), "=r"(r[2]), "=r"(r[3]) : "r"(addr));
}
__device__ __forceinline__ void mma16816h(float* c, const uint32_t* a, const uint32_t* b) {
    asm volatile("mma.sync.aligned.m16n8k16.row.col.f32.f16.f16.f32 "
        "{%0,%1,%2,%3}, {%4,%5,%6,%7}, {%8,%9}, {%0,%1,%2,%3};"
        : "+f"(c[0]), "+f"(c[1]), "+f"(c[2]), "+f"(c[3])
        : "r"(a[0]), "r"(a[1]), "r"(a[2]), "r"(a[3]), "r"(b[0]), "r"(b[1]));
}

__device__ __forceinline__ void hsplit(float a, fp16& hi, fp16& lo) {
    hi = __float2half_rn(a);
    lo = __float2half_rn(a - __half2float(hi));
}
__device__ __forceinline__ uint32_t packhf(fp16 a, fp16 b) {
    __half2 h = __halves2half2(a, b);
    return *reinterpret_cast<uint32_t*>(&h);
}

// ---------------------------------------------------------------------------
// GEMM core (fp16x2): C[M,N] = (Ah+Al) @ B^T + bias
//   A: fp16 hi/lo (exact pair), B: single fp16 (weights).
//   CTA tile 128x64, BK=64, 256 threads, 8 warps (4x2), warp tile 32x32,
//   2-stage cp.async, 80 KB smem -> 2 CTAs/SM.
//   OB=0: fp32 out; OB=1: fp16 hi/lo out; OB=2: fp16 single out.
//   PERM=1: A addresses patch `pslice` of the conv permutation of g_x.
// ---------------------------------------------------------------------------
#define A_TILE_B 16384              // 128 rows x 128B
#define B_TILE_B 8192               // 64 rows x 128B
#define STAGE_B  (2 * A_TILE_B + B_TILE_B)       // 40 KB
#define GEMM_SMEM (2 * STAGE_B)                  // 80 KB

template<int OB, int PERM>
__device__ __forceinline__ void gemm_core(
    uint32_t sb,
    const fp16* __restrict__ Ah, const fp16* __restrict__ Al,
    const fp16* __restrict__ B,
    const float* __restrict__ bias, void* __restrict__ Cv, void* __restrict__ Cv2,
    int K, int ldc, int bx, int by, int pslice)
{
    int tid = threadIdx.x, wid = tid >> 5, lane = tid & 31;

    const fp16* aAh = PERM ? Ah : Ah + (size_t)by * 128 * K;
    const fp16* aAl = PERM ? Al : Al + (size_t)by * 128 * K;
    const fp16* aB  = B + (size_t)bx * 64 * K;

    auto issue = [&](int chunk, int buf) {
        int k0 = chunk << 6;
        uint32_t stg = sb + buf * STAGE_B;
        // A tiles (hi, lo): 1024 16B units each -> 4 per thread each
#pragma unroll
        for (int t = 0; t < 2; t++) {
            const fp16* src = t ? aAl : aAh;
#pragma unroll
            for (int it = 0; it < 4; it++) {
                int idx = it * 256 + tid;
                int r = idx >> 3, c16 = idx & 7;
                size_t goff;
                if (PERM) {
                    int m = by * 128 + r;
                    int bb = m >> 10, pp = m & 1023;
                    int tok = bb * NQ + ((pp >> 5) * 2 + (pslice >> 1)) * 64
                            + ((pp & 31) * 2 + (pslice & 1));
                    goff = (size_t)tok * CD + k0 + c16 * 8;
                } else {
                    goff = (size_t)r * K + k0 + c16 * 8;
                }
                cp16(stg + t * A_TILE_B + SW128(r * 128 + c16 * 16), src + goff);
            }
        }
        // B tile: 512 16B units -> 2 per thread
        {
            const fp16* src = aB + k0;
            uint32_t base = stg + 2 * A_TILE_B;
#pragma unroll
            for (int it = 0; it < 2; it++) {
                int idx = it * 256 + tid;
                int r = idx >> 3, c16 = idx & 7;
                cp16(base + SW128(r * 128 + c16 * 16),
                     src + (size_t)r * K + c16 * 8);
            }
        }
        cp_commit();
    };

    float acc[2][4][4];
#pragma unroll
    for (int i = 0; i < 2; i++)
#pragma unroll
        for (int j = 0; j < 4; j++)
#pragma unroll
            for (int e = 0; e < 4; e++) acc[i][j][e] = 0.f;

    int wm = wid >> 1, wn = wid & 1;     // 4 x 2 warp grid, 32x32 per warp
    int nch = K >> 6;

    issue(0, 0);
    for (int i = 0; i < nch; i++) {
        int buf = i & 1;
        if (i + 1 < nch) { issue(i + 1, buf ^ 1); cp_wait<1>(); }
        else             { cp_wait<0>(); }
        __syncthreads();

        uint32_t stg = sb + buf * STAGE_B;
        uint32_t aH = stg;
        uint32_t aL = stg + A_TILE_B;
        uint32_t bB = stg + 2 * A_TILE_B;

#pragma unroll
        for (int ks = 0; ks < 4; ks++) {
            int kb = ks * 32;
            uint32_t ah[2][4], al[2][4], bh[4][2];
#pragma unroll
            for (int at = 0; at < 2; at++) {
                int row = wm * 32 + at * 16 + (lane & 15);
                int colb = kb + ((lane >> 4) << 4);
                uint32_t off = SW128(row * 128 + colb);
                ldm_x4(aH + off, ah[at]);
                ldm_x4(aL + off, al[at]);
            }
#pragma unroll
            for (int bt = 0; bt < 2; bt++) {
                int row = wn * 32 + bt * 16 + ((lane >> 4) << 3) + (lane & 7);
                int colb = kb + (((lane >> 3) & 1) << 4);
                uint32_t off = SW128(row * 128 + colb);
                uint32_t t[4];
                ldm_x4(bB + off, t);
                bh[bt * 2][0] = t[0]; bh[bt * 2][1] = t[1];
                bh[bt * 2 + 1][0] = t[2]; bh[bt * 2 + 1][1] = t[3];
            }
            // two passes: hi, lo (chain-breaking layout preserved)
#pragma unroll
            for (int at = 0; at < 2; at++)
#pragma unroll
                for (int nt = 0; nt < 4; nt++)
                    mma16816h(acc[at][nt], ah[at], bh[nt]);
#pragma unroll
            for (int at = 0; at < 2; at++)
#pragma unroll
                for (int nt = 0; nt < 4; nt++)
                    mma16816h(acc[at][nt], al[at], bh[nt]);
        }
        __syncthreads();
    }

    int g = lane >> 2, tc = (lane & 3) * 2;
#pragma unroll
    for (int nt = 0; nt < 4; nt++) {
        int col = bx * 64 + wn * 32 + nt * 8 + tc;
        float b0 = bias[col], b1 = bias[col + 1];
#pragma unroll
        for (int at = 0; at < 2; at++) {
            int row0 = by * 128 + wm * 32 + at * 16 + g;
            float v00 = acc[at][nt][0] + b0, v01 = acc[at][nt][1] + b1;
            float v10 = acc[at][nt][2] + b0, v11 = acc[at][nt][3] + b1;
            if (OB == 1) {
                fp16* C  = (fp16*)Cv;
                fp16* C2 = (fp16*)Cv2;
                fp16 h0, l0, h1, l1;
                hsplit(v00, h0, l0); hsplit(v01, h1, l1);
                *(uint32_t*)(C  + (size_t)row0 * ldc + col) = packhf(h0, h1);
                *(uint32_t*)(C2 + (size_t)row0 * ldc + col) = packhf(l0, l1);
                hsplit(v10, h0, l0); hsplit(v11, h1, l1);
                *(uint32_t*)(C  + (size_t)(row0 + 8) * ldc + col) = packhf(h0, h1);
                *(uint32_t*)(C2 + (size_t)(row0 + 8) * ldc + col) = packhf(l0, l1);
            } else if (OB == 2) {
                fp16* C = (fp16*)Cv;
                *(uint32_t*)(C + (size_t)row0 * ldc + col) =
                    packhf(__float2half_rn(v00), __float2half_rn(v01));
                *(uint32_t*)(C + (size_t)(row0 + 8) * ldc + col) =
                    packhf(__float2half_rn(v10), __float2half_rn(v11));
            } else {
                float* C = (float*)Cv;
                *(float2*)(C + (size_t)row0 * ldc + col)       = make_float2(v00, v01);
                *(float2*)(C + (size_t)(row0 + 8) * ldc + col) = make_float2(v10, v11);
            }
        }
    }
}

template<int OB>
__global__ __launch_bounds__(256, 2) void gemm_fp16x2(
    const fp16* __restrict__ Ah, const fp16* __restrict__ Al,
    const fp16* __restrict__ B,
    const float* __restrict__ bias, void* __restrict__ Cv, void* __restrict__ Cv2,
    int K, int ldc)
{
    extern __shared__ char smem[];
    gemm_core<OB, 0>(smem_u32(smem), Ah, Al, B, bias, Cv, Cv2, K, ldc,
                     blockIdx.x, blockIdx.y, 0);
}

// Merged independent GEMMs: grid (8, 128).
__global__ __launch_bounds__(256, 2) void gemm_q_xs(
    const float* __restrict__ bq)
{
    extern __shared__ char smem[];
    uint32_t sb = smem_u32(smem);
    if (blockIdx.y < 64) {
        int slice = blockIdx.y >> 4, mt = blockIdx.y & 15;
        gemm_core<0, 1>(sb, g_x_hi, g_x_lo,
                        g_BsrT + (size_t)slice * CD * CD,
                        g_zbias, (void*)g_xsp[slice], nullptr,
                        CD, CD, blockIdx.x, mt, slice);
    } else {
        gemm_core<1, 0>(sb, g_x_hi, g_x_lo, g_BqT, bq,
                        (void*)g_q_hi, (void*)g_q_lo, CD, CD,
                        blockIdx.x, blockIdx.y - 64, 0);
    }
}

// ---------------------------------------------------------------------------
// Merged prep: x -> fp16 hi/lo; weights -> transposed single fp16 (+LoRA).
// ---------------------------------------------------------------------------
__global__ __launch_bounds__(256) void prep_all(
    const float* __restrict__ x,
    const float* __restrict__ Wq,   const float* __restrict__ Aq, const float* __restrict__ Bq,
    const float* __restrict__ Wkv,  const float* __restrict__ Av, const float* __restrict__ Bv,
    const float* __restrict__ Wsr,  const float* __restrict__ Wproj)
{
    if (blockIdx.x < 4096) {
        int e = blockIdx.x * 256 + threadIdx.x;
        float4 v = ((const float4*)x)[e];
        fp16 h0, l0, h1, l1, h2, l2, h3, l3;
        hsplit(v.x, h0, l0); hsplit(v.y, h1, l1);
        hsplit(v.z, h2, l2); hsplit(v.w, h3, l3);
        ((uint32_t*)g_x_hi)[e * 2]     = packhf(h0, h1);
        ((uint32_t*)g_x_hi)[e * 2 + 1] = packhf(h2, h3);
        ((uint32_t*)g_x_lo)[e * 2]     = packhf(l0, l1);
        ((uint32_t*)g_x_lo)[e * 2 + 1] = packhf(l2, l3);
        return;
    }

    __shared__ float tile[32][33];
    int t = blockIdx.x - 4096;
    const float *W, *A = nullptr, *LB = nullptr;
    fp16 *D;
    int K, stride, k0, n0;

    if (t < 256) {
        W = Wq; A = Aq; LB = Bq; D = g_BqT;
        K = 512; stride = 512; k0 = (t >> 4) * 32; n0 = (t & 15) * 32;
    } else if (t < 768) {
        int i = t - 256;
        W = Wkv; A = Av; LB = Bv; D = g_BkvT;
        K = 512; stride = 1024; k0 = (i >> 5) * 32; n0 = (i & 31) * 32;
    } else if (t < 1792) {
        int i = t - 768;
        W = Wsr;
        int kk0 = (i >> 4) * 32;
        int nn0 = (i & 15) * 32;
        int tx = threadIdx.x & 31, ty = threadIdx.x >> 5;
#pragma unroll
        for (int ii = 0; ii < 4; ii++) {
            int kk = kk0 + ty + ii * 8, n = nn0 + tx;
            tile[ty + ii * 8][tx] = W[(size_t)kk * 512 + n];
        }
        __syncthreads();
#pragma unroll
        for (int ii = 0; ii < 4; ii++) {
            int n = nn0 + ty + ii * 8, kk = kk0 + tx;
            int p = kk >> 9, k = kk & 511;
            g_BsrT[(size_t)p * CD * CD + (size_t)n * CD + k] =
                __float2half_rn(tile[tx][ty + ii * 8]);
        }
        return;
    } else {
        int i = t - 1792;
        W = Wproj; D = g_BpT;
        K = 512; stride = 512; k0 = (i >> 4) * 32; n0 = (i & 15) * 32;
    }

    int tx = threadIdx.x & 31, ty = threadIdx.x >> 5;
#pragma unroll
    for (int i = 0; i < 4; i++) {
        int k = k0 + ty + i * 8, n = n0 + tx;
        float v = W[(size_t)k * stride + n];
        if (A) {
            float l = 0.f;
#pragma unroll
            for (int r = 0; r < RLORA; r++)
                l = fmaf(A[k * RLORA + r], LB[r * CD + (n & (CD - 1))], l);
            v += l;
        }
        tile[ty + i * 8][tx] = v;
    }
    __syncthreads();
#pragma unroll
    for (int i = 0; i < 4; i++) {
        int n = n0 + ty + i * 8, k = k0 + tx;
        D[(size_t)n * K + k] = __float2half_rn(tile[tx][ty + i * 8]);
    }
}

// ---------------------------------------------------------------------------
// LayerNorm: sum split-K partials (+bsr), normalize -> fp16 hi/lo
// ---------------------------------------------------------------------------
__device__ __forceinline__ float warp_sum(float v) {
#pragma unroll
    for (int o = 16; o > 0; o >>= 1) v += __shfl_xor_sync(0xffffffffu, v, o);
    return v;
}

__global__ __launch_bounds__(256) void ln_split_kernel(const float* __restrict__ gamma,
                                                       const float* __restrict__ beta,
                                                       const float* __restrict__ bsr) {
    int row = blockIdx.x;
    size_t base = (size_t)row * CD;
    int tid = threadIdx.x;
    float a = ((g_xsp[0][base + tid]       + g_xsp[1][base + tid])
            +  (g_xsp[2][base + tid]       + g_xsp[3][base + tid])) + bsr[tid];
    float c = ((g_xsp[0][base + tid + 256] + g_xsp[1][base + tid + 256])
            +  (g_xsp[2][base + tid + 256] + g_xsp[3][base + tid + 256])) + bsr[tid + 256];

    float s  = warp_sum(a + c);
    float sq = warp_sum(a * a + c * c);
    __shared__ float sh[16];
    int w = tid >> 5, l = tid & 31;
    if (l == 0) { sh[w] = s; sh[8 + w] = sq; }
    __syncthreads();
    if (w == 0) {
        float ts = (l < 8) ? sh[l] : 0.f;
        float tq = (l < 8) ? sh[8 + l] : 0.f;
        ts = warp_sum(ts); tq = warp_sum(tq);
        if (l == 0) { sh[0] = ts; sh[1] = tq; }
    }
    __syncthreads();
    float mean = sh[0] * (1.f / CD);
    float var  = sh[1] * (1.f / CD) - mean * mean;
    float inv  = rsqrtf(var + LN_EPS);
    float y0 = (a - mean) * inv * gamma[tid] + beta[tid];
    float y1 = (c - mean) * inv * gamma[tid + 256] + beta[tid + 256];
    fp16 h, lo;
    hsplit(y0, h, lo); g_xs_hi[base + tid] = h;       g_xs_lo[base + tid] = lo;
    hsplit(y1, h, lo); g_xs_hi[base + tid + 256] = h; g_xs_lo[base + tid + 256] = lo;
}

// ---------------------------------------------------------------------------
// HMMA flash attention, fp16x2 (validated in R14); o -> fp16 hi/lo.
// grid (NQ/128, NHEAD, NB), 256 threads (8 warps x 16 q-rows), 64 KB smem.
// ---------------------------------------------------------------------------
#define ATTN_SMEM 65536

__global__ __launch_bounds__(256, 2) void attn_hmma(
    const fp16* __restrict__ qh, const fp16* __restrict__ ql,
    const fp16* __restrict__ kv)
{
    extern __shared__ char smem[];
    uint32_t sb = smem_u32(smem);
    const uint32_t QH = sb, QL = sb + 16384, ST = sb + 32768;

    int tid = threadIdx.x, lane = tid & 31, wid = tid >> 5;
    int b = blockIdx.z, h = blockIdx.y;
    int q0 = blockIdx.x * 128;

    const fp16* qgh = qh + (size_t)(b * NQ + q0) * CD + h * DH;
    const fp16* qgl = ql + (size_t)(b * NQ + q0) * CD + h * DH;
    const fp16* kg  = kv + (size_t)b * NKV * (2 * CD) + h * DH;
    const fp16* vg  = kg + CD;

#pragma unroll
    for (int it = 0; it < 4; it++) {
        int idx = it * 256 + tid;
        int r = idx >> 3, c16 = idx & 7;
        uint32_t so = SW128(r * 128 + c16 * 16);
        size_t go = (size_t)r * CD + c16 * 8;
        cp16(QH + so, qgh + go);
        cp16(QL + so, qgl + go);
    }
    cp_commit();

    auto issue_kv = [&](int t, int bufi) {
        int m0 = t * 64;
        uint32_t SBB = ST + bufi * 16384;
#pragma unroll
        for (int it = 0; it < 2; it++) {
            int idx = it * 256 + tid;
            int r = idx >> 3, c16 = idx & 7;
            size_t go = (size_t)(m0 + r) * (2 * CD) + c16 * 8;
            uint32_t so = SW128(r * 128 + c16 * 16);
            cp16(SBB + so,        kg + go);
            cp16(SBB + 8192 + so, vg + go);
        }
        cp_commit();
    };

    issue_kv(0, 0);
    cp_wait<1>();
    __syncthreads();

    float o[8][4];
#pragma unroll
    for (int nt = 0; nt < 8; nt++)
#pragma unroll
        for (int e = 0; e < 4; e++) o[nt][e] = 0.f;
    float rs0 = 0.f, rs1 = 0.f;

    const float SC = 0.125f;
    int qrow = wid * 16 + (lane & 15);
    int qcolb = (lane >> 4) << 4;

    for (int t = 0; t < 16; t++) {
        int bufi = t & 1;
        if (t + 1 < 16) { issue_kv(t + 1, bufi ^ 1); cp_wait<1>(); }
        else            { cp_wait<0>(); }
        __syncthreads();

        uint32_t SBB = ST + bufi * 16384;

        float s[8][4];
#pragma unroll
        for (int nt = 0; nt < 8; nt++)
#pragma unroll
            for (int e = 0; e < 4; e++) s[nt][e] = 0.f;

#pragma unroll
        for (int ks = 0; ks < 4; ks++) {
            uint32_t aqh[4], aql[4];
            {
                uint32_t off = SW128(qrow * 128 + ks * 32 + qcolb);
                ldm_x4(QH + off, aqh);
                ldm_x4(QL + off, aql);
            }
            uint32_t bh[8][2];
#pragma unroll
            for (int bt = 0; bt < 4; bt++) {
                int row = bt * 16 + ((lane >> 4) << 3) + (lane & 7);
                int colb = ks * 32 + (((lane >> 3) & 1) << 4);
                uint32_t off = SW128(row * 128 + colb);
                uint32_t tr[4];
                ldm_x4(SBB + off, tr);
                bh[bt * 2][0] = tr[0];     bh[bt * 2][1] = tr[1];
                bh[bt * 2 + 1][0] = tr[2]; bh[bt * 2 + 1][1] = tr[3];
            }
#pragma unroll
            for (int nt = 0; nt < 8; nt++)
                mma16816h(s[nt], aqh, bh[nt]);
#pragma unroll
            for (int nt = 0; nt < 8; nt++)
                mma16816h(s[nt], aql, bh[nt]);
        }

        uint32_t pah[4][4], pal[4][4];
#pragma unroll
        for (int nt = 0; nt < 8; nt++) {
            float p0 = __expf(s[nt][0] * SC);
            float p1 = __expf(s[nt][1] * SC);
            float p2 = __expf(s[nt][2] * SC);
            float p3 = __expf(s[nt][3] * SC);
            rs0 += p0 + p1;
            rs1 += p2 + p3;
            fp16 h0, l0, h1, l1, h2, l2, h3, l3;
            hsplit(p0, h0, l0); hsplit(p1, h1, l1);
            hsplit(p2, h2, l2); hsplit(p3, h3, l3);
            int j = nt >> 1, half = nt & 1;
            pah[j][half * 2]     = packhf(h0, h1);
            pah[j][half * 2 + 1] = packhf(h2, h3);
            pal[j][half * 2]     = packhf(l0, l1);
            pal[j][half * 2 + 1] = packhf(l2, l3);
        }

#pragma unroll
        for (int j = 0; j < 4; j++) {
            uint32_t vbh[8][2];
#pragma unroll
            for (int nh = 0; nh < 4; nh++) {
                int row = j * 16 + (lane & 15);
                int colb = nh * 32 + ((lane >> 4) << 4);
                uint32_t off = SW128(row * 128 + colb);
                uint32_t tr[4];
                ldm_x4_t(SBB + 8192 + off, tr);
                vbh[nh * 2][0] = tr[0];     vbh[nh * 2][1] = tr[1];
                vbh[nh * 2 + 1][0] = tr[2]; vbh[nh * 2 + 1][1] = tr[3];
            }
#pragma unroll
            for (int nt = 0; nt < 8; nt++)
                mma16816h(o[nt], pah[j], vbh[nt]);
#pragma unroll
            for (int nt = 0; nt < 8; nt++)
                mma16816h(o[nt], pal[j], vbh[nt]);
        }
        __syncthreads();
    }

    rs0 += __shfl_xor_sync(0xffffffffu, rs0, 1);
    rs0 += __shfl_xor_sync(0xffffffffu, rs0, 2);
    rs1 += __shfl_xor_sync(0xffffffffu, rs1, 1);
    rs1 += __shfl_xor_sync(0xffffffffu, rs1, 2);

    int g = lane >> 2, tc = (lane & 3) * 2;
    int row0 = q0 + wid * 16 + g;
    float i0 = 1.f / rs0, i1 = 1.f / rs1;
#pragma unroll
    for (int nt = 0; nt < 8; nt++) {
        int col = h * DH + nt * 8 + tc;
        size_t off0 = (size_t)(b * NQ + row0) * CD + col;
        size_t off1 = off0 + (size_t)8 * CD;
        float v0 = o[nt][0] * i0, v1 = o[nt][1] * i0;
        float v2 = o[nt][2] * i1, v3 = o[nt][3] * i1;
        fp16 h0, l0, h1, l1;
        hsplit(v0, h0, l0); hsplit(v1, h1, l1);
        *(uint32_t*)(g_o_hi + off0) = packhf(h0, h1);
        *(uint32_t*)(g_o_lo + off0) = packhf(l0, l1);
        hsplit(v2, h0, l0); hsplit(v3, h1, l1);
        *(uint32_t*)(g_o_hi + off1) = packhf(h0, h1);
        *(uint32_t*)(g_o_lo + off1) = packhf(l0, l1);
    }
}

// ---------------------------------------------------------------------------
// kernel_launch
// ---------------------------------------------------------------------------
extern "C" void kernel_launch(void* const* d_in, const int* in_sizes, int n_in,
                              void* d_out, int out_size) {
    const float* x     = (const float*)d_in[0];
    const float* Wq    = (const float*)d_in[1];
    const float* bq    = (const float*)d_in[2];
    const float* Wkv   = (const float*)d_in[3];
    const float* bkv   = (const float*)d_in[4];
    const float* Wproj = (const float*)d_in[5];
    const float* bproj = (const float*)d_in[6];
    const float* Aq    = (const float*)d_in[7];
    const float* Bq    = (const float*)d_in[8];
    const float* Av    = (const float*)d_in[9];
    const float* Bv    = (const float*)d_in[10];
    const float* Wsr   = (const float*)d_in[11];
    const float* bsr   = (const float*)d_in[12];
    const float* gamma = (const float*)d_in[13];
    const float* beta  = (const float*)d_in[14];
    float* outp = (float*)d_out;

    fp16 *xsh, *xsl, *oh, *ol, *pqh, *pql, *pkv, *bkvT, *bpT;
    cudaGetSymbolAddress((void**)&bkvT, g_BkvT);
    cudaGetSymbolAddress((void**)&bpT,  g_BpT);
    cudaGetSymbolAddress((void**)&xsh,  g_xs_hi);  cudaGetSymbolAddress((void**)&xsl,  g_xs_lo);
    cudaGetSymbolAddress((void**)&oh,   g_o_hi);   cudaGetSymbolAddress((void**)&ol,   g_o_lo);
    cudaGetSymbolAddress((void**)&pqh,  g_q_hi);   cudaGetSymbolAddress((void**)&pql,  g_q_lo);
    cudaGetSymbolAddress((void**)&pkv,  g_kv);

    cudaFuncSetAttribute(gemm_fp16x2<0>, cudaFuncAttributeMaxDynamicSharedMemorySize, GEMM_SMEM);
    cudaFuncSetAttribute(gemm_fp16x2<2>, cudaFuncAttributeMaxDynamicSharedMemorySize, GEMM_SMEM);
    cudaFuncSetAttribute(gemm_q_xs, cudaFuncAttributeMaxDynamicSharedMemorySize, GEMM_SMEM);
    cudaFuncSetAttribute(attn_hmma, cudaFuncAttributeMaxDynamicSharedMemorySize, ATTN_SMEM);

    // 1) merged prep: split x (fp16 hi/lo) + weights (single fp16, +LoRA)
    prep_all<<<6144, 256>>>(x, Wq, Aq, Bq, Wkv, Av, Bv, Wsr, Wproj);

    // 2) merged: xs split-K partial GEMMs (4 slices) + q GEMM (fp16 hi/lo out)
    gemm_q_xs<<<dim3(8, 128), 256, GEMM_SMEM>>>(bq);

    // 3) LayerNorm (sums split-K partials + bsr) -> fp16 hi/lo
    ln_split_kernel<<<NB * NKV, 256>>>(gamma, beta, bsr);

    // 4) kv GEMM (2048 x 1024, K=512), fp16 single out
    gemm_fp16x2<2><<<dim3(16, 16), 256, GEMM_SMEM>>>(
        xsh, xsl, bkvT, bkv, pkv, nullptr, CD, 2 * CD);

    // 5) attention (fp16x2 HMMA) -> fp16 hi/lo
    attn_hmma<<<dim3(NQ / 128, NHEAD, NB), 256, ATTN_SMEM>>>(pqh, pql, pkv);

    // 6) out GEMM -> d_out (fp32)
    gemm_fp16x2<0><<<dim3(8, 64), 256, GEMM_SMEM>>>(
        oh, ol, bpT, bproj, outp, nullptr, CD, CD);
}

// round 16
// speedup vs baseline: 2.1709x; 1.2200x over previous
#include <cuda_runtime.h>
#include <cuda_bf16.h>
#include <cuda_fp16.h>
#include <cstdint>
#include <math.h>

#define NB    2
#define NQ    4096
#define NKV   1024
#define CD    512
#define NHEAD 8
#define DH    64
#define RLORA 8
#define LN_EPS 1e-5f

typedef __half fp16;

// ---------------------------------------------------------------------------
// Device scratch
// ---------------------------------------------------------------------------
__device__ fp16  g_x_hi [NB*NQ*CD],      g_x_lo [NB*NQ*CD];
__device__ fp16  g_BqT [CD*CD];
__device__ fp16  g_BkvT[2*CD*CD];
__device__ fp16  g_BsrT[CD*4*CD];        // slice-blocked: [p][n][k]
__device__ fp16  g_BpT [CD*CD];
__device__ fp16  g_q   [NB*NQ*CD];       // q: single fp16 (softmax-damped)
__device__ fp16  g_kv  [NB*NKV*2*CD];
__device__ float g_xsp[4][NB*NKV*CD];
__device__ fp16  g_xs_hi[NB*NKV*CD],     g_xs_lo[NB*NKV*CD];
__device__ fp16  g_o_hi[NB*NQ*CD],       g_o_lo[NB*NQ*CD];
__device__ float g_zbias[2*CD];

// ---------------------------------------------------------------------------
// helpers
// ---------------------------------------------------------------------------
__device__ __forceinline__ uint32_t smem_u32(const void* p) {
    uint32_t a;
    asm("{ .reg .u64 t; cvta.to.shared.u64 t, %1; cvt.u32.u64 %0, t; }" : "=r"(a) : "l"(p));
    return a;
}
#define SW128(o) ((o) ^ (((o) >> 3) & 0x70))

__device__ __forceinline__ void cp16(uint32_t dst, const void* src) {
    asm volatile("cp.async.cg.shared.global [%0], [%1], 16;" :: "r"(dst), "l"(src));
}
__device__ __forceinline__ void cp_commit() { asm volatile("cp.async.commit_group;"); }
template<int N> __device__ __forceinline__ void cp_wait() {
    asm volatile("cp.async.wait_group %0;" :: "n"(N));
}

__device__ __forceinline__ void ldm_x4(uint32_t addr, uint32_t* r) {
    asm volatile("ldmatrix.sync.aligned.m8n8.x4.shared.b16 {%0,%1,%2,%3}, [%4];"
        : "=r"(r[0]), "=r"(r[1]), "=r"(r[2]), "=r"(r[3]) : "r"(addr));
}
__device__ __forceinline__ void ldm_x4_t(uint32_t addr, uint32_t* r) {
    asm volatile("ldmatrix.sync.aligned.m8n8.x4.trans.shared.b16 {%0,%1,%2,%3}, [%4];"
        : "=r"(r[0]), "=r"(r[1]), "=r"(r[2]), "=r"(r[3]) : "r"(addr));
}
__device__ __forceinline__ void mma16816h(float* c, const uint32_t* a, const uint32_t* b) {
    asm volatile("mma.sync.aligned.m16n8k16.row.col.f32.f16.f16.f32 "
        "{%0,%1,%2,%3}, {%4,%5,%6,%7}, {%8,%9}, {%0,%1,%2,%3};"
        : "+f"(c[0]), "+f"(c[1]), "+f"(c[2]), "+f"(c[3])
        : "r"(a[0]), "r"(a[1]), "r"(a[2]), "r"(a[3]), "r"(b[0]), "r"(b[1]));
}

__device__ __forceinline__ void hsplit(float a, fp16& hi, fp16& lo) {
    hi = __float2half_rn(a);
    lo = __float2half_rn(a - __half2float(hi));
}
__device__ __forceinline__ uint32_t packhf(fp16 a, fp16 b) {
    __half2 h = __halves2half2(a, b);
    return *reinterpret_cast<uint32_t*>(&h);
}

// ---------------------------------------------------------------------------
// GEMM core (fp16x2): C[M,N] = (Ah+Al) @ B^T + bias
//   A: fp16 hi/lo pair, B: single fp16 weights.
//   CTA tile 128x64, BK=64, 256 threads, 8 warps (4x2), warp tile 32x32,
//   2-stage cp.async, 80 KB smem -> 2 CTAs/SM.
//   OB=0: fp32 out; OB=1: fp16 hi/lo out; OB=2: fp16 single out.
//   PERM=1: A addresses patch `pslice` of the conv permutation of g_x.
// ---------------------------------------------------------------------------
#define A_TILE_B 16384
#define B_TILE_B 8192
#define STAGE_B  (2 * A_TILE_B + B_TILE_B)       // 40 KB
#define GEMM_SMEM (2 * STAGE_B)                  // 80 KB

template<int OB, int PERM>
__device__ __forceinline__ void gemm_core(
    uint32_t sb,
    const fp16* __restrict__ Ah, const fp16* __restrict__ Al,
    const fp16* __restrict__ B,
    const float* __restrict__ bias, void* __restrict__ Cv, void* __restrict__ Cv2,
    int K, int ldc, int bx, int by, int pslice)
{
    int tid = threadIdx.x, wid = tid >> 5, lane = tid & 31;

    const fp16* aAh = PERM ? Ah : Ah + (size_t)by * 128 * K;
    const fp16* aAl = PERM ? Al : Al + (size_t)by * 128 * K;
    const fp16* aB  = B + (size_t)bx * 64 * K;

    auto issue = [&](int chunk, int buf) {
        int k0 = chunk << 6;
        uint32_t stg = sb + buf * STAGE_B;
#pragma unroll
        for (int t = 0; t < 2; t++) {
            const fp16* src = t ? aAl : aAh;
#pragma unroll
            for (int it = 0; it < 4; it++) {
                int idx = it * 256 + tid;
                int r = idx >> 3, c16 = idx & 7;
                size_t goff;
                if (PERM) {
                    int m = by * 128 + r;
                    int bb = m >> 10, pp = m & 1023;
                    int tok = bb * NQ + ((pp >> 5) * 2 + (pslice >> 1)) * 64
                            + ((pp & 31) * 2 + (pslice & 1));
                    goff = (size_t)tok * CD + k0 + c16 * 8;
                } else {
                    goff = (size_t)r * K + k0 + c16 * 8;
                }
                cp16(stg + t * A_TILE_B + SW128(r * 128 + c16 * 16), src + goff);
            }
        }
        {
            const fp16* src = aB + k0;
            uint32_t base = stg + 2 * A_TILE_B;
#pragma unroll
            for (int it = 0; it < 2; it++) {
                int idx = it * 256 + tid;
                int r = idx >> 3, c16 = idx & 7;
                cp16(base + SW128(r * 128 + c16 * 16),
                     src + (size_t)r * K + c16 * 8);
            }
        }
        cp_commit();
    };

    float acc[2][4][4];
#pragma unroll
    for (int i = 0; i < 2; i++)
#pragma unroll
        for (int j = 0; j < 4; j++)
#pragma unroll
            for (int e = 0; e < 4; e++) acc[i][j][e] = 0.f;

    int wm = wid >> 1, wn = wid & 1;
    int nch = K >> 6;

    issue(0, 0);
    for (int i = 0; i < nch; i++) {
        int buf = i & 1;
        if (i + 1 < nch) { issue(i + 1, buf ^ 1); cp_wait<1>(); }
        else             { cp_wait<0>(); }
        __syncthreads();

        uint32_t stg = sb + buf * STAGE_B;
        uint32_t aH = stg;
        uint32_t aL = stg + A_TILE_B;
        uint32_t bB = stg + 2 * A_TILE_B;

#pragma unroll
        for (int ks = 0; ks < 4; ks++) {
            int kb = ks * 32;
            uint32_t ah[2][4], al[2][4], bh[4][2];
#pragma unroll
            for (int at = 0; at < 2; at++) {
                int row = wm * 32 + at * 16 + (lane & 15);
                int colb = kb + ((lane >> 4) << 4);
                uint32_t off = SW128(row * 128 + colb);
                ldm_x4(aH + off, ah[at]);
                ldm_x4(aL + off, al[at]);
            }
#pragma unroll
            for (int bt = 0; bt < 2; bt++) {
                int row = wn * 32 + bt * 16 + ((lane >> 4) << 3) + (lane & 7);
                int colb = kb + (((lane >> 3) & 1) << 4);
                uint32_t off = SW128(row * 128 + colb);
                uint32_t t[4];
                ldm_x4(bB + off, t);
                bh[bt * 2][0] = t[0]; bh[bt * 2][1] = t[1];
                bh[bt * 2 + 1][0] = t[2]; bh[bt * 2 + 1][1] = t[3];
            }
#pragma unroll
            for (int at = 0; at < 2; at++)
#pragma unroll
                for (int nt = 0; nt < 4; nt++)
                    mma16816h(acc[at][nt], ah[at], bh[nt]);
#pragma unroll
            for (int at = 0; at < 2; at++)
#pragma unroll
                for (int nt = 0; nt < 4; nt++)
                    mma16816h(acc[at][nt], al[at], bh[nt]);
        }
        __syncthreads();
    }

    int g = lane >> 2, tc = (lane & 3) * 2;
#pragma unroll
    for (int nt = 0; nt < 4; nt++) {
        int col = bx * 64 + wn * 32 + nt * 8 + tc;
        float b0 = bias[col], b1 = bias[col + 1];
#pragma unroll
        for (int at = 0; at < 2; at++) {
            int row0 = by * 128 + wm * 32 + at * 16 + g;
            float v00 = acc[at][nt][0] + b0, v01 = acc[at][nt][1] + b1;
            float v10 = acc[at][nt][2] + b0, v11 = acc[at][nt][3] + b1;
            if (OB == 1) {
                fp16* C  = (fp16*)Cv;
                fp16* C2 = (fp16*)Cv2;
                fp16 h0, l0, h1, l1;
                hsplit(v00, h0, l0); hsplit(v01, h1, l1);
                *(uint32_t*)(C  + (size_t)row0 * ldc + col) = packhf(h0, h1);
                *(uint32_t*)(C2 + (size_t)row0 * ldc + col) = packhf(l0, l1);
                hsplit(v10, h0, l0); hsplit(v11, h1, l1);
                *(uint32_t*)(C  + (size_t)(row0 + 8) * ldc + col) = packhf(h0, h1);
                *(uint32_t*)(C2 + (size_t)(row0 + 8) * ldc + col) = packhf(l0, l1);
            } else if (OB == 2) {
                fp16* C = (fp16*)Cv;
                *(uint32_t*)(C + (size_t)row0 * ldc + col) =
                    packhf(__float2half_rn(v00), __float2half_rn(v01));
                *(uint32_t*)(C + (size_t)(row0 + 8) * ldc + col) =
                    packhf(__float2half_rn(v10), __float2half_rn(v11));
            } else {
                float* C = (float*)Cv;
                *(float2*)(C + (size_t)row0 * ldc + col)       = make_float2(v00, v01);
                *(float2*)(C + (size_t)(row0 + 8) * ldc + col) = make_float2(v10, v11);
            }
        }
    }
}

template<int OB>
__global__ __launch_bounds__(256, 2) void gemm_fp16x2(
    const fp16* __restrict__ Ah, const fp16* __restrict__ Al,
    const fp16* __restrict__ B,
    const float* __restrict__ bias, void* __restrict__ Cv, void* __restrict__ Cv2,
    int K, int ldc)
{
    extern __shared__ char smem[];
    gemm_core<OB, 0>(smem_u32(smem), Ah, Al, B, bias, Cv, Cv2, K, ldc,
                     blockIdx.x, blockIdx.y, 0);
}

// Merged independent GEMMs: grid (8, 128).
//  by in [0,64):   xs partial (slice = by>>4, m-tile = by&15)
//  by in [64,128): q  (single fp16 out)
__global__ __launch_bounds__(256, 2) void gemm_q_xs(
    const float* __restrict__ bq)
{
    extern __shared__ char smem[];
    uint32_t sb = smem_u32(smem);
    if (blockIdx.y < 64) {
        int slice = blockIdx.y >> 4, mt = blockIdx.y & 15;
        gemm_core<0, 1>(sb, g_x_hi, g_x_lo,
                        g_BsrT + (size_t)slice * CD * CD,
                        g_zbias, (void*)g_xsp[slice], nullptr,
                        CD, CD, blockIdx.x, mt, slice);
    } else {
        gemm_core<2, 0>(sb, g_x_hi, g_x_lo, g_BqT, bq,
                        (void*)g_q, nullptr, CD, CD,
                        blockIdx.x, blockIdx.y - 64, 0);
    }
}

// ---------------------------------------------------------------------------
// Merged prep (unchanged from R15)
// ---------------------------------------------------------------------------
__global__ __launch_bounds__(256) void prep_all(
    const float* __restrict__ x,
    const float* __restrict__ Wq,   const float* __restrict__ Aq, const float* __restrict__ Bq,
    const float* __restrict__ Wkv,  const float* __restrict__ Av, const float* __restrict__ Bv,
    const float* __restrict__ Wsr,  const float* __restrict__ Wproj)
{
    if (blockIdx.x < 4096) {
        int e = blockIdx.x * 256 + threadIdx.x;
        float4 v = ((const float4*)x)[e];
        fp16 h0, l0, h1, l1, h2, l2, h3, l3;
        hsplit(v.x, h0, l0); hsplit(v.y, h1, l1);
        hsplit(v.z, h2, l2); hsplit(v.w, h3, l3);
        ((uint32_t*)g_x_hi)[e * 2]     = packhf(h0, h1);
        ((uint32_t*)g_x_hi)[e * 2 + 1] = packhf(h2, h3);
        ((uint32_t*)g_x_lo)[e * 2]     = packhf(l0, l1);
        ((uint32_t*)g_x_lo)[e * 2 + 1] = packhf(l2, l3);
        return;
    }

    __shared__ float tile[32][33];
    int t = blockIdx.x - 4096;
    const float *W, *A = nullptr, *LB = nullptr;
    fp16 *D;
    int K, stride, k0, n0;

    if (t < 256) {
        W = Wq; A = Aq; LB = Bq; D = g_BqT;
        K = 512; stride = 512; k0 = (t >> 4) * 32; n0 = (t & 15) * 32;
    } else if (t < 768) {
        int i = t - 256;
        W = Wkv; A = Av; LB = Bv; D = g_BkvT;
        K = 512; stride = 1024; k0 = (i >> 5) * 32; n0 = (i & 31) * 32;
    } else if (t < 1792) {
        int i = t - 768;
        W = Wsr;
        int kk0 = (i >> 4) * 32;
        int nn0 = (i & 15) * 32;
        int tx = threadIdx.x & 31, ty = threadIdx.x >> 5;
#pragma unroll
        for (int ii = 0; ii < 4; ii++) {
            int kk = kk0 + ty + ii * 8, n = nn0 + tx;
            tile[ty + ii * 8][tx] = W[(size_t)kk * 512 + n];
        }
        __syncthreads();
#pragma unroll
        for (int ii = 0; ii < 4; ii++) {
            int n = nn0 + ty + ii * 8, kk = kk0 + tx;
            int p = kk >> 9, k = kk & 511;
            g_BsrT[(size_t)p * CD * CD + (size_t)n * CD + k] =
                __float2half_rn(tile[tx][ty + ii * 8]);
        }
        return;
    } else {
        int i = t - 1792;
        W = Wproj; D = g_BpT;
        K = 512; stride = 512; k0 = (i >> 4) * 32; n0 = (i & 15) * 32;
    }

    int tx = threadIdx.x & 31, ty = threadIdx.x >> 5;
#pragma unroll
    for (int i = 0; i < 4; i++) {
        int k = k0 + ty + i * 8, n = n0 + tx;
        float v = W[(size_t)k * stride + n];
        if (A) {
            float l = 0.f;
#pragma unroll
            for (int r = 0; r < RLORA; r++)
                l = fmaf(A[k * RLORA + r], LB[r * CD + (n & (CD - 1))], l);
            v += l;
        }
        tile[ty + i * 8][tx] = v;
    }
    __syncthreads();
#pragma unroll
    for (int i = 0; i < 4; i++) {
        int n = n0 + ty + i * 8, k = k0 + tx;
        D[(size_t)n * K + k] = __float2half_rn(tile[tx][ty + i * 8]);
    }
}

// ---------------------------------------------------------------------------
// LayerNorm (unchanged from R15)
// ---------------------------------------------------------------------------
__device__ __forceinline__ float warp_sum(float v) {
#pragma unroll
    for (int o = 16; o > 0; o >>= 1) v += __shfl_xor_sync(0xffffffffu, v, o);
    return v;
}

__global__ __launch_bounds__(256) void ln_split_kernel(const float* __restrict__ gamma,
                                                       const float* __restrict__ beta,
                                                       const float* __restrict__ bsr) {
    int row = blockIdx.x;
    size_t base = (size_t)row * CD;
    int tid = threadIdx.x;
    float a = ((g_xsp[0][base + tid]       + g_xsp[1][base + tid])
            +  (g_xsp[2][base + tid]       + g_xsp[3][base + tid])) + bsr[tid];
    float c = ((g_xsp[0][base + tid + 256] + g_xsp[1][base + tid + 256])
            +  (g_xsp[2][base + tid + 256] + g_xsp[3][base + tid + 256])) + bsr[tid + 256];

    float s  = warp_sum(a + c);
    float sq = warp_sum(a * a + c * c);
    __shared__ float sh[16];
    int w = tid >> 5, l = tid & 31;
    if (l == 0) { sh[w] = s; sh[8 + w] = sq; }
    __syncthreads();
    if (w == 0) {
        float ts = (l < 8) ? sh[l] : 0.f;
        float tq = (l < 8) ? sh[8 + l] : 0.f;
        ts = warp_sum(ts); tq = warp_sum(tq);
        if (l == 0) { sh[0] = ts; sh[1] = tq; }
    }
    __syncthreads();
    float mean = sh[0] * (1.f / CD);
    float var  = sh[1] * (1.f / CD) - mean * mean;
    float inv  = rsqrtf(var + LN_EPS);
    float y0 = (a - mean) * inv * gamma[tid] + beta[tid];
    float y1 = (c - mean) * inv * gamma[tid + 256] + beta[tid + 256];
    fp16 h, lo;
    hsplit(y0, h, lo); g_xs_hi[base + tid] = h;       g_xs_lo[base + tid] = lo;
    hsplit(y1, h, lo); g_xs_hi[base + tid + 256] = h; g_xs_lo[base + tid + 256] = lo;
}

// ---------------------------------------------------------------------------
// HMMA flash attention, fully single-fp16 operands:
//   S = q . k     (1 pass; q,k single fp16 -- softmax-damped errors)
//   O = p . v     (1 pass; p,v single fp16 -- each ~2.4e-4, undamped)
// fp32 exp/rowsum/accum. o emitted as fp16 hi/lo for the out-proj.
// grid (NQ/128, NHEAD, NB), 256 threads (8 warps x 16 q-rows), 48 KB smem.
// ---------------------------------------------------------------------------
#define ATTN_SMEM 49152   // Q 16KB + 2 x (k 8KB + v 8KB)

__global__ __launch_bounds__(256, 2) void attn_hmma(
    const fp16* __restrict__ q, const fp16* __restrict__ kv)
{
    extern __shared__ char smem[];
    uint32_t sb = smem_u32(smem);
    const uint32_t QS = sb, ST = sb + 16384;

    int tid = threadIdx.x, lane = tid & 31, wid = tid >> 5;
    int b = blockIdx.z, h = blockIdx.y;
    int q0 = blockIdx.x * 128;

    const fp16* qg = q + (size_t)(b * NQ + q0) * CD + h * DH;
    const fp16* kg = kv + (size_t)b * NKV * (2 * CD) + h * DH;
    const fp16* vg = kg + CD;

#pragma unroll
    for (int it = 0; it < 4; it++) {
        int idx = it * 256 + tid;
        int r = idx >> 3, c16 = idx & 7;
        cp16(QS + SW128(r * 128 + c16 * 16), qg + (size_t)r * CD + c16 * 8);
    }
    cp_commit();

    auto issue_kv = [&](int t, int bufi) {
        int m0 = t * 64;
        uint32_t SBB = ST + bufi * 16384;
#pragma unroll
        for (int it = 0; it < 2; it++) {
            int idx = it * 256 + tid;
            int r = idx >> 3, c16 = idx & 7;
            size_t go = (size_t)(m0 + r) * (2 * CD) + c16 * 8;
            uint32_t so = SW128(r * 128 + c16 * 16);
            cp16(SBB + so,        kg + go);
            cp16(SBB + 8192 + so, vg + go);
        }
        cp_commit();
    };

    issue_kv(0, 0);
    cp_wait<1>();
    __syncthreads();

    float o[8][4];
#pragma unroll
    for (int nt = 0; nt < 8; nt++)
#pragma unroll
        for (int e = 0; e < 4; e++) o[nt][e] = 0.f;
    float rs0 = 0.f, rs1 = 0.f;

    const float SC = 0.125f;
    int qrow = wid * 16 + (lane & 15);
    int qcolb = (lane >> 4) << 4;

    for (int t = 0; t < 16; t++) {
        int bufi = t & 1;
        if (t + 1 < 16) { issue_kv(t + 1, bufi ^ 1); cp_wait<1>(); }
        else            { cp_wait<0>(); }
        __syncthreads();

        uint32_t SBB = ST + bufi * 16384;

        float s[8][4];
#pragma unroll
        for (int nt = 0; nt < 8; nt++)
#pragma unroll
            for (int e = 0; e < 4; e++) s[nt][e] = 0.f;

#pragma unroll
        for (int ks = 0; ks < 4; ks++) {
            uint32_t aq[4];
            ldm_x4(QS + SW128(qrow * 128 + ks * 32 + qcolb), aq);
            uint32_t bh[8][2];
#pragma unroll
            for (int bt = 0; bt < 4; bt++) {
                int row = bt * 16 + ((lane >> 4) << 3) + (lane & 7);
                int colb = ks * 32 + (((lane >> 3) & 1) << 4);
                uint32_t off = SW128(row * 128 + colb);
                uint32_t tr[4];
                ldm_x4(SBB + off, tr);
                bh[bt * 2][0] = tr[0];     bh[bt * 2][1] = tr[1];
                bh[bt * 2 + 1][0] = tr[2]; bh[bt * 2 + 1][1] = tr[3];
            }
#pragma unroll
            for (int nt = 0; nt < 8; nt++)
                mma16816h(s[nt], aq, bh[nt]);
        }

        uint32_t pa[4][4];
#pragma unroll
        for (int nt = 0; nt < 8; nt++) {
            float p0 = __expf(s[nt][0] * SC);
            float p1 = __expf(s[nt][1] * SC);
            float p2 = __expf(s[nt][2] * SC);
            float p3 = __expf(s[nt][3] * SC);
            rs0 += p0 + p1;
            rs1 += p2 + p3;
            int j = nt >> 1, half = nt & 1;
            pa[j][half * 2]     = packhf(__float2half_rn(p0), __float2half_rn(p1));
            pa[j][half * 2 + 1] = packhf(__float2half_rn(p2), __float2half_rn(p3));
        }

#pragma unroll
        for (int j = 0; j < 4; j++) {
            uint32_t vb[8][2];
#pragma unroll
            for (int nh = 0; nh < 4; nh++) {
                int row = j * 16 + (lane & 15);
                int colb = nh * 32 + ((lane >> 4) << 4);
                uint32_t off = SW128(row * 128 + colb);
                uint32_t tr[4];
                ldm_x4_t(SBB + 8192 + off, tr);
                vb[nh * 2][0] = tr[0];     vb[nh * 2][1] = tr[1];
                vb[nh * 2 + 1][0] = tr[2]; vb[nh * 2 + 1][1] = tr[3];
            }
#pragma unroll
            for (int nt = 0; nt < 8; nt++)
                mma16816h(o[nt], pa[j], vb[nt]);
        }
        __syncthreads();
    }

    rs0 += __shfl_xor_sync(0xffffffffu, rs0, 1);
    rs0 += __shfl_xor_sync(0xffffffffu, rs0, 2);
    rs1 += __shfl_xor_sync(0xffffffffu, rs1, 1);
    rs1 += __shfl_xor_sync(0xffffffffu, rs1, 2);

    int g = lane >> 2, tc = (lane & 3) * 2;
    int row0 = q0 + wid * 16 + g;
    float i0 = 1.f / rs0, i1 = 1.f / rs1;
#pragma unroll
    for (int nt = 0; nt < 8; nt++) {
        int col = h * DH + nt * 8 + tc;
        size_t off0 = (size_t)(b * NQ + row0) * CD + col;
        size_t off1 = off0 + (size_t)8 * CD;
        float v0 = o[nt][0] * i0, v1 = o[nt][1] * i0;
        float v2 = o[nt][2] * i1, v3 = o[nt][3] * i1;
        fp16 h0, l0, h1, l1;
        hsplit(v0, h0, l0); hsplit(v1, h1, l1);
        *(uint32_t*)(g_o_hi + off0) = packhf(h0, h1);
        *(uint32_t*)(g_o_lo + off0) = packhf(l0, l1);
        hsplit(v2, h0, l0); hsplit(v3, h1, l1);
        *(uint32_t*)(g_o_hi + off1) = packhf(h0, h1);
        *(uint32_t*)(g_o_lo + off1) = packhf(l0, l1);
    }
}

// ---------------------------------------------------------------------------
// kernel_launch
// ---------------------------------------------------------------------------
extern "C" void kernel_launch(void* const* d_in, const int* in_sizes, int n_in,
                              void* d_out, int out_size) {
    const float* x     = (const float*)d_in[0];
    const float* Wq    = (const float*)d_in[1];
    const float* bq    = (const float*)d_in[2];
    const float* Wkv   = (const float*)d_in[3];
    const float* bkv   = (const float*)d_in[4];
    const float* Wproj = (const float*)d_in[5];
    const float* bproj = (const float*)d_in[6];
    const float* Aq    = (const float*)d_in[7];
    const float* Bq    = (const float*)d_in[8];
    const float* Av    = (const float*)d_in[9];
    const float* Bv    = (const float*)d_in[10];
    const float* Wsr   = (const float*)d_in[11];
    const float* bsr   = (const float*)d_in[12];
    const float* gamma = (const float*)d_in[13];
    const float* beta  = (const float*)d_in[14];
    float* outp = (float*)d_out;

    fp16 *xsh, *xsl, *oh, *ol, *pq, *pkv, *bkvT, *bpT;
    cudaGetSymbolAddress((void**)&bkvT, g_BkvT);
    cudaGetSymbolAddress((void**)&bpT,  g_BpT);
    cudaGetSymbolAddress((void**)&xsh,  g_xs_hi);  cudaGetSymbolAddress((void**)&xsl,  g_xs_lo);
    cudaGetSymbolAddress((void**)&oh,   g_o_hi);   cudaGetSymbolAddress((void**)&ol,   g_o_lo);
    cudaGetSymbolAddress((void**)&pq,   g_q);
    cudaGetSymbolAddress((void**)&pkv,  g_kv);

    cudaFuncSetAttribute(gemm_fp16x2<0>, cudaFuncAttributeMaxDynamicSharedMemorySize, GEMM_SMEM);
    cudaFuncSetAttribute(gemm_fp16x2<2>, cudaFuncAttributeMaxDynamicSharedMemorySize, GEMM_SMEM);
    cudaFuncSetAttribute(gemm_q_xs, cudaFuncAttributeMaxDynamicSharedMemorySize, GEMM_SMEM);
    cudaFuncSetAttribute(attn_hmma, cudaFuncAttributeMaxDynamicSharedMemorySize, ATTN_SMEM);

    // 1) merged prep: split x (fp16 hi/lo) + weights (single fp16, +LoRA)
    prep_all<<<6144, 256>>>(x, Wq, Aq, Bq, Wkv, Av, Bv, Wsr, Wproj);

    // 2) merged: xs split-K partial GEMMs (4 slices) + q GEMM (single fp16 out)
    gemm_q_xs<<<dim3(8, 128), 256, GEMM_SMEM>>>(bq);

    // 3) LayerNorm (sums split-K partials + bsr) -> fp16 hi/lo
    ln_split_kernel<<<NB * NKV, 256>>>(gamma, beta, bsr);

    // 4) kv GEMM (2048 x 1024, K=512), fp16 single out
    gemm_fp16x2<2><<<dim3(16, 16), 256, GEMM_SMEM>>>(
        xsh, xsl, bkvT, bkv, pkv, nullptr, CD, 2 * CD);

    // 5) attention (single-fp16 HMMA) -> fp16 hi/lo
    attn_hmma<<<dim3(NQ / 128, NHEAD, NB), 256, ATTN_SMEM>>>(pq, pkv);

    // 6) out GEMM -> d_out (fp32)
    gemm_fp16x2<0><<<dim3(8, 64), 256, GEMM_SMEM>>>(
        oh, ol, bpT, bproj, outp, nullptr, CD, CD);
}

// round 17
// speedup vs baseline: 2.6572x; 1.2240x over previous
#include <cuda_runtime.h>
#include <cuda_bf16.h>
#include <cuda_fp16.h>
#include <cstdint>
#include <math.h>

#define NB    2
#define NQ    4096
#define NKV   1024
#define CD    512
#define NHEAD 8
#define DH    64
#define RLORA 8
#define LN_EPS 1e-5f

typedef __half fp16;

// ---------------------------------------------------------------------------
// Device scratch
// ---------------------------------------------------------------------------
__device__ fp16  g_x   [NB*NQ*CD];       // x: single fp16 (q damped; xs budgeted)
__device__ fp16  g_BqT [CD*CD];
__device__ fp16  g_BkvT[2*CD*CD];
__device__ fp16  g_BsrT[CD*4*CD];        // slice-blocked: [p][n][k]
__device__ fp16  g_BpT [CD*CD];
__device__ fp16  g_q   [NB*NQ*CD];       // q: single fp16
__device__ fp16  g_kv  [NB*NKV*2*CD];
__device__ float g_xsp[4][NB*NKV*CD];
__device__ fp16  g_xs_hi[NB*NKV*CD],     g_xs_lo[NB*NKV*CD];
__device__ fp16  g_o   [NB*NQ*CD];       // o: single fp16 (budgeted)
__device__ float g_zbias[2*CD];

// ---------------------------------------------------------------------------
// helpers
// ---------------------------------------------------------------------------
__device__ __forceinline__ uint32_t smem_u32(const void* p) {
    uint32_t a;
    asm("{ .reg .u64 t; cvta.to.shared.u64 t, %1; cvt.u32.u64 %0, t; }" : "=r"(a) : "l"(p));
    return a;
}
#define SW128(o) ((o) ^ (((o) >> 3) & 0x70))

__device__ __forceinline__ void cp16(uint32_t dst, const void* src) {
    asm volatile("cp.async.cg.shared.global [%0], [%1], 16;" :: "r"(dst), "l"(src));
}
__device__ __forceinline__ void cp_commit() { asm volatile("cp.async.commit_group;"); }
template<int N> __device__ __forceinline__ void cp_wait() {
    asm volatile("cp.async.wait_group %0;" :: "n"(N));
}

__device__ __forceinline__ void ldm_x4(uint32_t addr, uint32_t* r) {
    asm volatile("ldmatrix.sync.aligned.m8n8.x4.shared.b16 {%0,%1,%2,%3}, [%4];"
        : "=r"(r[0]), "=r"(r[1]), "=r"(r[2]), "=r"(r[3]) : "r"(addr));
}
__device__ __forceinline__ void ldm_x4_t(uint32_t addr, uint32_t* r) {
    asm volatile("ldmatrix.sync.aligned.m8n8.x4.trans.shared.b16 {%0,%1,%2,%3}, [%4];"
        : "=r"(r[0]), "=r"(r[1]), "=r"(r[2]), "=r"(r[3]) : "r"(addr));
}
__device__ __forceinline__ void mma16816h(float* c, const uint32_t* a, const uint32_t* b) {
    asm volatile("mma.sync.aligned.m16n8k16.row.col.f32.f16.f16.f32 "
        "{%0,%1,%2,%3}, {%4,%5,%6,%7}, {%8,%9}, {%0,%1,%2,%3};"
        : "+f"(c[0]), "+f"(c[1]), "+f"(c[2]), "+f"(c[3])
        : "r"(a[0]), "r"(a[1]), "r"(a[2]), "r"(a[3]), "r"(b[0]), "r"(b[1]));
}

__device__ __forceinline__ void hsplit(float a, fp16& hi, fp16& lo) {
    hi = __float2half_rn(a);
    lo = __float2half_rn(a - __half2float(hi));
}
__device__ __forceinline__ uint32_t packhf(fp16 a, fp16 b) {
    __half2 h = __halves2half2(a, b);
    return *reinterpret_cast<uint32_t*>(&h);
}

// ---------------------------------------------------------------------------
// GEMM core: C[M,N] = A @ B^T + bias, fp16 HMMA.
//   AL=1: A is an fp16 hi/lo pair (2 MMA passes); AL=0: single A (1 pass).
//   CTA tile 128x64, BK=64, 256 threads, 8 warps (4x2), warp tile 32x32,
//   2-stage cp.async. Smem: AL=1 80KB, AL=0 48KB; both -> 2 CTAs/SM.
//   OB=0: fp32 out; OB=2: fp16 single out.
//   PERM=1: A addresses patch `pslice` of the conv permutation of g_x.
// ---------------------------------------------------------------------------
#define A_TILE_B 16384
#define B_TILE_B 8192

template<int OB, int PERM, int AL>
__device__ __forceinline__ void gemm_core(
    uint32_t sb,
    const fp16* __restrict__ Ah, const fp16* __restrict__ Al,
    const fp16* __restrict__ B,
    const float* __restrict__ bias, void* __restrict__ Cv,
    int K, int ldc, int bx, int by, int pslice)
{
    constexpr uint32_t STG_B = (AL ? 2 : 1) * A_TILE_B + B_TILE_B;
    constexpr uint32_t B_OFF = (AL ? 2 : 1) * A_TILE_B;

    int tid = threadIdx.x, wid = tid >> 5, lane = tid & 31;

    const fp16* aAh = PERM ? Ah : Ah + (size_t)by * 128 * K;
    const fp16* aAl = AL ? (PERM ? Al : Al + (size_t)by * 128 * K) : nullptr;
    const fp16* aB  = B + (size_t)bx * 64 * K;

    auto issue = [&](int chunk, int buf) {
        int k0 = chunk << 6;
        uint32_t stg = sb + buf * STG_B;
#pragma unroll
        for (int t = 0; t < (AL ? 2 : 1); t++) {
            const fp16* src = t ? aAl : aAh;
#pragma unroll
            for (int it = 0; it < 4; it++) {
                int idx = it * 256 + tid;
                int r = idx >> 3, c16 = idx & 7;
                size_t goff;
                if (PERM) {
                    int m = by * 128 + r;
                    int bb = m >> 10, pp = m & 1023;
                    int tok = bb * NQ + ((pp >> 5) * 2 + (pslice >> 1)) * 64
                            + ((pp & 31) * 2 + (pslice & 1));
                    goff = (size_t)tok * CD + k0 + c16 * 8;
                } else {
                    goff = (size_t)r * K + k0 + c16 * 8;
                }
                cp16(stg + t * A_TILE_B + SW128(r * 128 + c16 * 16), src + goff);
            }
        }
        {
            const fp16* src = aB + k0;
            uint32_t base = stg + B_OFF;
#pragma unroll
            for (int it = 0; it < 2; it++) {
                int idx = it * 256 + tid;
                int r = idx >> 3, c16 = idx & 7;
                cp16(base + SW128(r * 128 + c16 * 16),
                     src + (size_t)r * K + c16 * 8);
            }
        }
        cp_commit();
    };

    float acc[2][4][4];
#pragma unroll
    for (int i = 0; i < 2; i++)
#pragma unroll
        for (int j = 0; j < 4; j++)
#pragma unroll
            for (int e = 0; e < 4; e++) acc[i][j][e] = 0.f;

    int wm = wid >> 1, wn = wid & 1;
    int nch = K >> 6;

    issue(0, 0);
    for (int i = 0; i < nch; i++) {
        int buf = i & 1;
        if (i + 1 < nch) { issue(i + 1, buf ^ 1); cp_wait<1>(); }
        else             { cp_wait<0>(); }
        __syncthreads();

        uint32_t stg = sb + buf * STG_B;
        uint32_t aH = stg;
        uint32_t aL = stg + A_TILE_B;
        uint32_t bB = stg + B_OFF;

#pragma unroll
        for (int ks = 0; ks < 4; ks++) {
            int kb = ks * 32;
            uint32_t ah[2][4], al[2][4], bh[4][2];
#pragma unroll
            for (int at = 0; at < 2; at++) {
                int row = wm * 32 + at * 16 + (lane & 15);
                int colb = kb + ((lane >> 4) << 4);
                uint32_t off = SW128(row * 128 + colb);
                ldm_x4(aH + off, ah[at]);
                if (AL) ldm_x4(aL + off, al[at]);
            }
#pragma unroll
            for (int bt = 0; bt < 2; bt++) {
                int row = wn * 32 + bt * 16 + ((lane >> 4) << 3) + (lane & 7);
                int colb = kb + (((lane >> 3) & 1) << 4);
                uint32_t off = SW128(row * 128 + colb);
                uint32_t t[4];
                ldm_x4(bB + off, t);
                bh[bt * 2][0] = t[0]; bh[bt * 2][1] = t[1];
                bh[bt * 2 + 1][0] = t[2]; bh[bt * 2 + 1][1] = t[3];
            }
#pragma unroll
            for (int at = 0; at < 2; at++)
#pragma unroll
                for (int nt = 0; nt < 4; nt++)
                    mma16816h(acc[at][nt], ah[at], bh[nt]);
            if (AL) {
#pragma unroll
                for (int at = 0; at < 2; at++)
#pragma unroll
                    for (int nt = 0; nt < 4; nt++)
                        mma16816h(acc[at][nt], al[at], bh[nt]);
            }
        }
        __syncthreads();
    }

    int g = lane >> 2, tc = (lane & 3) * 2;
#pragma unroll
    for (int nt = 0; nt < 4; nt++) {
        int col = bx * 64 + wn * 32 + nt * 8 + tc;
        float b0 = bias[col], b1 = bias[col + 1];
#pragma unroll
        for (int at = 0; at < 2; at++) {
            int row0 = by * 128 + wm * 32 + at * 16 + g;
            float v00 = acc[at][nt][0] + b0, v01 = acc[at][nt][1] + b1;
            float v10 = acc[at][nt][2] + b0, v11 = acc[at][nt][3] + b1;
            if (OB == 2) {
                fp16* C = (fp16*)Cv;
                *(uint32_t*)(C + (size_t)row0 * ldc + col) =
                    packhf(__float2half_rn(v00), __float2half_rn(v01));
                *(uint32_t*)(C + (size_t)(row0 + 8) * ldc + col) =
                    packhf(__float2half_rn(v10), __float2half_rn(v11));
            } else {
                float* C = (float*)Cv;
                *(float2*)(C + (size_t)row0 * ldc + col)       = make_float2(v00, v01);
                *(float2*)(C + (size_t)(row0 + 8) * ldc + col) = make_float2(v10, v11);
            }
        }
    }
}

#define GEMM_SMEM_AL1 (2 * (2 * A_TILE_B + B_TILE_B))   // 80 KB
#define GEMM_SMEM_AL0 (2 * (A_TILE_B + B_TILE_B))       // 48 KB

template<int OB, int AL>
__global__ __launch_bounds__(256, 2) void gemm_fp16(
    const fp16* __restrict__ Ah, const fp16* __restrict__ Al,
    const fp16* __restrict__ B,
    const float* __restrict__ bias, void* __restrict__ Cv,
    int K, int ldc)
{
    extern __shared__ char smem[];
    gemm_core<OB, 0, AL>(smem_u32(smem), Ah, Al, B, bias, Cv, K, ldc,
                         blockIdx.x, blockIdx.y, 0);
}

// Merged independent GEMMs: grid (8, 128). Both paths single-A (AL=0).
//  by in [0,64):   xs partial (slice = by>>4, m-tile = by&15), fp32 out
//  by in [64,128): q (single fp16 out)
__global__ __launch_bounds__(256, 2) void gemm_q_xs(
    const float* __restrict__ bq)
{
    extern __shared__ char smem[];
    uint32_t sb = smem_u32(smem);
    if (blockIdx.y < 64) {
        int slice = blockIdx.y >> 4, mt = blockIdx.y & 15;
        gemm_core<0, 1, 0>(sb, g_x, nullptr,
                           g_BsrT + (size_t)slice * CD * CD,
                           g_zbias, (void*)g_xsp[slice],
                           CD, CD, blockIdx.x, mt, slice);
    } else {
        gemm_core<2, 0, 0>(sb, g_x, nullptr, g_BqT, bq,
                           (void*)g_q, CD, CD,
                           blockIdx.x, blockIdx.y - 64, 0);
    }
}

// ---------------------------------------------------------------------------
// Merged prep: x -> single fp16; weights -> transposed single fp16 (+LoRA).
// ---------------------------------------------------------------------------
__global__ __launch_bounds__(256) void prep_all(
    const float* __restrict__ x,
    const float* __restrict__ Wq,   const float* __restrict__ Aq, const float* __restrict__ Bq,
    const float* __restrict__ Wkv,  const float* __restrict__ Av, const float* __restrict__ Bv,
    const float* __restrict__ Wsr,  const float* __restrict__ Wproj)
{
    if (blockIdx.x < 4096) {
        int e = blockIdx.x * 256 + threadIdx.x;
        float4 v = ((const float4*)x)[e];
        ((uint32_t*)g_x)[e * 2]     = packhf(__float2half_rn(v.x), __float2half_rn(v.y));
        ((uint32_t*)g_x)[e * 2 + 1] = packhf(__float2half_rn(v.z), __float2half_rn(v.w));
        return;
    }

    __shared__ float tile[32][33];
    int t = blockIdx.x - 4096;
    const float *W, *A = nullptr, *LB = nullptr;
    fp16 *D;
    int K, stride, k0, n0;

    if (t < 256) {
        W = Wq; A = Aq; LB = Bq; D = g_BqT;
        K = 512; stride = 512; k0 = (t >> 4) * 32; n0 = (t & 15) * 32;
    } else if (t < 768) {
        int i = t - 256;
        W = Wkv; A = Av; LB = Bv; D = g_BkvT;
        K = 512; stride = 1024; k0 = (i >> 5) * 32; n0 = (i & 31) * 32;
    } else if (t < 1792) {
        int i = t - 768;
        W = Wsr;
        int kk0 = (i >> 4) * 32;
        int nn0 = (i & 15) * 32;
        int tx = threadIdx.x & 31, ty = threadIdx.x >> 5;
#pragma unroll
        for (int ii = 0; ii < 4; ii++) {
            int kk = kk0 + ty + ii * 8, n = nn0 + tx;
            tile[ty + ii * 8][tx] = W[(size_t)kk * 512 + n];
        }
        __syncthreads();
#pragma unroll
        for (int ii = 0; ii < 4; ii++) {
            int n = nn0 + ty + ii * 8, kk = kk0 + tx;
            int p = kk >> 9, k = kk & 511;
            g_BsrT[(size_t)p * CD * CD + (size_t)n * CD + k] =
                __float2half_rn(tile[tx][ty + ii * 8]);
        }
        return;
    } else {
        int i = t - 1792;
        W = Wproj; D = g_BpT;
        K = 512; stride = 512; k0 = (i >> 4) * 32; n0 = (i & 15) * 32;
    }

    int tx = threadIdx.x & 31, ty = threadIdx.x >> 5;
#pragma unroll
    for (int i = 0; i < 4; i++) {
        int k = k0 + ty + i * 8, n = n0 + tx;
        float v = W[(size_t)k * stride + n];
        if (A) {
            float l = 0.f;
#pragma unroll
            for (int r = 0; r < RLORA; r++)
                l = fmaf(A[k * RLORA + r], LB[r * CD + (n & (CD - 1))], l);
            v += l;
        }
        tile[ty + i * 8][tx] = v;
    }
    __syncthreads();
#pragma unroll
    for (int i = 0; i < 4; i++) {
        int n = n0 + ty + i * 8, k = k0 + tx;
        D[(size_t)n * K + k] = __float2half_rn(tile[tx][ty + i * 8]);
    }
}

// ---------------------------------------------------------------------------
// LayerNorm: sum split-K partials (+bsr), normalize -> fp16 hi/lo (kv keeps AL=1)
// ---------------------------------------------------------------------------
__device__ __forceinline__ float warp_sum(float v) {
#pragma unroll
    for (int o = 16; o > 0; o >>= 1) v += __shfl_xor_sync(0xffffffffu, v, o);
    return v;
}

__global__ __launch_bounds__(256) void ln_split_kernel(const float* __restrict__ gamma,
                                                       const float* __restrict__ beta,
                                                       const float* __restrict__ bsr) {
    int row = blockIdx.x;
    size_t base = (size_t)row * CD;
    int tid = threadIdx.x;
    float a = ((g_xsp[0][base + tid]       + g_xsp[1][base + tid])
            +  (g_xsp[2][base + tid]       + g_xsp[3][base + tid])) + bsr[tid];
    float c = ((g_xsp[0][base + tid + 256] + g_xsp[1][base + tid + 256])
            +  (g_xsp[2][base + tid + 256] + g_xsp[3][base + tid + 256])) + bsr[tid + 256];

    float s  = warp_sum(a + c);
    float sq = warp_sum(a * a + c * c);
    __shared__ float sh[16];
    int w = tid >> 5, l = tid & 31;
    if (l == 0) { sh[w] = s; sh[8 + w] = sq; }
    __syncthreads();
    if (w == 0) {
        float ts = (l < 8) ? sh[l] : 0.f;
        float tq = (l < 8) ? sh[8 + l] : 0.f;
        ts = warp_sum(ts); tq = warp_sum(tq);
        if (l == 0) { sh[0] = ts; sh[1] = tq; }
    }
    __syncthreads();
    float mean = sh[0] * (1.f / CD);
    float var  = sh[1] * (1.f / CD) - mean * mean;
    float inv  = rsqrtf(var + LN_EPS);
    float y0 = (a - mean) * inv * gamma[tid] + beta[tid];
    float y1 = (c - mean) * inv * gamma[tid + 256] + beta[tid + 256];
    fp16 h, lo;
    hsplit(y0, h, lo); g_xs_hi[base + tid] = h;       g_xs_lo[base + tid] = lo;
    hsplit(y1, h, lo); g_xs_hi[base + tid + 256] = h; g_xs_lo[base + tid + 256] = lo;
}

// ---------------------------------------------------------------------------
// HMMA flash attention (single-fp16 operands, validated R16); o -> single fp16.
// grid (NQ/128, NHEAD, NB), 256 threads (8 warps x 16 q-rows), 48 KB smem.
// ---------------------------------------------------------------------------
#define ATTN_SMEM 49152

__global__ __launch_bounds__(256, 2) void attn_hmma(
    const fp16* __restrict__ q, const fp16* __restrict__ kv)
{
    extern __shared__ char smem[];
    uint32_t sb = smem_u32(smem);
    const uint32_t QS = sb, ST = sb + 16384;

    int tid = threadIdx.x, lane = tid & 31, wid = tid >> 5;
    int b = blockIdx.z, h = blockIdx.y;
    int q0 = blockIdx.x * 128;

    const fp16* qg = q + (size_t)(b * NQ + q0) * CD + h * DH;
    const fp16* kg = kv + (size_t)b * NKV * (2 * CD) + h * DH;
    const fp16* vg = kg + CD;

#pragma unroll
    for (int it = 0; it < 4; it++) {
        int idx = it * 256 + tid;
        int r = idx >> 3, c16 = idx & 7;
        cp16(QS + SW128(r * 128 + c16 * 16), qg + (size_t)r * CD + c16 * 8);
    }
    cp_commit();

    auto issue_kv = [&](int t, int bufi) {
        int m0 = t * 64;
        uint32_t SBB = ST + bufi * 16384;
#pragma unroll
        for (int it = 0; it < 2; it++) {
            int idx = it * 256 + tid;
            int r = idx >> 3, c16 = idx & 7;
            size_t go = (size_t)(m0 + r) * (2 * CD) + c16 * 8;
            uint32_t so = SW128(r * 128 + c16 * 16);
            cp16(SBB + so,        kg + go);
            cp16(SBB + 8192 + so, vg + go);
        }
        cp_commit();
    };

    issue_kv(0, 0);
    cp_wait<1>();
    __syncthreads();

    float o[8][4];
#pragma unroll
    for (int nt = 0; nt < 8; nt++)
#pragma unroll
        for (int e = 0; e < 4; e++) o[nt][e] = 0.f;
    float rs0 = 0.f, rs1 = 0.f;

    const float SC = 0.125f;
    int qrow = wid * 16 + (lane & 15);
    int qcolb = (lane >> 4) << 4;

    for (int t = 0; t < 16; t++) {
        int bufi = t & 1;
        if (t + 1 < 16) { issue_kv(t + 1, bufi ^ 1); cp_wait<1>(); }
        else            { cp_wait<0>(); }
        __syncthreads();

        uint32_t SBB = ST + bufi * 16384;

        float s[8][4];
#pragma unroll
        for (int nt = 0; nt < 8; nt++)
#pragma unroll
            for (int e = 0; e < 4; e++) s[nt][e] = 0.f;

#pragma unroll
        for (int ks = 0; ks < 4; ks++) {
            uint32_t aq[4];
            ldm_x4(QS + SW128(qrow * 128 + ks * 32 + qcolb), aq);
            uint32_t bh[8][2];
#pragma unroll
            for (int bt = 0; bt < 4; bt++) {
                int row = bt * 16 + ((lane >> 4) << 3) + (lane & 7);
                int colb = ks * 32 + (((lane >> 3) & 1) << 4);
                uint32_t off = SW128(row * 128 + colb);
                uint32_t tr[4];
                ldm_x4(SBB + off, tr);
                bh[bt * 2][0] = tr[0];     bh[bt * 2][1] = tr[1];
                bh[bt * 2 + 1][0] = tr[2]; bh[bt * 2 + 1][1] = tr[3];
            }
#pragma unroll
            for (int nt = 0; nt < 8; nt++)
                mma16816h(s[nt], aq, bh[nt]);
        }

        uint32_t pa[4][4];
#pragma unroll
        for (int nt = 0; nt < 8; nt++) {
            float p0 = __expf(s[nt][0] * SC);
            float p1 = __expf(s[nt][1] * SC);
            float p2 = __expf(s[nt][2] * SC);
            float p3 = __expf(s[nt][3] * SC);
            rs0 += p0 + p1;
            rs1 += p2 + p3;
            int j = nt >> 1, half = nt & 1;
            pa[j][half * 2]     = packhf(__float2half_rn(p0), __float2half_rn(p1));
            pa[j][half * 2 + 1] = packhf(__float2half_rn(p2), __float2half_rn(p3));
        }

#pragma unroll
        for (int j = 0; j < 4; j++) {
            uint32_t vb[8][2];
#pragma unroll
            for (int nh = 0; nh < 4; nh++) {
                int row = j * 16 + (lane & 15);
                int colb = nh * 32 + ((lane >> 4) << 4);
                uint32_t off = SW128(row * 128 + colb);
                uint32_t tr[4];
                ldm_x4_t(SBB + 8192 + off, tr);
                vb[nh * 2][0] = tr[0];     vb[nh * 2][1] = tr[1];
                vb[nh * 2 + 1][0] = tr[2]; vb[nh * 2 + 1][1] = tr[3];
            }
#pragma unroll
            for (int nt = 0; nt < 8; nt++)
                mma16816h(o[nt], pa[j], vb[nt]);
        }
        __syncthreads();
    }

    rs0 += __shfl_xor_sync(0xffffffffu, rs0, 1);
    rs0 += __shfl_xor_sync(0xffffffffu, rs0, 2);
    rs1 += __shfl_xor_sync(0xffffffffu, rs1, 1);
    rs1 += __shfl_xor_sync(0xffffffffu, rs1, 2);

    int g = lane >> 2, tc = (lane & 3) * 2;
    int row0 = q0 + wid * 16 + g;
    float i0 = 1.f / rs0, i1 = 1.f / rs1;
#pragma unroll
    for (int nt = 0; nt < 8; nt++) {
        int col = h * DH + nt * 8 + tc;
        size_t off0 = (size_t)(b * NQ + row0) * CD + col;
        size_t off1 = off0 + (size_t)8 * CD;
        *(uint32_t*)(g_o + off0) =
            packhf(__float2half_rn(o[nt][0] * i0), __float2half_rn(o[nt][1] * i0));
        *(uint32_t*)(g_o + off1) =
            packhf(__float2half_rn(o[nt][2] * i1), __float2half_rn(o[nt][3] * i1));
    }
}

// ---------------------------------------------------------------------------
// kernel_launch
// ---------------------------------------------------------------------------
extern "C" void kernel_launch(void* const* d_in, const int* in_sizes, int n_in,
                              void* d_out, int out_size) {
    const float* x     = (const float*)d_in[0];
    const float* Wq    = (const float*)d_in[1];
    const float* bq    = (const float*)d_in[2];
    const float* Wkv   = (const float*)d_in[3];
    const float* bkv   = (const float*)d_in[4];
    const float* Wproj = (const float*)d_in[5];
    const float* bproj = (const float*)d_in[6];
    const float* Aq    = (const float*)d_in[7];
    const float* Bq    = (const float*)d_in[8];
    const float* Av    = (const float*)d_in[9];
    const float* Bv    = (const float*)d_in[10];
    const float* Wsr   = (const float*)d_in[11];
    const float* bsr   = (const float*)d_in[12];
    const float* gamma = (const float*)d_in[13];
    const float* beta  = (const float*)d_in[14];
    float* outp = (float*)d_out;

    fp16 *xsh, *xsl, *po, *pq, *pkv, *bkvT, *bpT;
    cudaGetSymbolAddress((void**)&bkvT, g_BkvT);
    cudaGetSymbolAddress((void**)&bpT,  g_BpT);
    cudaGetSymbolAddress((void**)&xsh,  g_xs_hi);  cudaGetSymbolAddress((void**)&xsl,  g_xs_lo);
    cudaGetSymbolAddress((void**)&po,   g_o);
    cudaGetSymbolAddress((void**)&pq,   g_q);
    cudaGetSymbolAddress((void**)&pkv,  g_kv);

    cudaFuncSetAttribute((const void*)gemm_fp16<2, 1>, cudaFuncAttributeMaxDynamicSharedMemorySize, GEMM_SMEM_AL1);
    cudaFuncSetAttribute((const void*)gemm_fp16<0, 0>, cudaFuncAttributeMaxDynamicSharedMemorySize, GEMM_SMEM_AL0);
    cudaFuncSetAttribute((const void*)gemm_q_xs, cudaFuncAttributeMaxDynamicSharedMemorySize, GEMM_SMEM_AL0);
    cudaFuncSetAttribute((const void*)attn_hmma, cudaFuncAttributeMaxDynamicSharedMemorySize, ATTN_SMEM);

    // 1) merged prep: x -> single fp16 + weights (single fp16, +LoRA)
    prep_all<<<6144, 256>>>(x, Wq, Aq, Bq, Wkv, Av, Bv, Wsr, Wproj);

    // 2) merged: xs split-K partial GEMMs (4 slices, single-A) + q GEMM (single-A)
    gemm_q_xs<<<dim3(8, 128), 256, GEMM_SMEM_AL0>>>(bq);

    // 3) LayerNorm (sums split-K partials + bsr) -> fp16 hi/lo
    ln_split_kernel<<<NB * NKV, 256>>>(gamma, beta, bsr);

    // 4) kv GEMM (2048 x 1024, K=512), xs hi/lo (AL=1), fp16 single out
    gemm_fp16<2, 1><<<dim3(16, 16), 256, GEMM_SMEM_AL1>>>(
        xsh, xsl, bkvT, bkv, pkv, CD, 2 * CD);

    // 5) attention (single-fp16 HMMA) -> single fp16
    attn_hmma<<<dim3(NQ / 128, NHEAD, NB), 256, ATTN_SMEM>>>(pq, pkv);

    // 6) out GEMM (single-A) -> d_out (fp32)
    gemm_fp16<0, 0><<<dim3(8, 64), 256, GEMM_SMEM_AL0>>>(
        po, nullptr, bpT, bproj, outp, CD, CD);
}